// round 5
// baseline (speedup 1.0000x reference)
#include <cuda_runtime.h>
#include <math.h>

#define B_ 4
#define T_ 2048
#define D_ 1024
#define H_ 16
#define DK_ 64

// Scratch: 4 x 32MB device globals (allocation-free rule)
__device__ float g_q[B_*H_*T_*DK_];
__device__ float g_k[B_*H_*T_*DK_];
__device__ float g_v[B_*H_*T_*DK_];
__device__ float g_att[B_*T_*D_];

// ---------------------------------------------------------------------------
// SGEMM: C[M,N] = A[M,K] @ W[N,K]^T + bias[N]
// M=8192, N=1024, K=1024. 128x128 block tile, BK=8, 256 threads, 8x8/thread.
// qkvLayout=1: scatter to [B,H,T,DK]; else plain row-major [M,N].
// ---------------------------------------------------------------------------
__global__ __launch_bounds__(256) void sgemm_bias(
    const float* __restrict__ A, const float* __restrict__ W,
    const float* __restrict__ bias, float* __restrict__ out, int qkvLayout)
{
    const int K = 1024;
    __shared__ float As[8][128];
    __shared__ float Ws[8][128];

    int tid = threadIdx.x;
    int tx = tid & 15, ty = tid >> 4;
    int m0 = blockIdx.y * 128, n0 = blockIdx.x * 128;

    int lr = tid >> 1;          // 0..127 tile row
    int lc = (tid & 1) * 4;     // 0 or 4  (k offset)
    const float* Ag = A + (size_t)(m0 + lr) * K + lc;
    const float* Wg = W + (size_t)(n0 + lr) * K + lc;

    float acc[8][8];
#pragma unroll
    for (int i = 0; i < 8; i++)
#pragma unroll
        for (int j = 0; j < 8; j++) acc[i][j] = 0.f;

    float4 a_next = *(const float4*)Ag;
    float4 w_next = *(const float4*)Wg;

    for (int kt = 0; kt < K / 8; ++kt) {
        As[lc + 0][lr] = a_next.x; As[lc + 1][lr] = a_next.y;
        As[lc + 2][lr] = a_next.z; As[lc + 3][lr] = a_next.w;
        Ws[lc + 0][lr] = w_next.x; Ws[lc + 1][lr] = w_next.y;
        Ws[lc + 2][lr] = w_next.z; Ws[lc + 3][lr] = w_next.w;
        __syncthreads();

        if (kt + 1 < K / 8) {
            a_next = *(const float4*)(Ag + (kt + 1) * 8);
            w_next = *(const float4*)(Wg + (kt + 1) * 8);
        }

#pragma unroll
        for (int k = 0; k < 8; k++) {
            float4 a0 = *(const float4*)&As[k][ty * 4];
            float4 a1 = *(const float4*)&As[k][ty * 4 + 64];
            float4 b0 = *(const float4*)&Ws[k][tx * 4];
            float4 b1 = *(const float4*)&Ws[k][tx * 4 + 64];
            float av[8] = {a0.x, a0.y, a0.z, a0.w, a1.x, a1.y, a1.z, a1.w};
            float bv[8] = {b0.x, b0.y, b0.z, b0.w, b1.x, b1.y, b1.z, b1.w};
#pragma unroll
            for (int i = 0; i < 8; i++)
#pragma unroll
                for (int j = 0; j < 8; j++)
                    acc[i][j] += av[i] * bv[j];
        }
        __syncthreads();
    }

    // Epilogue
#pragma unroll
    for (int ia = 0; ia < 2; ia++) {
#pragma unroll
        for (int i = 0; i < 4; i++) {
            int m = m0 + ia * 64 + ty * 4 + i;
#pragma unroll
            for (int jb = 0; jb < 2; jb++) {
                int n = n0 + jb * 64 + tx * 4;
                float4 v;
                v.x = acc[ia * 4 + i][jb * 4 + 0] + bias[n + 0];
                v.y = acc[ia * 4 + i][jb * 4 + 1] + bias[n + 1];
                v.z = acc[ia * 4 + i][jb * 4 + 2] + bias[n + 2];
                v.w = acc[ia * 4 + i][jb * 4 + 3] + bias[n + 3];
                if (qkvLayout) {
                    int b = m >> 11, t = m & 2047, h = n >> 6, d = n & 63;
                    *(float4*)(out + (((size_t)(b * H_ + h) * T_ + t) * DK_ + d)) = v;
                } else {
                    *(float4*)(out + (size_t)m * 1024 + n) = v;
                }
            }
        }
    }
}

// ---------------------------------------------------------------------------
// Causal flash attention, fp32. One block per (q-tile=64 rows, b*h).
// 256 threads, each owns a 4x4 micro-tile of the 64x64 S / O tiles.
// Q and K are stored TRANSPOSED in smem ([d][row]) for conflict-free LDS.128.
// P tile reuses the K smem buffer (3 x 16KB = exactly 48KB static smem).
// ---------------------------------------------------------------------------
__global__ __launch_bounds__(256) void attn_kernel(
    const float* __restrict__ Qg, const float* __restrict__ Kg,
    const float* __restrict__ Vg, float* __restrict__ out)
{
    __shared__ float Qst[64][64];   // [d][r]
    __shared__ float KPs[64][64];   // K: [d][c]  -> reused as P: [r][s]
    __shared__ float Vs[64][64];    // [s][c]

    int tid = threadIdx.x;
    int tx = tid & 15, ty = tid >> 4;
    int qt = blockIdx.x;            // 0..31
    int bh = blockIdx.y;            // 0..63
    const float* qb = Qg + (size_t)bh * T_ * DK_;
    const float* kb = Kg + (size_t)bh * T_ * DK_;
    const float* vb = Vg + (size_t)bh * T_ * DK_;

    int lrr = tid >> 2;             // 0..63
    int ldd = (tid & 3) * 16;       // 0,16,32,48

    // Load Q tile (transposed into smem)
    {
        const float* src = qb + (size_t)(qt * 64 + lrr) * DK_ + ldd;
#pragma unroll
        for (int v4 = 0; v4 < 4; v4++) {
            float4 f = *(const float4*)(src + v4 * 4);
            Qst[ldd + v4 * 4 + 0][lrr] = f.x;
            Qst[ldd + v4 * 4 + 1][lrr] = f.y;
            Qst[ldd + v4 * 4 + 2][lrr] = f.z;
            Qst[ldd + v4 * 4 + 3][lrr] = f.w;
        }
    }

    float o[4][4];
#pragma unroll
    for (int i = 0; i < 4; i++)
#pragma unroll
        for (int j = 0; j < 4; j++) o[i][j] = 0.f;
    float mrow[4] = {-3e38f, -3e38f, -3e38f, -3e38f};
    float lrow[4] = {0.f, 0.f, 0.f, 0.f};

    for (int kt = 0; kt <= qt; ++kt) {
        __syncthreads();  // previous iteration's KPs/Vs readers done (also covers Q store)
        // Load K (transposed) + V (straight)
        {
            const float* ksrc = kb + (size_t)(kt * 64 + lrr) * DK_ + ldd;
            const float* vsrc = vb + (size_t)(kt * 64 + lrr) * DK_ + ldd;
#pragma unroll
            for (int v4 = 0; v4 < 4; v4++) {
                float4 f = *(const float4*)(ksrc + v4 * 4);
                KPs[ldd + v4 * 4 + 0][lrr] = f.x;
                KPs[ldd + v4 * 4 + 1][lrr] = f.y;
                KPs[ldd + v4 * 4 + 2][lrr] = f.z;
                KPs[ldd + v4 * 4 + 3][lrr] = f.w;
                *(float4*)&Vs[lrr][ldd + v4 * 4] = *(const float4*)(vsrc + v4 * 4);
            }
        }
        __syncthreads();

        // S = Q K^T (4x4 per thread)
        float s[4][4];
#pragma unroll
        for (int i = 0; i < 4; i++)
#pragma unroll
            for (int j = 0; j < 4; j++) s[i][j] = 0.f;
#pragma unroll 16
        for (int d = 0; d < 64; d++) {
            float4 qv = *(const float4*)&Qst[d][ty * 4];
            float4 kv = *(const float4*)&KPs[d][tx * 4];
            float av[4] = {qv.x, qv.y, qv.z, qv.w};
            float bv[4] = {kv.x, kv.y, kv.z, kv.w};
#pragma unroll
            for (int i = 0; i < 4; i++)
#pragma unroll
                for (int j = 0; j < 4; j++)
                    s[i][j] += av[i] * bv[j];
        }

        // Scale + causal mask + online softmax
        bool diag = (kt == qt);
#pragma unroll
        for (int i = 0; i < 4; i++) {
            float mloc = -3e38f;
#pragma unroll
            for (int j = 0; j < 4; j++) {
                float sv = s[i][j] * 0.125f;
                if (diag && (tx * 4 + j > ty * 4 + i)) sv = -3e38f;
                s[i][j] = sv;
                mloc = fmaxf(mloc, sv);
            }
#pragma unroll
            for (int off = 1; off < 16; off <<= 1)
                mloc = fmaxf(mloc, __shfl_xor_sync(0xffffffffu, mloc, off));
            float mn = fmaxf(mrow[i], mloc);
            float alpha = __expf(mrow[i] - mn);
            mrow[i] = mn;
            float rsum = 0.f;
#pragma unroll
            for (int j = 0; j < 4; j++) {
                float p = __expf(s[i][j] - mn);
                s[i][j] = p;
                rsum += p;
            }
#pragma unroll
            for (int off = 1; off < 16; off <<= 1)
                rsum += __shfl_xor_sync(0xffffffffu, rsum, off);
            lrow[i] = lrow[i] * alpha + rsum;
#pragma unroll
            for (int j = 0; j < 4; j++) o[i][j] *= alpha;
        }

        __syncthreads();  // all S reads of KPs complete
        // Write P into KPs (as [r][s])
#pragma unroll
        for (int i = 0; i < 4; i++)
            *(float4*)&KPs[ty * 4 + i][tx * 4] =
                make_float4(s[i][0], s[i][1], s[i][2], s[i][3]);
        __syncthreads();

        // O += P V
#pragma unroll 8
        for (int ss = 0; ss < 64; ss++) {
            float4 vv = *(const float4*)&Vs[ss][tx * 4];
#pragma unroll
            for (int i = 0; i < 4; i++) {
                float p = KPs[ty * 4 + i][ss];
                o[i][0] += p * vv.x;
                o[i][1] += p * vv.y;
                o[i][2] += p * vv.z;
                o[i][3] += p * vv.w;
            }
        }
    }

    // Normalize and write att: [B,T,D] with D index = h*64 + c
    int b = bh >> 4, h = bh & 15;
#pragma unroll
    for (int i = 0; i < 4; i++) {
        float inv = 1.f / lrow[i];
        int t = qt * 64 + ty * 4 + i;
        float* dst = out + ((size_t)(b * T_ + t) * D_ + h * DK_ + tx * 4);
        *(float4*)dst = make_float4(o[i][0] * inv, o[i][1] * inv,
                                    o[i][2] * inv, o[i][3] * inv);
    }
}

// ---------------------------------------------------------------------------
extern "C" void kernel_launch(void* const* d_in, const int* in_sizes, int n_in,
                              void* d_out, int out_size)
{
    const float* x  = (const float*)d_in[0];
    const float* wq = (const float*)d_in[1];
    const float* bq = (const float*)d_in[2];
    const float* wk = (const float*)d_in[3];
    const float* bk = (const float*)d_in[4];
    const float* wv = (const float*)d_in[5];
    const float* bv = (const float*)d_in[6];
    const float* wo = (const float*)d_in[7];
    const float* bo = (const float*)d_in[8];
    float* out = (float*)d_out;

    float *q, *k, *v, *att;
    cudaGetSymbolAddress((void**)&q, g_q);
    cudaGetSymbolAddress((void**)&k, g_k);
    cudaGetSymbolAddress((void**)&v, g_v);
    cudaGetSymbolAddress((void**)&att, g_att);

    dim3 gemmGrid(1024 / 128, 8192 / 128);  // (8, 64)
    sgemm_bias<<<gemmGrid, 256>>>(x, wq, bq, q, 1);
    sgemm_bias<<<gemmGrid, 256>>>(x, wk, bk, k, 1);
    sgemm_bias<<<gemmGrid, 256>>>(x, wv, bv, v, 1);

    dim3 attnGrid(T_ / 64, B_ * H_);        // (32, 64)
    attn_kernel<<<attnGrid, 256>>>(q, k, v, att);

    sgemm_bias<<<gemmGrid, 256>>>(att, wo, bo, out, 0);
}

// round 7
// speedup vs baseline: 1.1074x; 1.1074x over previous
#include <cuda_runtime.h>
#include <cuda_bf16.h>
#include <math.h>
#include <stdint.h>

#define B_ 4
#define T_ 2048
#define D_ 1024
#define H_ 16
#define DK_ 64

// Scratch (allocation-free rule)
__device__ float g_q[B_*H_*T_*DK_];
__device__ float g_k[B_*H_*T_*DK_];
__device__ float g_v[B_*H_*T_*DK_];
__device__ float g_att[B_*T_*D_];

// ---------------------------------------------------------------------------
// Portable tensor-core primitives (no 'a'-suffix features): ldmatrix + mma.sync
// ---------------------------------------------------------------------------
__device__ __forceinline__ uint32_t smem_u32(const void* p) {
    uint32_t r;
    asm("{ .reg .u64 t; cvta.to.shared.u64 t, %1; cvt.u32.u64 %0, t; }"
        : "=r"(r) : "l"(p));
    return r;
}
__device__ __forceinline__ void ldsm_x4(uint32_t* r, uint32_t addr) {
    asm volatile("ldmatrix.sync.aligned.m8n8.x4.shared.b16 {%0,%1,%2,%3}, [%4];"
        : "=r"(r[0]), "=r"(r[1]), "=r"(r[2]), "=r"(r[3]) : "r"(addr));
}
__device__ __forceinline__ void ldsm_x2(uint32_t* r, uint32_t addr) {
    asm volatile("ldmatrix.sync.aligned.m8n8.x2.shared.b16 {%0,%1}, [%2];"
        : "=r"(r[0]), "=r"(r[1]) : "r"(addr));
}
__device__ __forceinline__ void mma16816(float* c, const uint32_t* a, const uint32_t* b) {
    asm volatile(
        "mma.sync.aligned.m16n8k16.row.col.f32.bf16.bf16.f32 "
        "{%0,%1,%2,%3}, {%4,%5,%6,%7}, {%8,%9}, {%0,%1,%2,%3};"
        : "+f"(c[0]), "+f"(c[1]), "+f"(c[2]), "+f"(c[3])
        : "r"(a[0]), "r"(a[1]), "r"(a[2]), "r"(a[3]), "r"(b[0]), "r"(b[1]));
}

#define SWZ(o) ((o) ^ (((o) >> 3) & 0x70))

// ---------------------------------------------------------------------------
// Split-bf16 tensor-core GEMM: C[M=8192,N=1024] = A[M,K=1024] @ W[N,K]^T + bias
// A,W fp32 -> bf16 hi+lo on the fly; 3 MMAs per fragment pair (err ~2^-17).
// 128x128 CTA tile, 8 warps (2x4), 64x32 warp tile, K chunks of 64,
// double-buffered smem (4 x 16KB x 2 = 128KB), SW128 swizzle.
// qkvLayout=1 scatters to [B,H,T,DK].
// ---------------------------------------------------------------------------
__device__ __forceinline__ void sts_hilo(char* base_hi, int row, int c4, float4 f) {
    __nv_bfloat16 h0 = __float2bfloat16_rn(f.x);
    __nv_bfloat16 h1 = __float2bfloat16_rn(f.y);
    __nv_bfloat16 h2 = __float2bfloat16_rn(f.z);
    __nv_bfloat16 h3 = __float2bfloat16_rn(f.w);
    __nv_bfloat16 l0 = __float2bfloat16_rn(f.x - __bfloat162float(h0));
    __nv_bfloat16 l1 = __float2bfloat16_rn(f.y - __bfloat162float(h1));
    __nv_bfloat16 l2 = __float2bfloat16_rn(f.z - __bfloat162float(h2));
    __nv_bfloat16 l3 = __float2bfloat16_rn(f.w - __bfloat162float(h3));
    uint32_t off = SWZ((uint32_t)(row * 128 + c4 * 8));
    uint32_t hi01 = (uint32_t)__bfloat16_as_ushort(h0) | ((uint32_t)__bfloat16_as_ushort(h1) << 16);
    uint32_t hi23 = (uint32_t)__bfloat16_as_ushort(h2) | ((uint32_t)__bfloat16_as_ushort(h3) << 16);
    uint32_t lo01 = (uint32_t)__bfloat16_as_ushort(l0) | ((uint32_t)__bfloat16_as_ushort(l1) << 16);
    uint32_t lo23 = (uint32_t)__bfloat16_as_ushort(l2) | ((uint32_t)__bfloat16_as_ushort(l3) << 16);
    *(uint2*)(base_hi + off)         = make_uint2(hi01, hi23);
    *(uint2*)(base_hi + 16384 + off) = make_uint2(lo01, lo23);
}

__global__ __launch_bounds__(256, 1) void gemm_tc(
    const float* __restrict__ A, const float* __restrict__ W,
    const float* __restrict__ bias, float* __restrict__ out, int qkvLayout)
{
    extern __shared__ char dsm_raw[];
    char* dsm = (char*)(((uintptr_t)dsm_raw + 1023) & ~(uintptr_t)1023);

    const int tid  = threadIdx.x;
    const int lane = tid & 31;
    const int wid  = tid >> 5;
    const int warp_m = wid >> 2;     // 0-1 -> 64 rows each
    const int warp_n = wid & 3;      // 0-3 -> 32 cols each
    const int m0 = blockIdx.y * 128;
    const int n0 = blockIdx.x * 128;
    const uint32_t dbase = smem_u32(dsm);

    float acc[4][4][4];
#pragma unroll
    for (int i = 0; i < 4; i++)
#pragma unroll
        for (int j = 0; j < 4; j++)
#pragma unroll
            for (int r = 0; r < 4; r++) acc[i][j][r] = 0.f;

    // ldmatrix lane addressing (tile-local)
    const uint32_t rowA = (uint32_t)(warp_m * 64 + (lane & 15));
    const uint32_t colA = (uint32_t)((lane >> 4) * 16);
    const uint32_t rowB = (uint32_t)(warp_n * 32 + (lane & 7));
    const uint32_t colB = (uint32_t)(((lane >> 3) & 1) * 16);

    // staging: each thread owns 8 float4 per matrix per chunk (2 threads/row)
    const int srow = tid >> 1;                 // 0..127
    const int sc4  = (tid & 1) * 8;            // float4 col base: 0 or 8

    // ---- prologue: chunk 0 -> buffer 0 ----
    {
#pragma unroll
        for (int i = 0; i < 8; i++) {
            float4 fa = *(const float4*)(A + (size_t)(m0 + srow) * 1024 + (sc4 + i) * 4);
            float4 fw = *(const float4*)(W + (size_t)(n0 + srow) * 1024 + (sc4 + i) * 4);
            sts_hilo(dsm, srow, sc4 + i, fa);
            sts_hilo(dsm + 32768, srow, sc4 + i, fw);
        }
        __syncthreads();
    }

    const int NCH = 16;
#pragma unroll 1
    for (int kt = 0; kt < NCH; kt++) {
        const uint32_t tb = dbase + (uint32_t)(kt & 1) * 65536u;

        // prefetch next chunk globals into registers (overlaps with MMAs below)
        float4 fa[8], fw[8];
        if (kt + 1 < NCH) {
            const float* Ap = A + (size_t)(m0 + srow) * 1024 + (kt + 1) * 64 + sc4 * 4;
            const float* Wp = W + (size_t)(n0 + srow) * 1024 + (kt + 1) * 64 + sc4 * 4;
#pragma unroll
            for (int i = 0; i < 8; i++) {
                fa[i] = *(const float4*)(Ap + i * 4);
                fw[i] = *(const float4*)(Wp + i * 4);
            }
        }

        // ---- 4 k-steps of 16 ----
#pragma unroll
        for (int ks = 0; ks < 4; ks++) {
            uint32_t ah[4][4], al[4][4], bh[4][2], bl[4][2];
#pragma unroll
            for (int i = 0; i < 4; i++) {
                uint32_t off = (rowA + i * 16) * 128 + (uint32_t)ks * 32 + colA;
                uint32_t sw = SWZ(off);
                ldsm_x4(ah[i], tb + sw);
                ldsm_x4(al[i], tb + 16384u + sw);
            }
#pragma unroll
            for (int j = 0; j < 4; j++) {
                uint32_t off = (rowB + j * 8) * 128 + (uint32_t)ks * 32 + colB;
                uint32_t sw = SWZ(off);
                ldsm_x2(bh[j], tb + 32768u + sw);
                ldsm_x2(bl[j], tb + 49152u + sw);
            }
#pragma unroll
            for (int i = 0; i < 4; i++)
#pragma unroll
                for (int j = 0; j < 4; j++) {
                    mma16816(acc[i][j], ah[i], bh[j]);
                    mma16816(acc[i][j], ah[i], bl[j]);
                    mma16816(acc[i][j], al[i], bh[j]);
                }
        }

        // store prefetched chunk into the other buffer
        if (kt + 1 < NCH) {
            char* nb = dsm + (size_t)((kt + 1) & 1) * 65536u;
#pragma unroll
            for (int i = 0; i < 8; i++) {
                sts_hilo(nb, srow, sc4 + i, fa[i]);
                sts_hilo(nb + 32768, srow, sc4 + i, fw[i]);
            }
        }
        __syncthreads();
    }

    // ---- epilogue: fragments -> global (+bias), optional qkv scatter ----
    const int mw = m0 + warp_m * 64;
    const int nw = n0 + warp_n * 32;
    const int rl = lane >> 2;            // 0..7
    const int cl = (lane & 3) * 2;       // 0,2,4,6
#pragma unroll
    for (int i = 0; i < 4; i++) {
#pragma unroll
        for (int j = 0; j < 4; j++) {
            int m = mw + i * 16 + rl;
            int n = nw + j * 8 + cl;
            float2 bv = *(const float2*)(bias + n);
            float2 v0 = make_float2(acc[i][j][0] + bv.x, acc[i][j][1] + bv.y);
            float2 v1 = make_float2(acc[i][j][2] + bv.x, acc[i][j][3] + bv.y);
            if (qkvLayout) {
                int h = n >> 6, d = n & 63;
                int b0 = m >> 11, t0 = m & 2047;
                int m1 = m + 8;
                int b1 = m1 >> 11, t1 = m1 & 2047;
                *(float2*)(out + (((size_t)(b0 * H_ + h) * T_ + t0) * DK_ + d)) = v0;
                *(float2*)(out + (((size_t)(b1 * H_ + h) * T_ + t1) * DK_ + d)) = v1;
            } else {
                *(float2*)(out + (size_t)m * 1024 + n) = v0;
                *(float2*)(out + (size_t)(m + 8) * 1024 + n) = v1;
            }
        }
    }
}

// ---------------------------------------------------------------------------
// Causal flash attention, fp32 (unchanged, known-good)
// ---------------------------------------------------------------------------
__global__ __launch_bounds__(256) void attn_kernel(
    const float* __restrict__ Qg, const float* __restrict__ Kg,
    const float* __restrict__ Vg, float* __restrict__ out)
{
    __shared__ float Qst[64][64];
    __shared__ float KPs[64][64];
    __shared__ float Vs[64][64];

    int tid = threadIdx.x;
    int tx = tid & 15, ty = tid >> 4;
    int qt = blockIdx.x;
    int bh = blockIdx.y;
    const float* qb = Qg + (size_t)bh * T_ * DK_;
    const float* kb = Kg + (size_t)bh * T_ * DK_;
    const float* vb = Vg + (size_t)bh * T_ * DK_;

    int lrr = tid >> 2;
    int ldd = (tid & 3) * 16;

    {
        const float* src = qb + (size_t)(qt * 64 + lrr) * DK_ + ldd;
#pragma unroll
        for (int v4 = 0; v4 < 4; v4++) {
            float4 f = *(const float4*)(src + v4 * 4);
            Qst[ldd + v4 * 4 + 0][lrr] = f.x;
            Qst[ldd + v4 * 4 + 1][lrr] = f.y;
            Qst[ldd + v4 * 4 + 2][lrr] = f.z;
            Qst[ldd + v4 * 4 + 3][lrr] = f.w;
        }
    }

    float o[4][4];
#pragma unroll
    for (int i = 0; i < 4; i++)
#pragma unroll
        for (int j = 0; j < 4; j++) o[i][j] = 0.f;
    float mrow[4] = {-3e38f, -3e38f, -3e38f, -3e38f};
    float lrow[4] = {0.f, 0.f, 0.f, 0.f};

    for (int kt = 0; kt <= qt; ++kt) {
        __syncthreads();
        {
            const float* ksrc = kb + (size_t)(kt * 64 + lrr) * DK_ + ldd;
            const float* vsrc = vb + (size_t)(kt * 64 + lrr) * DK_ + ldd;
#pragma unroll
            for (int v4 = 0; v4 < 4; v4++) {
                float4 f = *(const float4*)(ksrc + v4 * 4);
                KPs[ldd + v4 * 4 + 0][lrr] = f.x;
                KPs[ldd + v4 * 4 + 1][lrr] = f.y;
                KPs[ldd + v4 * 4 + 2][lrr] = f.z;
                KPs[ldd + v4 * 4 + 3][lrr] = f.w;
                *(float4*)&Vs[lrr][ldd + v4 * 4] = *(const float4*)(vsrc + v4 * 4);
            }
        }
        __syncthreads();

        float s[4][4];
#pragma unroll
        for (int i = 0; i < 4; i++)
#pragma unroll
            for (int j = 0; j < 4; j++) s[i][j] = 0.f;
#pragma unroll 16
        for (int d = 0; d < 64; d++) {
            float4 qv = *(const float4*)&Qst[d][ty * 4];
            float4 kv = *(const float4*)&KPs[d][tx * 4];
            float av[4] = {qv.x, qv.y, qv.z, qv.w};
            float bv[4] = {kv.x, kv.y, kv.z, kv.w};
#pragma unroll
            for (int i = 0; i < 4; i++)
#pragma unroll
                for (int j = 0; j < 4; j++)
                    s[i][j] += av[i] * bv[j];
        }

        bool diag = (kt == qt);
#pragma unroll
        for (int i = 0; i < 4; i++) {
            float mloc = -3e38f;
#pragma unroll
            for (int j = 0; j < 4; j++) {
                float sv = s[i][j] * 0.125f;
                if (diag && (tx * 4 + j > ty * 4 + i)) sv = -3e38f;
                s[i][j] = sv;
                mloc = fmaxf(mloc, sv);
            }
#pragma unroll
            for (int off = 1; off < 16; off <<= 1)
                mloc = fmaxf(mloc, __shfl_xor_sync(0xffffffffu, mloc, off));
            float mn = fmaxf(mrow[i], mloc);
            float alpha = __expf(mrow[i] - mn);
            mrow[i] = mn;
            float rsum = 0.f;
#pragma unroll
            for (int j = 0; j < 4; j++) {
                float p = __expf(s[i][j] - mn);
                s[i][j] = p;
                rsum += p;
            }
#pragma unroll
            for (int off = 1; off < 16; off <<= 1)
                rsum += __shfl_xor_sync(0xffffffffu, rsum, off);
            lrow[i] = lrow[i] * alpha + rsum;
#pragma unroll
            for (int j = 0; j < 4; j++) o[i][j] *= alpha;
        }

        __syncthreads();
#pragma unroll
        for (int i = 0; i < 4; i++)
            *(float4*)&KPs[ty * 4 + i][tx * 4] =
                make_float4(s[i][0], s[i][1], s[i][2], s[i][3]);
        __syncthreads();

#pragma unroll 8
        for (int ss = 0; ss < 64; ss++) {
            float4 vv = *(const float4*)&Vs[ss][tx * 4];
#pragma unroll
            for (int i = 0; i < 4; i++) {
                float p = KPs[ty * 4 + i][ss];
                o[i][0] += p * vv.x;
                o[i][1] += p * vv.y;
                o[i][2] += p * vv.z;
                o[i][3] += p * vv.w;
            }
        }
    }

    int b = bh >> 4, h = bh & 15;
#pragma unroll
    for (int i = 0; i < 4; i++) {
        float inv = 1.f / lrow[i];
        int t = qt * 64 + ty * 4 + i;
        float* dst = out + ((size_t)(b * T_ + t) * D_ + h * DK_ + tx * 4);
        *(float4*)dst = make_float4(o[i][0] * inv, o[i][1] * inv,
                                    o[i][2] * inv, o[i][3] * inv);
    }
}

// ---------------------------------------------------------------------------
extern "C" void kernel_launch(void* const* d_in, const int* in_sizes, int n_in,
                              void* d_out, int out_size)
{
    const float* x  = (const float*)d_in[0];
    const float* wq = (const float*)d_in[1];
    const float* bq = (const float*)d_in[2];
    const float* wk = (const float*)d_in[3];
    const float* bk = (const float*)d_in[4];
    const float* wv = (const float*)d_in[5];
    const float* bv = (const float*)d_in[6];
    const float* wo = (const float*)d_in[7];
    const float* bo = (const float*)d_in[8];
    float* out = (float*)d_out;

    float *q, *k, *v, *att;
    cudaGetSymbolAddress((void**)&q, g_q);
    cudaGetSymbolAddress((void**)&k, g_k);
    cudaGetSymbolAddress((void**)&v, g_v);
    cudaGetSymbolAddress((void**)&att, g_att);

    const int SMEM_GEMM = 2 * 4 * 16384 + 1024;  // 132096 bytes
    cudaFuncSetAttribute(gemm_tc, cudaFuncAttributeMaxDynamicSharedMemorySize, SMEM_GEMM);

    dim3 gemmGrid(1024 / 128, 8192 / 128);  // (8, 64)
    gemm_tc<<<gemmGrid, 256, SMEM_GEMM>>>(x, wq, bq, q, 1);
    gemm_tc<<<gemmGrid, 256, SMEM_GEMM>>>(x, wk, bk, k, 1);
    gemm_tc<<<gemmGrid, 256, SMEM_GEMM>>>(x, wv, bv, v, 1);

    dim3 attnGrid(T_ / 64, B_ * H_);        // (32, 64)
    attn_kernel<<<attnGrid, 256>>>(q, k, v, att);

    gemm_tc<<<gemmGrid, 256, SMEM_GEMM>>>(att, wo, bo, out, 0);
}

// round 8
// speedup vs baseline: 1.5497x; 1.3994x over previous
#include <cuda_runtime.h>
#include <cuda_bf16.h>
#include <math.h>
#include <stdint.h>

#define B_ 4
#define T_ 2048
#define D_ 1024
#define H_ 16
#define DK_ 64

// Scratch (allocation-free rule)
__device__ float g_q[B_*H_*T_*DK_];
__device__ float g_k[B_*H_*T_*DK_];
__device__ float g_v[B_*H_*T_*DK_];
__device__ float g_att[B_*T_*D_];

// ---------------------------------------------------------------------------
// Portable tensor-core primitives (no 'a'-suffix features): ldmatrix + mma.sync
// ---------------------------------------------------------------------------
__device__ __forceinline__ uint32_t smem_u32(const void* p) {
    uint32_t r;
    asm("{ .reg .u64 t; cvta.to.shared.u64 t, %1; cvt.u32.u64 %0, t; }"
        : "=r"(r) : "l"(p));
    return r;
}
__device__ __forceinline__ void ldsm_x4(uint32_t* r, uint32_t addr) {
    asm volatile("ldmatrix.sync.aligned.m8n8.x4.shared.b16 {%0,%1,%2,%3}, [%4];"
        : "=r"(r[0]), "=r"(r[1]), "=r"(r[2]), "=r"(r[3]) : "r"(addr));
}
__device__ __forceinline__ void ldsm_x4_t(uint32_t* r, uint32_t addr) {
    asm volatile("ldmatrix.sync.aligned.m8n8.x4.trans.shared.b16 {%0,%1,%2,%3}, [%4];"
        : "=r"(r[0]), "=r"(r[1]), "=r"(r[2]), "=r"(r[3]) : "r"(addr));
}
__device__ __forceinline__ void ldsm_x2(uint32_t* r, uint32_t addr) {
    asm volatile("ldmatrix.sync.aligned.m8n8.x2.shared.b16 {%0,%1}, [%2];"
        : "=r"(r[0]), "=r"(r[1]) : "r"(addr));
}
__device__ __forceinline__ void mma16816(float* c, const uint32_t* a, const uint32_t* b) {
    asm volatile(
        "mma.sync.aligned.m16n8k16.row.col.f32.bf16.bf16.f32 "
        "{%0,%1,%2,%3}, {%4,%5,%6,%7}, {%8,%9}, {%0,%1,%2,%3};"
        : "+f"(c[0]), "+f"(c[1]), "+f"(c[2]), "+f"(c[3])
        : "r"(a[0]), "r"(a[1]), "r"(a[2]), "r"(a[3]), "r"(b[0]), "r"(b[1]));
}

#define SWZ(o) ((o) ^ (((o) >> 3) & 0x70))

__device__ __forceinline__ uint32_t pack2_bf16(float x, float y) {
    // lower 16 = x, upper 16 = y
    __nv_bfloat16 hx = __float2bfloat16_rn(x);
    __nv_bfloat16 hy = __float2bfloat16_rn(y);
    return (uint32_t)__bfloat16_as_ushort(hx) |
           ((uint32_t)__bfloat16_as_ushort(hy) << 16);
}
__device__ __forceinline__ void split_pack2(float x, float y, uint32_t& hi, uint32_t& lo) {
    __nv_bfloat16 hx = __float2bfloat16_rn(x);
    __nv_bfloat16 hy = __float2bfloat16_rn(y);
    float rx = x - __bfloat162float(hx);
    float ry = y - __bfloat162float(hy);
    hi = (uint32_t)__bfloat16_as_ushort(hx) | ((uint32_t)__bfloat16_as_ushort(hy) << 16);
    lo = pack2_bf16(rx, ry);
}

// ---------------------------------------------------------------------------
// Split-bf16 tensor-core GEMM (unchanged, passing)
// ---------------------------------------------------------------------------
__device__ __forceinline__ void sts_hilo(char* base_hi, int row, int c4, float4 f) {
    __nv_bfloat16 h0 = __float2bfloat16_rn(f.x);
    __nv_bfloat16 h1 = __float2bfloat16_rn(f.y);
    __nv_bfloat16 h2 = __float2bfloat16_rn(f.z);
    __nv_bfloat16 h3 = __float2bfloat16_rn(f.w);
    __nv_bfloat16 l0 = __float2bfloat16_rn(f.x - __bfloat162float(h0));
    __nv_bfloat16 l1 = __float2bfloat16_rn(f.y - __bfloat162float(h1));
    __nv_bfloat16 l2 = __float2bfloat16_rn(f.z - __bfloat162float(h2));
    __nv_bfloat16 l3 = __float2bfloat16_rn(f.w - __bfloat162float(h3));
    uint32_t off = SWZ((uint32_t)(row * 128 + c4 * 8));
    uint32_t hi01 = (uint32_t)__bfloat16_as_ushort(h0) | ((uint32_t)__bfloat16_as_ushort(h1) << 16);
    uint32_t hi23 = (uint32_t)__bfloat16_as_ushort(h2) | ((uint32_t)__bfloat16_as_ushort(h3) << 16);
    uint32_t lo01 = (uint32_t)__bfloat16_as_ushort(l0) | ((uint32_t)__bfloat16_as_ushort(l1) << 16);
    uint32_t lo23 = (uint32_t)__bfloat16_as_ushort(l2) | ((uint32_t)__bfloat16_as_ushort(l3) << 16);
    *(uint2*)(base_hi + off)         = make_uint2(hi01, hi23);
    *(uint2*)(base_hi + 16384 + off) = make_uint2(lo01, lo23);
}

__global__ __launch_bounds__(256, 1) void gemm_tc(
    const float* __restrict__ A, const float* __restrict__ W,
    const float* __restrict__ bias, float* __restrict__ out, int qkvLayout)
{
    extern __shared__ char dsm_raw[];
    char* dsm = (char*)(((uintptr_t)dsm_raw + 1023) & ~(uintptr_t)1023);

    const int tid  = threadIdx.x;
    const int lane = tid & 31;
    const int wid  = tid >> 5;
    const int warp_m = wid >> 2;
    const int warp_n = wid & 3;
    const int m0 = blockIdx.y * 128;
    const int n0 = blockIdx.x * 128;
    const uint32_t dbase = smem_u32(dsm);

    float acc[4][4][4];
#pragma unroll
    for (int i = 0; i < 4; i++)
#pragma unroll
        for (int j = 0; j < 4; j++)
#pragma unroll
            for (int r = 0; r < 4; r++) acc[i][j][r] = 0.f;

    const uint32_t rowA = (uint32_t)(warp_m * 64 + (lane & 15));
    const uint32_t colA = (uint32_t)((lane >> 4) * 16);
    const uint32_t rowB = (uint32_t)(warp_n * 32 + (lane & 7));
    const uint32_t colB = (uint32_t)(((lane >> 3) & 1) * 16);

    const int srow = tid >> 1;
    const int sc4  = (tid & 1) * 8;

    {
#pragma unroll
        for (int i = 0; i < 8; i++) {
            float4 fa = *(const float4*)(A + (size_t)(m0 + srow) * 1024 + (sc4 + i) * 4);
            float4 fw = *(const float4*)(W + (size_t)(n0 + srow) * 1024 + (sc4 + i) * 4);
            sts_hilo(dsm, srow, sc4 + i, fa);
            sts_hilo(dsm + 32768, srow, sc4 + i, fw);
        }
        __syncthreads();
    }

    const int NCH = 16;
#pragma unroll 1
    for (int kt = 0; kt < NCH; kt++) {
        const uint32_t tb = dbase + (uint32_t)(kt & 1) * 65536u;

        float4 fa[8], fw[8];
        if (kt + 1 < NCH) {
            const float* Ap = A + (size_t)(m0 + srow) * 1024 + (kt + 1) * 64 + sc4 * 4;
            const float* Wp = W + (size_t)(n0 + srow) * 1024 + (kt + 1) * 64 + sc4 * 4;
#pragma unroll
            for (int i = 0; i < 8; i++) {
                fa[i] = *(const float4*)(Ap + i * 4);
                fw[i] = *(const float4*)(Wp + i * 4);
            }
        }

#pragma unroll
        for (int ks = 0; ks < 4; ks++) {
            uint32_t ah[4][4], al[4][4], bh[4][2], bl[4][2];
#pragma unroll
            for (int i = 0; i < 4; i++) {
                uint32_t off = (rowA + i * 16) * 128 + (uint32_t)ks * 32 + colA;
                uint32_t sw = SWZ(off);
                ldsm_x4(ah[i], tb + sw);
                ldsm_x4(al[i], tb + 16384u + sw);
            }
#pragma unroll
            for (int j = 0; j < 4; j++) {
                uint32_t off = (rowB + j * 8) * 128 + (uint32_t)ks * 32 + colB;
                uint32_t sw = SWZ(off);
                ldsm_x2(bh[j], tb + 32768u + sw);
                ldsm_x2(bl[j], tb + 49152u + sw);
            }
#pragma unroll
            for (int i = 0; i < 4; i++)
#pragma unroll
                for (int j = 0; j < 4; j++) {
                    mma16816(acc[i][j], ah[i], bh[j]);
                    mma16816(acc[i][j], ah[i], bl[j]);
                    mma16816(acc[i][j], al[i], bh[j]);
                }
        }

        if (kt + 1 < NCH) {
            char* nb = dsm + (size_t)((kt + 1) & 1) * 65536u;
#pragma unroll
            for (int i = 0; i < 8; i++) {
                sts_hilo(nb, srow, sc4 + i, fa[i]);
                sts_hilo(nb + 32768, srow, sc4 + i, fw[i]);
            }
        }
        __syncthreads();
    }

    const int mw = m0 + warp_m * 64;
    const int nw = n0 + warp_n * 32;
    const int rl = lane >> 2;
    const int cl = (lane & 3) * 2;
#pragma unroll
    for (int i = 0; i < 4; i++) {
#pragma unroll
        for (int j = 0; j < 4; j++) {
            int m = mw + i * 16 + rl;
            int n = nw + j * 8 + cl;
            float2 bv = *(const float2*)(bias + n);
            float2 v0 = make_float2(acc[i][j][0] + bv.x, acc[i][j][1] + bv.y);
            float2 v1 = make_float2(acc[i][j][2] + bv.x, acc[i][j][3] + bv.y);
            if (qkvLayout) {
                int h = n >> 6, d = n & 63;
                int b0 = m >> 11, t0 = m & 2047;
                int m1 = m + 8;
                int b1 = m1 >> 11, t1 = m1 & 2047;
                *(float2*)(out + (((size_t)(b0 * H_ + h) * T_ + t0) * DK_ + d)) = v0;
                *(float2*)(out + (((size_t)(b1 * H_ + h) * T_ + t1) * DK_ + d)) = v1;
            } else {
                *(float2*)(out + (size_t)m * 1024 + n) = v0;
                *(float2*)(out + (size_t)(m + 8) * 1024 + n) = v1;
            }
        }
    }
}

// ---------------------------------------------------------------------------
// Tensor-core causal flash attention, split-bf16 (3-MMA) for S and P@V.
// 128 threads / 4 warps, Br=Bc=64, DK=64. Warp w owns q rows 16w..16w+15.
// Smem: Q/K/V hi+lo bf16 tiles (64x64, 128B rows, SW128) = 48KB.
// ---------------------------------------------------------------------------
__device__ __forceinline__ void sts_hilo_att(char* base, int row, int col, float4 f, float scale) {
    float x = f.x * scale, y = f.y * scale, z = f.z * scale, w = f.w * scale;
    __nv_bfloat16 h0 = __float2bfloat16_rn(x);
    __nv_bfloat16 h1 = __float2bfloat16_rn(y);
    __nv_bfloat16 h2 = __float2bfloat16_rn(z);
    __nv_bfloat16 h3 = __float2bfloat16_rn(w);
    __nv_bfloat16 l0 = __float2bfloat16_rn(x - __bfloat162float(h0));
    __nv_bfloat16 l1 = __float2bfloat16_rn(y - __bfloat162float(h1));
    __nv_bfloat16 l2 = __float2bfloat16_rn(z - __bfloat162float(h2));
    __nv_bfloat16 l3 = __float2bfloat16_rn(w - __bfloat162float(h3));
    uint32_t off = SWZ((uint32_t)(row * 128 + col * 2));
    uint32_t hi01 = (uint32_t)__bfloat16_as_ushort(h0) | ((uint32_t)__bfloat16_as_ushort(h1) << 16);
    uint32_t hi23 = (uint32_t)__bfloat16_as_ushort(h2) | ((uint32_t)__bfloat16_as_ushort(h3) << 16);
    uint32_t lo01 = (uint32_t)__bfloat16_as_ushort(l0) | ((uint32_t)__bfloat16_as_ushort(l1) << 16);
    uint32_t lo23 = (uint32_t)__bfloat16_as_ushort(l2) | ((uint32_t)__bfloat16_as_ushort(l3) << 16);
    *(uint2*)(base + off)        = make_uint2(hi01, hi23);
    *(uint2*)(base + 8192 + off) = make_uint2(lo01, lo23);
}

__global__ __launch_bounds__(128) void attn_tc(
    const float* __restrict__ Qg, const float* __restrict__ Kg,
    const float* __restrict__ Vg, float* __restrict__ out)
{
    __shared__ __align__(16) char sQ[16384];   // hi [0,8K), lo [8K,16K)
    __shared__ __align__(16) char sK[16384];
    __shared__ __align__(16) char sV[16384];

    const int tid  = threadIdx.x;
    const int lane = tid & 31;
    const int w    = tid >> 5;            // 0..3
    const int qt   = blockIdx.x;          // 0..31
    const int bh   = blockIdx.y;          // 0..63
    const float* qb = Qg + (size_t)bh * T_ * DK_;
    const float* kb = Kg + (size_t)bh * T_ * DK_;
    const float* vb = Vg + (size_t)bh * T_ * DK_;

    const uint32_t uQ = smem_u32(sQ);
    const uint32_t uK = smem_u32(sK);
    const uint32_t uV = smem_u32(sV);

    const int srow = tid >> 1;            // 0..63
    const int scol = (tid & 1) * 32;      // 0 or 32

    // Q tile, scaled by 1/sqrt(DK) = 1/8, split hi/lo
    {
        const float* src = qb + (size_t)(qt * 64 + srow) * DK_ + scol;
#pragma unroll
        for (int i = 0; i < 8; i++)
            sts_hilo_att(sQ, srow, scol + i * 4, *(const float4*)(src + i * 4), 0.125f);
    }

    float o[8][4];
#pragma unroll
    for (int j = 0; j < 8; j++)
#pragma unroll
        for (int r = 0; r < 4; r++) o[j][r] = 0.f;
    float m0v = -1e30f, m1v = -1e30f, l0v = 0.f, l1v = 0.f;

    const int qrow0 = qt * 64 + w * 16 + (lane >> 2);   // rows qrow0, qrow0+8

    // precomputed ldsm lane offsets (tile-local, element coords)
    const uint32_t qRow = (uint32_t)(w * 16 + (lane & 15));
    const uint32_t qColB = (uint32_t)((lane >> 4) * 16);          // bytes
    const uint32_t kRowBase = (uint32_t)((lane >> 4) * 8 + (lane & 7));
    const uint32_t kColB = (uint32_t)(((lane >> 3) & 1) * 16);    // bytes
    const uint32_t vRow = (uint32_t)(lane & 15);
    const uint32_t vColB = (uint32_t)((lane >> 4) * 16);          // bytes

#pragma unroll 1
    for (int kt = 0; kt <= qt; kt++) {
        __syncthreads();
        {
            const float* ks = kb + (size_t)(kt * 64 + srow) * DK_ + scol;
            const float* vs = vb + (size_t)(kt * 64 + srow) * DK_ + scol;
#pragma unroll
            for (int i = 0; i < 8; i++) {
                sts_hilo_att(sK, srow, scol + i * 4, *(const float4*)(ks + i * 4), 1.f);
                sts_hilo_att(sV, srow, scol + i * 4, *(const float4*)(vs + i * 4), 1.f);
            }
        }
        __syncthreads();

        // ---- S = Q K^T (scaled), fp32 accum, 3-MMA split ----
        float s[8][4];
#pragma unroll
        for (int j = 0; j < 8; j++)
#pragma unroll
            for (int r = 0; r < 4; r++) s[j][r] = 0.f;

#pragma unroll
        for (int ks4 = 0; ks4 < 4; ks4++) {
            uint32_t qh[4], ql[4];
            uint32_t qoff = SWZ(qRow * 128 + (uint32_t)ks4 * 32 + qColB);
            ldsm_x4(qh, uQ + qoff);
            ldsm_x4(ql, uQ + 8192u + qoff);
#pragma unroll
            for (int nf = 0; nf < 4; nf++) {
                uint32_t kh[4], kl[4];
                uint32_t koff = SWZ((kRowBase + (uint32_t)nf * 16) * 128 +
                                    (uint32_t)ks4 * 32 + kColB);
                ldsm_x4(kh, uK + koff);
                ldsm_x4(kl, uK + 8192u + koff);
                mma16816(s[nf * 2],     qh, &kh[0]);
                mma16816(s[nf * 2],     qh, &kl[0]);
                mma16816(s[nf * 2],     ql, &kh[0]);
                mma16816(s[nf * 2 + 1], qh, &kh[2]);
                mma16816(s[nf * 2 + 1], qh, &kl[2]);
                mma16816(s[nf * 2 + 1], ql, &kh[2]);
            }
        }

        // ---- causal mask (diagonal tile only) ----
        if (kt == qt) {
#pragma unroll
            for (int j = 0; j < 8; j++) {
                int kc = kt * 64 + j * 8 + (lane & 3) * 2;
                if (kc     > qrow0)     s[j][0] = -1e30f;
                if (kc + 1 > qrow0)     s[j][1] = -1e30f;
                if (kc     > qrow0 + 8) s[j][2] = -1e30f;
                if (kc + 1 > qrow0 + 8) s[j][3] = -1e30f;
            }
        }

        // ---- online softmax (rows qrow0 / qrow0+8, quad = lanes xor 1,2) ----
        float mA = m0v, mB = m1v;
#pragma unroll
        for (int j = 0; j < 8; j++) {
            mA = fmaxf(mA, fmaxf(s[j][0], s[j][1]));
            mB = fmaxf(mB, fmaxf(s[j][2], s[j][3]));
        }
        mA = fmaxf(mA, __shfl_xor_sync(0xffffffffu, mA, 1));
        mA = fmaxf(mA, __shfl_xor_sync(0xffffffffu, mA, 2));
        mB = fmaxf(mB, __shfl_xor_sync(0xffffffffu, mB, 1));
        mB = fmaxf(mB, __shfl_xor_sync(0xffffffffu, mB, 2));

        float alphaA = __expf(m0v - mA);
        float alphaB = __expf(m1v - mB);
        float sumA = 0.f, sumB = 0.f;
#pragma unroll
        for (int j = 0; j < 8; j++) {
            s[j][0] = __expf(s[j][0] - mA);
            s[j][1] = __expf(s[j][1] - mA);
            s[j][2] = __expf(s[j][2] - mB);
            s[j][3] = __expf(s[j][3] - mB);
            sumA += s[j][0] + s[j][1];
            sumB += s[j][2] + s[j][3];
        }
        sumA += __shfl_xor_sync(0xffffffffu, sumA, 1);
        sumA += __shfl_xor_sync(0xffffffffu, sumA, 2);
        sumB += __shfl_xor_sync(0xffffffffu, sumB, 1);
        sumB += __shfl_xor_sync(0xffffffffu, sumB, 2);

        l0v = l0v * alphaA + sumA;
        l1v = l1v * alphaB + sumB;
        m0v = mA; m1v = mB;
#pragma unroll
        for (int j = 0; j < 8; j++) {
            o[j][0] *= alphaA; o[j][1] *= alphaA;
            o[j][2] *= alphaB; o[j][3] *= alphaB;
        }

        // ---- O += P V : repack P accum frags into A-operand (hi/lo) ----
#pragma unroll
        for (int ks4 = 0; ks4 < 4; ks4++) {
            uint32_t ahi[4], alo[4];
            split_pack2(s[2 * ks4][0],     s[2 * ks4][1],     ahi[0], alo[0]);
            split_pack2(s[2 * ks4][2],     s[2 * ks4][3],     ahi[1], alo[1]);
            split_pack2(s[2 * ks4 + 1][0], s[2 * ks4 + 1][1], ahi[2], alo[2]);
            split_pack2(s[2 * ks4 + 1][2], s[2 * ks4 + 1][3], ahi[3], alo[3]);
#pragma unroll
            for (int nf = 0; nf < 4; nf++) {
                uint32_t vh[4], vl[4];
                uint32_t voff = SWZ(((uint32_t)ks4 * 16 + vRow) * 128 +
                                    (uint32_t)nf * 32 + vColB);
                ldsm_x4_t(vh, uV + voff);
                ldsm_x4_t(vl, uV + 8192u + voff);
                mma16816(o[nf * 2],     ahi, &vh[0]);
                mma16816(o[nf * 2],     ahi, &vl[0]);
                mma16816(o[nf * 2],     alo, &vh[0]);
                mma16816(o[nf * 2 + 1], ahi, &vh[2]);
                mma16816(o[nf * 2 + 1], ahi, &vl[2]);
                mma16816(o[nf * 2 + 1], alo, &vh[2]);
            }
        }
    }

    // ---- normalize + write att[B,T,D], d = h*64 + col ----
    float invA = 1.f / l0v;
    float invB = 1.f / l1v;
    int b = bh >> 4, h = bh & 15;
    int t0 = qt * 64 + w * 16 + (lane >> 2);
    float* d0 = out + ((size_t)(b * T_ + t0) * D_ + h * DK_ + (lane & 3) * 2);
    float* d1 = out + ((size_t)(b * T_ + t0 + 8) * D_ + h * DK_ + (lane & 3) * 2);
#pragma unroll
    for (int j = 0; j < 8; j++) {
        *(float2*)(d0 + j * 8) = make_float2(o[j][0] * invA, o[j][1] * invA);
        *(float2*)(d1 + j * 8) = make_float2(o[j][2] * invB, o[j][3] * invB);
    }
}

// ---------------------------------------------------------------------------
extern "C" void kernel_launch(void* const* d_in, const int* in_sizes, int n_in,
                              void* d_out, int out_size)
{
    const float* x  = (const float*)d_in[0];
    const float* wq = (const float*)d_in[1];
    const float* bq = (const float*)d_in[2];
    const float* wk = (const float*)d_in[3];
    const float* bk = (const float*)d_in[4];
    const float* wv = (const float*)d_in[5];
    const float* bv = (const float*)d_in[6];
    const float* wo = (const float*)d_in[7];
    const float* bo = (const float*)d_in[8];
    float* out = (float*)d_out;

    float *q, *k, *v, *att;
    cudaGetSymbolAddress((void**)&q, g_q);
    cudaGetSymbolAddress((void**)&k, g_k);
    cudaGetSymbolAddress((void**)&v, g_v);
    cudaGetSymbolAddress((void**)&att, g_att);

    const int SMEM_GEMM = 2 * 4 * 16384 + 1024;  // 132096 bytes
    cudaFuncSetAttribute(gemm_tc, cudaFuncAttributeMaxDynamicSharedMemorySize, SMEM_GEMM);

    dim3 gemmGrid(1024 / 128, 8192 / 128);  // (8, 64)
    gemm_tc<<<gemmGrid, 256, SMEM_GEMM>>>(x, wq, bq, q, 1);
    gemm_tc<<<gemmGrid, 256, SMEM_GEMM>>>(x, wk, bk, k, 1);
    gemm_tc<<<gemmGrid, 256, SMEM_GEMM>>>(x, wv, bv, v, 1);

    dim3 attnGrid(T_ / 64, B_ * H_);        // (32, 64)
    attn_tc<<<attnGrid, 128>>>(q, k, v, att);

    gemm_tc<<<gemmGrid, 256, SMEM_GEMM>>>(att, wo, bo, out, 0);
}

// round 9
// speedup vs baseline: 2.3923x; 1.5437x over previous
#include <cuda_runtime.h>
#include <cuda_bf16.h>
#include <math.h>
#include <stdint.h>

#define B_ 4
#define T_ 2048
#define D_ 1024
#define H_ 16
#define DK_ 64

// Scratch (allocation-free rule): pre-split bf16 hi/lo tensors
__device__ __nv_bfloat16 g_xhi[8192*1024], g_xlo[8192*1024];
__device__ __nv_bfloat16 g_whi[4*1024*1024], g_wlo[4*1024*1024];   // q,k,v,o
__device__ __nv_bfloat16 g_qhi[64*2048*64], g_qlo[64*2048*64];
__device__ __nv_bfloat16 g_khi[64*2048*64], g_klo[64*2048*64];
__device__ __nv_bfloat16 g_vhi[64*2048*64], g_vlo[64*2048*64];
__device__ __nv_bfloat16 g_ahi[8192*1024], g_alo[8192*1024];

// ---------------------------------------------------------------------------
// Portable primitives (no 'a'-suffix features)
// ---------------------------------------------------------------------------
__device__ __forceinline__ uint32_t smem_u32(const void* p) {
    uint32_t r;
    asm("{ .reg .u64 t; cvta.to.shared.u64 t, %1; cvt.u32.u64 %0, t; }"
        : "=r"(r) : "l"(p));
    return r;
}
__device__ __forceinline__ void ldsm_x4(uint32_t* r, uint32_t addr) {
    asm volatile("ldmatrix.sync.aligned.m8n8.x4.shared.b16 {%0,%1,%2,%3}, [%4];"
        : "=r"(r[0]), "=r"(r[1]), "=r"(r[2]), "=r"(r[3]) : "r"(addr));
}
__device__ __forceinline__ void ldsm_x4_t(uint32_t* r, uint32_t addr) {
    asm volatile("ldmatrix.sync.aligned.m8n8.x4.trans.shared.b16 {%0,%1,%2,%3}, [%4];"
        : "=r"(r[0]), "=r"(r[1]), "=r"(r[2]), "=r"(r[3]) : "r"(addr));
}
__device__ __forceinline__ void ldsm_x2(uint32_t* r, uint32_t addr) {
    asm volatile("ldmatrix.sync.aligned.m8n8.x2.shared.b16 {%0,%1}, [%2];"
        : "=r"(r[0]), "=r"(r[1]) : "r"(addr));
}
__device__ __forceinline__ void mma16816(float* c, const uint32_t* a, const uint32_t* b) {
    asm volatile(
        "mma.sync.aligned.m16n8k16.row.col.f32.bf16.bf16.f32 "
        "{%0,%1,%2,%3}, {%4,%5,%6,%7}, {%8,%9}, {%0,%1,%2,%3};"
        : "+f"(c[0]), "+f"(c[1]), "+f"(c[2]), "+f"(c[3])
        : "r"(a[0]), "r"(a[1]), "r"(a[2]), "r"(a[3]), "r"(b[0]), "r"(b[1]));
}
__device__ __forceinline__ void cp16(uint32_t saddr, const void* g) {
    asm volatile("cp.async.cg.shared.global [%0], [%1], 16;" :: "r"(saddr), "l"(g));
}
#define CP_COMMIT() asm volatile("cp.async.commit_group;" ::: "memory")
#define CP_WAIT0()  asm volatile("cp.async.wait_group 0;" ::: "memory")
#define CP_WAIT1()  asm volatile("cp.async.wait_group 1;" ::: "memory")

#define SWZ(o) ((o) ^ (((o) >> 3) & 0x70))

__device__ __forceinline__ uint32_t pack2_bf16(float x, float y) {
    __nv_bfloat16 hx = __float2bfloat16_rn(x);
    __nv_bfloat16 hy = __float2bfloat16_rn(y);
    return (uint32_t)__bfloat16_as_ushort(hx) |
           ((uint32_t)__bfloat16_as_ushort(hy) << 16);
}
__device__ __forceinline__ void split_pack2(float x, float y, uint32_t& hi, uint32_t& lo) {
    __nv_bfloat16 hx = __float2bfloat16_rn(x);
    __nv_bfloat16 hy = __float2bfloat16_rn(y);
    float rx = x - __bfloat162float(hx);
    float ry = y - __bfloat162float(hy);
    hi = (uint32_t)__bfloat16_as_ushort(hx) | ((uint32_t)__bfloat16_as_ushort(hy) << 16);
    lo = pack2_bf16(rx, ry);
}

// ---------------------------------------------------------------------------
// fp32 -> bf16 hi/lo split (one-time)
// ---------------------------------------------------------------------------
__global__ void convert_split(const float* __restrict__ src,
                              __nv_bfloat16* __restrict__ hi,
                              __nv_bfloat16* __restrict__ lo, int n)
{
    int i = (blockIdx.x * blockDim.x + threadIdx.x) * 4;
    if (i < n) {
        float4 f = *(const float4*)(src + i);
        uint32_t h01, l01, h23, l23;
        split_pack2(f.x, f.y, h01, l01);
        split_pack2(f.z, f.w, h23, l23);
        *(uint2*)(hi + i) = make_uint2(h01, h23);
        *(uint2*)(lo + i) = make_uint2(l01, l23);
    }
}

// ---------------------------------------------------------------------------
// Split-bf16 tensor-core GEMM with pre-converted operands + cp.async staging.
// C[M=8192,N=1024] = A @ W^T + bias. 128x128 CTA tile, 8 warps, K chunks of 64,
// double-buffered smem (4 x 16KB x 2). qkvLayout=1: scale + split-store to
// outHi/outLo in [B,H,T,DK]; else fp32 row-major to outF.
// ---------------------------------------------------------------------------
__global__ __launch_bounds__(256, 1) void gemm_bf16(
    const __nv_bfloat16* __restrict__ Ahi, const __nv_bfloat16* __restrict__ Alo,
    const __nv_bfloat16* __restrict__ Whi, const __nv_bfloat16* __restrict__ Wlo,
    const float* __restrict__ bias,
    float* __restrict__ outF,
    __nv_bfloat16* __restrict__ outHi, __nv_bfloat16* __restrict__ outLo,
    float scale, int qkvLayout)
{
    extern __shared__ char dsm_raw[];
    char* dsm = (char*)(((uintptr_t)dsm_raw + 1023) & ~(uintptr_t)1023);

    const int tid  = threadIdx.x;
    const int lane = tid & 31;
    const int wid  = tid >> 5;
    const int warp_m = wid >> 2;
    const int warp_n = wid & 3;
    const int m0 = blockIdx.y * 128;
    const int n0 = blockIdx.x * 128;
    const uint32_t dbase = smem_u32(dsm);

    float acc[4][4][4];
#pragma unroll
    for (int i = 0; i < 4; i++)
#pragma unroll
        for (int j = 0; j < 4; j++)
#pragma unroll
            for (int r = 0; r < 4; r++) acc[i][j][r] = 0.f;

    const uint32_t rowA = (uint32_t)(warp_m * 64 + (lane & 15));
    const uint32_t colA = (uint32_t)((lane >> 4) * 16);
    const uint32_t rowB = (uint32_t)(warp_n * 32 + (lane & 7));
    const uint32_t colB = (uint32_t)(((lane >> 3) & 1) * 16);

    // staging: 2 threads/row, 4 granules of 16B each per matrix half
    const int srow  = tid >> 1;
    const int gbase = (tid & 1) * 4;
    const __nv_bfloat16* a_h = Ahi + (size_t)(m0 + srow) * 1024;
    const __nv_bfloat16* a_l = Alo + (size_t)(m0 + srow) * 1024;
    const __nv_bfloat16* w_h = Whi + (size_t)(n0 + srow) * 1024;
    const __nv_bfloat16* w_l = Wlo + (size_t)(n0 + srow) * 1024;

    // prologue: chunk 0 -> buffer 0
#pragma unroll
    for (int i = 0; i < 4; i++) {
        int g = gbase + i;
        uint32_t off = SWZ((uint32_t)(srow * 128 + g * 16));
        cp16(dbase + off,          a_h + g * 8);
        cp16(dbase + 16384u + off, a_l + g * 8);
        cp16(dbase + 32768u + off, w_h + g * 8);
        cp16(dbase + 49152u + off, w_l + g * 8);
    }
    CP_COMMIT();

    const int NCH = 16;
#pragma unroll 1
    for (int kt = 0; kt < NCH; kt++) {
        const uint32_t tb = dbase + (uint32_t)(kt & 1) * 65536u;

        if (kt + 1 < NCH) {
            uint32_t nb = dbase + (uint32_t)((kt + 1) & 1) * 65536u;
            int kc = (kt + 1) * 64;
#pragma unroll
            for (int i = 0; i < 4; i++) {
                int g = gbase + i;
                uint32_t off = SWZ((uint32_t)(srow * 128 + g * 16));
                cp16(nb + off,          a_h + kc + g * 8);
                cp16(nb + 16384u + off, a_l + kc + g * 8);
                cp16(nb + 32768u + off, w_h + kc + g * 8);
                cp16(nb + 49152u + off, w_l + kc + g * 8);
            }
            CP_COMMIT();
            CP_WAIT1();
        } else {
            CP_WAIT0();
        }
        __syncthreads();

#pragma unroll
        for (int ks = 0; ks < 4; ks++) {
            uint32_t ah[4][4], al[4][4], bh[4][2], bl[4][2];
#pragma unroll
            for (int i = 0; i < 4; i++) {
                uint32_t off = (rowA + i * 16) * 128 + (uint32_t)ks * 32 + colA;
                uint32_t sw = SWZ(off);
                ldsm_x4(ah[i], tb + sw);
                ldsm_x4(al[i], tb + 16384u + sw);
            }
#pragma unroll
            for (int j = 0; j < 4; j++) {
                uint32_t off = (rowB + j * 8) * 128 + (uint32_t)ks * 32 + colB;
                uint32_t sw = SWZ(off);
                ldsm_x2(bh[j], tb + 32768u + sw);
                ldsm_x2(bl[j], tb + 49152u + sw);
            }
#pragma unroll
            for (int i = 0; i < 4; i++)
#pragma unroll
                for (int j = 0; j < 4; j++) {
                    mma16816(acc[i][j], ah[i], bh[j]);
                    mma16816(acc[i][j], ah[i], bl[j]);
                    mma16816(acc[i][j], al[i], bh[j]);
                }
        }
        __syncthreads();
    }

    // ---- epilogue ----
    const int mw = m0 + warp_m * 64;
    const int nw = n0 + warp_n * 32;
    const int rl = lane >> 2;
    const int cl = (lane & 3) * 2;
#pragma unroll
    for (int i = 0; i < 4; i++) {
#pragma unroll
        for (int j = 0; j < 4; j++) {
            int m = mw + i * 16 + rl;
            int n = nw + j * 8 + cl;
            float2 bv = *(const float2*)(bias + n);
            float y00 = (acc[i][j][0] + bv.x) * scale;
            float y01 = (acc[i][j][1] + bv.y) * scale;
            float y10 = (acc[i][j][2] + bv.x) * scale;
            float y11 = (acc[i][j][3] + bv.y) * scale;
            if (qkvLayout) {
                int h = n >> 6, d = n & 63;
                int b0 = m >> 11, t0 = m & 2047;
                int m1 = m + 8;
                int b1 = m1 >> 11, t1 = m1 & 2047;
                size_t i0 = ((size_t)(b0 * H_ + h) * T_ + t0) * DK_ + d;
                size_t i1 = ((size_t)(b1 * H_ + h) * T_ + t1) * DK_ + d;
                uint32_t hh, ll;
                split_pack2(y00, y01, hh, ll);
                *(uint32_t*)&outHi[i0] = hh; *(uint32_t*)&outLo[i0] = ll;
                split_pack2(y10, y11, hh, ll);
                *(uint32_t*)&outHi[i1] = hh; *(uint32_t*)&outLo[i1] = ll;
            } else {
                *(float2*)(outF + (size_t)m * 1024 + n) = make_float2(y00, y01);
                *(float2*)(outF + (size_t)(m + 8) * 1024 + n) = make_float2(y10, y11);
            }
        }
    }
}

// ---------------------------------------------------------------------------
// Tensor-core causal flash attention on pre-split bf16 q/k/v.
// 128 threads / 4 warps, Br=Bc=64, DK=64. Output: bf16 hi/lo att (for final GEMM).
// Smem: Q/K/V hi+lo (64 rows x 128B per half) = 48KB.
// ---------------------------------------------------------------------------
__global__ __launch_bounds__(128) void attn_tc(
    const __nv_bfloat16* __restrict__ qhi, const __nv_bfloat16* __restrict__ qlo,
    const __nv_bfloat16* __restrict__ khi, const __nv_bfloat16* __restrict__ klo,
    const __nv_bfloat16* __restrict__ vhi, const __nv_bfloat16* __restrict__ vlo,
    __nv_bfloat16* __restrict__ atthi, __nv_bfloat16* __restrict__ attlo)
{
    __shared__ __align__(16) char sQ[16384];   // hi [0,8K), lo [8K,16K)
    __shared__ __align__(16) char sK[16384];
    __shared__ __align__(16) char sV[16384];

    const int tid  = threadIdx.x;
    const int lane = tid & 31;
    const int w    = tid >> 5;
    const int qt   = blockIdx.x;
    const int bh   = blockIdx.y;
    const size_t bhoff = (size_t)bh * T_ * DK_;

    const uint32_t uQ = smem_u32(sQ);
    const uint32_t uK = smem_u32(sK);
    const uint32_t uV = smem_u32(sV);

    const int srow  = tid >> 1;            // 0..63
    const int gbase = (tid & 1) * 4;       // granules 0-3 or 4-7

    // Q tile (pre-scaled by 1/8 at QKV epilogue)
    {
        const __nv_bfloat16* qh = qhi + bhoff + (size_t)(qt * 64 + srow) * DK_;
        const __nv_bfloat16* ql = qlo + bhoff + (size_t)(qt * 64 + srow) * DK_;
#pragma unroll
        for (int i = 0; i < 4; i++) {
            int g = gbase + i;
            uint32_t off = SWZ((uint32_t)(srow * 128 + g * 16));
            cp16(uQ + off,         qh + g * 8);
            cp16(uQ + 8192u + off, ql + g * 8);
        }
        CP_COMMIT();
    }

    float o[8][4];
#pragma unroll
    for (int j = 0; j < 8; j++)
#pragma unroll
        for (int r = 0; r < 4; r++) o[j][r] = 0.f;
    float m0v = -1e30f, m1v = -1e30f, l0v = 0.f, l1v = 0.f;

    const int qrow0 = qt * 64 + w * 16 + (lane >> 2);

    const uint32_t qRow = (uint32_t)(w * 16 + (lane & 15));
    const uint32_t qColB = (uint32_t)((lane >> 4) * 16);
    const uint32_t kRowBase = (uint32_t)((lane >> 4) * 8 + (lane & 7));
    const uint32_t kColB = (uint32_t)(((lane >> 3) & 1) * 16);
    const uint32_t vRow = (uint32_t)(lane & 15);
    const uint32_t vColB = (uint32_t)((lane >> 4) * 16);

#pragma unroll 1
    for (int kt = 0; kt <= qt; kt++) {
        __syncthreads();   // previous iteration's readers done with sK/sV
        {
            const __nv_bfloat16* kh = khi + bhoff + (size_t)(kt * 64 + srow) * DK_;
            const __nv_bfloat16* kl = klo + bhoff + (size_t)(kt * 64 + srow) * DK_;
            const __nv_bfloat16* vh = vhi + bhoff + (size_t)(kt * 64 + srow) * DK_;
            const __nv_bfloat16* vl = vlo + bhoff + (size_t)(kt * 64 + srow) * DK_;
#pragma unroll
            for (int i = 0; i < 4; i++) {
                int g = gbase + i;
                uint32_t off = SWZ((uint32_t)(srow * 128 + g * 16));
                cp16(uK + off,         kh + g * 8);
                cp16(uK + 8192u + off, kl + g * 8);
                cp16(uV + off,         vh + g * 8);
                cp16(uV + 8192u + off, vl + g * 8);
            }
            CP_COMMIT();
            CP_WAIT0();
        }
        __syncthreads();

        // ---- S = Q K^T, fp32 accum, 3-MMA split ----
        float s[8][4];
#pragma unroll
        for (int j = 0; j < 8; j++)
#pragma unroll
            for (int r = 0; r < 4; r++) s[j][r] = 0.f;

#pragma unroll
        for (int ks4 = 0; ks4 < 4; ks4++) {
            uint32_t qh[4], ql[4];
            uint32_t qoff = SWZ(qRow * 128 + (uint32_t)ks4 * 32 + qColB);
            ldsm_x4(qh, uQ + qoff);
            ldsm_x4(ql, uQ + 8192u + qoff);
#pragma unroll
            for (int nf = 0; nf < 4; nf++) {
                uint32_t kh[4], kl[4];
                uint32_t koff = SWZ((kRowBase + (uint32_t)nf * 16) * 128 +
                                    (uint32_t)ks4 * 32 + kColB);
                ldsm_x4(kh, uK + koff);
                ldsm_x4(kl, uK + 8192u + koff);
                mma16816(s[nf * 2],     qh, &kh[0]);
                mma16816(s[nf * 2],     qh, &kl[0]);
                mma16816(s[nf * 2],     ql, &kh[0]);
                mma16816(s[nf * 2 + 1], qh, &kh[2]);
                mma16816(s[nf * 2 + 1], qh, &kl[2]);
                mma16816(s[nf * 2 + 1], ql, &kh[2]);
            }
        }

        // ---- causal mask (diagonal tile) ----
        if (kt == qt) {
#pragma unroll
            for (int j = 0; j < 8; j++) {
                int kc = kt * 64 + j * 8 + (lane & 3) * 2;
                if (kc     > qrow0)     s[j][0] = -1e30f;
                if (kc + 1 > qrow0)     s[j][1] = -1e30f;
                if (kc     > qrow0 + 8) s[j][2] = -1e30f;
                if (kc + 1 > qrow0 + 8) s[j][3] = -1e30f;
            }
        }

        // ---- online softmax ----
        float mA = m0v, mB = m1v;
#pragma unroll
        for (int j = 0; j < 8; j++) {
            mA = fmaxf(mA, fmaxf(s[j][0], s[j][1]));
            mB = fmaxf(mB, fmaxf(s[j][2], s[j][3]));
        }
        mA = fmaxf(mA, __shfl_xor_sync(0xffffffffu, mA, 1));
        mA = fmaxf(mA, __shfl_xor_sync(0xffffffffu, mA, 2));
        mB = fmaxf(mB, __shfl_xor_sync(0xffffffffu, mB, 1));
        mB = fmaxf(mB, __shfl_xor_sync(0xffffffffu, mB, 2));

        float alphaA = __expf(m0v - mA);
        float alphaB = __expf(m1v - mB);
        float sumA = 0.f, sumB = 0.f;
#pragma unroll
        for (int j = 0; j < 8; j++) {
            s[j][0] = __expf(s[j][0] - mA);
            s[j][1] = __expf(s[j][1] - mA);
            s[j][2] = __expf(s[j][2] - mB);
            s[j][3] = __expf(s[j][3] - mB);
            sumA += s[j][0] + s[j][1];
            sumB += s[j][2] + s[j][3];
        }
        sumA += __shfl_xor_sync(0xffffffffu, sumA, 1);
        sumA += __shfl_xor_sync(0xffffffffu, sumA, 2);
        sumB += __shfl_xor_sync(0xffffffffu, sumB, 1);
        sumB += __shfl_xor_sync(0xffffffffu, sumB, 2);

        l0v = l0v * alphaA + sumA;
        l1v = l1v * alphaB + sumB;
        m0v = mA; m1v = mB;
#pragma unroll
        for (int j = 0; j < 8; j++) {
            o[j][0] *= alphaA; o[j][1] *= alphaA;
            o[j][2] *= alphaB; o[j][3] *= alphaB;
        }

        // ---- O += P V ----
#pragma unroll
        for (int ks4 = 0; ks4 < 4; ks4++) {
            uint32_t ahi[4], alo[4];
            split_pack2(s[2 * ks4][0],     s[2 * ks4][1],     ahi[0], alo[0]);
            split_pack2(s[2 * ks4][2],     s[2 * ks4][3],     ahi[1], alo[1]);
            split_pack2(s[2 * ks4 + 1][0], s[2 * ks4 + 1][1], ahi[2], alo[2]);
            split_pack2(s[2 * ks4 + 1][2], s[2 * ks4 + 1][3], ahi[3], alo[3]);
#pragma unroll
            for (int nf = 0; nf < 4; nf++) {
                uint32_t vh[4], vl[4];
                uint32_t voff = SWZ(((uint32_t)ks4 * 16 + vRow) * 128 +
                                    (uint32_t)nf * 32 + vColB);
                ldsm_x4_t(vh, uV + voff);
                ldsm_x4_t(vl, uV + 8192u + voff);
                mma16816(o[nf * 2],     ahi, &vh[0]);
                mma16816(o[nf * 2],     ahi, &vl[0]);
                mma16816(o[nf * 2],     alo, &vh[0]);
                mma16816(o[nf * 2 + 1], ahi, &vh[2]);
                mma16816(o[nf * 2 + 1], ahi, &vl[2]);
                mma16816(o[nf * 2 + 1], alo, &vh[2]);
            }
        }
    }

    // ---- normalize + split-store att (bf16 hi/lo), att row = b*T + t ----
    float invA = 1.f / l0v;
    float invB = 1.f / l1v;
    int b = bh >> 4, h = bh & 15;
    int t0 = qt * 64 + w * 16 + (lane >> 2);
    size_t r0 = (size_t)(b * T_ + t0) * D_ + h * DK_ + (lane & 3) * 2;
    size_t r1 = (size_t)(b * T_ + t0 + 8) * D_ + h * DK_ + (lane & 3) * 2;
#pragma unroll
    for (int j = 0; j < 8; j++) {
        uint32_t hh, ll;
        split_pack2(o[j][0] * invA, o[j][1] * invA, hh, ll);
        *(uint32_t*)&atthi[r0 + j * 8] = hh;
        *(uint32_t*)&attlo[r0 + j * 8] = ll;
        split_pack2(o[j][2] * invB, o[j][3] * invB, hh, ll);
        *(uint32_t*)&atthi[r1 + j * 8] = hh;
        *(uint32_t*)&attlo[r1 + j * 8] = ll;
    }
}

// ---------------------------------------------------------------------------
extern "C" void kernel_launch(void* const* d_in, const int* in_sizes, int n_in,
                              void* d_out, int out_size)
{
    const float* x  = (const float*)d_in[0];
    const float* wq = (const float*)d_in[1];
    const float* bq = (const float*)d_in[2];
    const float* wk = (const float*)d_in[3];
    const float* bk = (const float*)d_in[4];
    const float* wv = (const float*)d_in[5];
    const float* bv = (const float*)d_in[6];
    const float* wo = (const float*)d_in[7];
    const float* bo = (const float*)d_in[8];
    float* out = (float*)d_out;

    __nv_bfloat16 *xhi, *xlo, *whi, *wlo;
    __nv_bfloat16 *qhi, *qlo, *khi, *klo, *vhi, *vlo, *ahi, *alo;
    cudaGetSymbolAddress((void**)&xhi, g_xhi);
    cudaGetSymbolAddress((void**)&xlo, g_xlo);
    cudaGetSymbolAddress((void**)&whi, g_whi);
    cudaGetSymbolAddress((void**)&wlo, g_wlo);
    cudaGetSymbolAddress((void**)&qhi, g_qhi);
    cudaGetSymbolAddress((void**)&qlo, g_qlo);
    cudaGetSymbolAddress((void**)&khi, g_khi);
    cudaGetSymbolAddress((void**)&klo, g_klo);
    cudaGetSymbolAddress((void**)&vhi, g_vhi);
    cudaGetSymbolAddress((void**)&vlo, g_vlo);
    cudaGetSymbolAddress((void**)&ahi, g_ahi);
    cudaGetSymbolAddress((void**)&alo, g_alo);

    // one-time fp32 -> bf16 hi/lo splits
    const int NX = 8192 * 1024, NW = 1024 * 1024;
    convert_split<<<NX / 4 / 256, 256>>>(x,  xhi, xlo, NX);
    convert_split<<<NW / 4 / 256, 256>>>(wq, whi + 0 * NW, wlo + 0 * NW, NW);
    convert_split<<<NW / 4 / 256, 256>>>(wk, whi + 1 * NW, wlo + 1 * NW, NW);
    convert_split<<<NW / 4 / 256, 256>>>(wv, whi + 2 * NW, wlo + 2 * NW, NW);
    convert_split<<<NW / 4 / 256, 256>>>(wo, whi + 3 * NW, wlo + 3 * NW, NW);

    const int SMEM_GEMM = 2 * 4 * 16384 + 1024;  // 132096 bytes
    cudaFuncSetAttribute(gemm_bf16, cudaFuncAttributeMaxDynamicSharedMemorySize, SMEM_GEMM);

    dim3 gemmGrid(1024 / 128, 8192 / 128);  // (8, 64)
    gemm_bf16<<<gemmGrid, 256, SMEM_GEMM>>>(xhi, xlo, whi + 0 * NW, wlo + 0 * NW,
                                            bq, nullptr, qhi, qlo, 0.125f, 1);
    gemm_bf16<<<gemmGrid, 256, SMEM_GEMM>>>(xhi, xlo, whi + 1 * NW, wlo + 1 * NW,
                                            bk, nullptr, khi, klo, 1.0f, 1);
    gemm_bf16<<<gemmGrid, 256, SMEM_GEMM>>>(xhi, xlo, whi + 2 * NW, wlo + 2 * NW,
                                            bv, nullptr, vhi, vlo, 1.0f, 1);

    dim3 attnGrid(T_ / 64, B_ * H_);        // (32, 64)
    attn_tc<<<attnGrid, 128>>>(qhi, qlo, khi, klo, vhi, vlo, ahi, alo);

    gemm_bf16<<<gemmGrid, 256, SMEM_GEMM>>>(ahi, alo, whi + 3 * NW, wlo + 3 * NW,
                                            bo, out, nullptr, nullptr, 1.0f, 0);
}

// round 10
// speedup vs baseline: 2.5045x; 1.0469x over previous
#include <cuda_runtime.h>
#include <cuda_bf16.h>
#include <math.h>
#include <stdint.h>

#define B_ 4
#define T_ 2048
#define D_ 1024
#define H_ 16
#define DK_ 64

// Scratch (allocation-free rule): pre-split bf16 hi/lo tensors
__device__ __nv_bfloat16 g_xhi[8192*1024], g_xlo[8192*1024];
__device__ __nv_bfloat16 g_whi[4*1024*1024], g_wlo[4*1024*1024];   // q,k,v,o
__device__ __nv_bfloat16 g_qhi[64*2048*64], g_qlo[64*2048*64];
__device__ __nv_bfloat16 g_khi[64*2048*64], g_klo[64*2048*64];
__device__ __nv_bfloat16 g_vhi[64*2048*64], g_vlo[64*2048*64];
__device__ __nv_bfloat16 g_ahi[8192*1024], g_alo[8192*1024];

// ---------------------------------------------------------------------------
// Portable primitives (no 'a'-suffix features)
// ---------------------------------------------------------------------------
__device__ __forceinline__ uint32_t smem_u32(const void* p) {
    uint32_t r;
    asm("{ .reg .u64 t; cvta.to.shared.u64 t, %1; cvt.u32.u64 %0, t; }"
        : "=r"(r) : "l"(p));
    return r;
}
__device__ __forceinline__ void ldsm_x4(uint32_t* r, uint32_t addr) {
    asm volatile("ldmatrix.sync.aligned.m8n8.x4.shared.b16 {%0,%1,%2,%3}, [%4];"
        : "=r"(r[0]), "=r"(r[1]), "=r"(r[2]), "=r"(r[3]) : "r"(addr));
}
__device__ __forceinline__ void ldsm_x4_t(uint32_t* r, uint32_t addr) {
    asm volatile("ldmatrix.sync.aligned.m8n8.x4.trans.shared.b16 {%0,%1,%2,%3}, [%4];"
        : "=r"(r[0]), "=r"(r[1]), "=r"(r[2]), "=r"(r[3]) : "r"(addr));
}
__device__ __forceinline__ void ldsm_x2(uint32_t* r, uint32_t addr) {
    asm volatile("ldmatrix.sync.aligned.m8n8.x2.shared.b16 {%0,%1}, [%2];"
        : "=r"(r[0]), "=r"(r[1]) : "r"(addr));
}
__device__ __forceinline__ void mma16816(float* c, const uint32_t* a, const uint32_t* b) {
    asm volatile(
        "mma.sync.aligned.m16n8k16.row.col.f32.bf16.bf16.f32 "
        "{%0,%1,%2,%3}, {%4,%5,%6,%7}, {%8,%9}, {%0,%1,%2,%3};"
        : "+f"(c[0]), "+f"(c[1]), "+f"(c[2]), "+f"(c[3])
        : "r"(a[0]), "r"(a[1]), "r"(a[2]), "r"(a[3]), "r"(b[0]), "r"(b[1]));
}
__device__ __forceinline__ void cp16(uint32_t saddr, const void* g) {
    asm volatile("cp.async.cg.shared.global [%0], [%1], 16;" :: "r"(saddr), "l"(g));
}
#define CP_COMMIT() asm volatile("cp.async.commit_group;" ::: "memory")
#define CP_WAIT0()  asm volatile("cp.async.wait_group 0;" ::: "memory")
#define CP_WAIT1()  asm volatile("cp.async.wait_group 1;" ::: "memory")

#define SWZ(o) ((o) ^ (((o) >> 3) & 0x70))

__device__ __forceinline__ uint32_t pack2_bf16(float x, float y) {
    __nv_bfloat16 hx = __float2bfloat16_rn(x);
    __nv_bfloat16 hy = __float2bfloat16_rn(y);
    return (uint32_t)__bfloat16_as_ushort(hx) |
           ((uint32_t)__bfloat16_as_ushort(hy) << 16);
}
__device__ __forceinline__ void split_pack2(float x, float y, uint32_t& hi, uint32_t& lo) {
    __nv_bfloat16 hx = __float2bfloat16_rn(x);
    __nv_bfloat16 hy = __float2bfloat16_rn(y);
    float rx = x - __bfloat162float(hx);
    float ry = y - __bfloat162float(hy);
    hi = (uint32_t)__bfloat16_as_ushort(hx) | ((uint32_t)__bfloat16_as_ushort(hy) << 16);
    lo = pack2_bf16(rx, ry);
}

// ---------------------------------------------------------------------------
// fp32 -> bf16 hi/lo split (one-time)
// ---------------------------------------------------------------------------
__global__ void convert_split(const float* __restrict__ src,
                              __nv_bfloat16* __restrict__ hi,
                              __nv_bfloat16* __restrict__ lo, int n)
{
    int i = (blockIdx.x * blockDim.x + threadIdx.x) * 4;
    if (i < n) {
        float4 f = *(const float4*)(src + i);
        uint32_t h01, l01, h23, l23;
        split_pack2(f.x, f.y, h01, l01);
        split_pack2(f.z, f.w, h23, l23);
        *(uint2*)(hi + i) = make_uint2(h01, h23);
        *(uint2*)(lo + i) = make_uint2(l01, l23);
    }
}

// ---------------------------------------------------------------------------
// Split-bf16 tensor-core GEMM with pre-converted operands + cp.async staging.
// (unchanged from round 9 passing version)
// ---------------------------------------------------------------------------
__global__ __launch_bounds__(256, 1) void gemm_bf16(
    const __nv_bfloat16* __restrict__ Ahi, const __nv_bfloat16* __restrict__ Alo,
    const __nv_bfloat16* __restrict__ Whi, const __nv_bfloat16* __restrict__ Wlo,
    const float* __restrict__ bias,
    float* __restrict__ outF,
    __nv_bfloat16* __restrict__ outHi, __nv_bfloat16* __restrict__ outLo,
    float scale, int qkvLayout)
{
    extern __shared__ char dsm_raw[];
    char* dsm = (char*)(((uintptr_t)dsm_raw + 1023) & ~(uintptr_t)1023);

    const int tid  = threadIdx.x;
    const int lane = tid & 31;
    const int wid  = tid >> 5;
    const int warp_m = wid >> 2;
    const int warp_n = wid & 3;
    const int m0 = blockIdx.y * 128;
    const int n0 = blockIdx.x * 128;
    const uint32_t dbase = smem_u32(dsm);

    float acc[4][4][4];
#pragma unroll
    for (int i = 0; i < 4; i++)
#pragma unroll
        for (int j = 0; j < 4; j++)
#pragma unroll
            for (int r = 0; r < 4; r++) acc[i][j][r] = 0.f;

    const uint32_t rowA = (uint32_t)(warp_m * 64 + (lane & 15));
    const uint32_t colA = (uint32_t)((lane >> 4) * 16);
    const uint32_t rowB = (uint32_t)(warp_n * 32 + (lane & 7));
    const uint32_t colB = (uint32_t)(((lane >> 3) & 1) * 16);

    const int srow  = tid >> 1;
    const int gbase = (tid & 1) * 4;
    const __nv_bfloat16* a_h = Ahi + (size_t)(m0 + srow) * 1024;
    const __nv_bfloat16* a_l = Alo + (size_t)(m0 + srow) * 1024;
    const __nv_bfloat16* w_h = Whi + (size_t)(n0 + srow) * 1024;
    const __nv_bfloat16* w_l = Wlo + (size_t)(n0 + srow) * 1024;

#pragma unroll
    for (int i = 0; i < 4; i++) {
        int g = gbase + i;
        uint32_t off = SWZ((uint32_t)(srow * 128 + g * 16));
        cp16(dbase + off,          a_h + g * 8);
        cp16(dbase + 16384u + off, a_l + g * 8);
        cp16(dbase + 32768u + off, w_h + g * 8);
        cp16(dbase + 49152u + off, w_l + g * 8);
    }
    CP_COMMIT();

    const int NCH = 16;
#pragma unroll 1
    for (int kt = 0; kt < NCH; kt++) {
        const uint32_t tb = dbase + (uint32_t)(kt & 1) * 65536u;

        if (kt + 1 < NCH) {
            uint32_t nb = dbase + (uint32_t)((kt + 1) & 1) * 65536u;
            int kc = (kt + 1) * 64;
#pragma unroll
            for (int i = 0; i < 4; i++) {
                int g = gbase + i;
                uint32_t off = SWZ((uint32_t)(srow * 128 + g * 16));
                cp16(nb + off,          a_h + kc + g * 8);
                cp16(nb + 16384u + off, a_l + kc + g * 8);
                cp16(nb + 32768u + off, w_h + kc + g * 8);
                cp16(nb + 49152u + off, w_l + kc + g * 8);
            }
            CP_COMMIT();
            CP_WAIT1();
        } else {
            CP_WAIT0();
        }
        __syncthreads();

#pragma unroll
        for (int ks = 0; ks < 4; ks++) {
            uint32_t ah[4][4], al[4][4], bh[4][2], bl[4][2];
#pragma unroll
            for (int i = 0; i < 4; i++) {
                uint32_t off = (rowA + i * 16) * 128 + (uint32_t)ks * 32 + colA;
                uint32_t sw = SWZ(off);
                ldsm_x4(ah[i], tb + sw);
                ldsm_x4(al[i], tb + 16384u + sw);
            }
#pragma unroll
            for (int j = 0; j < 4; j++) {
                uint32_t off = (rowB + j * 8) * 128 + (uint32_t)ks * 32 + colB;
                uint32_t sw = SWZ(off);
                ldsm_x2(bh[j], tb + 32768u + sw);
                ldsm_x2(bl[j], tb + 49152u + sw);
            }
#pragma unroll
            for (int i = 0; i < 4; i++)
#pragma unroll
                for (int j = 0; j < 4; j++) {
                    mma16816(acc[i][j], ah[i], bh[j]);
                    mma16816(acc[i][j], ah[i], bl[j]);
                    mma16816(acc[i][j], al[i], bh[j]);
                }
        }
        __syncthreads();
    }

    const int mw = m0 + warp_m * 64;
    const int nw = n0 + warp_n * 32;
    const int rl = lane >> 2;
    const int cl = (lane & 3) * 2;
#pragma unroll
    for (int i = 0; i < 4; i++) {
#pragma unroll
        for (int j = 0; j < 4; j++) {
            int m = mw + i * 16 + rl;
            int n = nw + j * 8 + cl;
            float2 bv = *(const float2*)(bias + n);
            float y00 = (acc[i][j][0] + bv.x) * scale;
            float y01 = (acc[i][j][1] + bv.y) * scale;
            float y10 = (acc[i][j][2] + bv.x) * scale;
            float y11 = (acc[i][j][3] + bv.y) * scale;
            if (qkvLayout) {
                int h = n >> 6, d = n & 63;
                int b0 = m >> 11, t0 = m & 2047;
                int m1 = m + 8;
                int b1 = m1 >> 11, t1 = m1 & 2047;
                size_t i0 = ((size_t)(b0 * H_ + h) * T_ + t0) * DK_ + d;
                size_t i1 = ((size_t)(b1 * H_ + h) * T_ + t1) * DK_ + d;
                uint32_t hh, ll;
                split_pack2(y00, y01, hh, ll);
                *(uint32_t*)&outHi[i0] = hh; *(uint32_t*)&outLo[i0] = ll;
                split_pack2(y10, y11, hh, ll);
                *(uint32_t*)&outHi[i1] = hh; *(uint32_t*)&outLo[i1] = ll;
            } else {
                *(float2*)(outF + (size_t)m * 1024 + n) = make_float2(y00, y01);
                *(float2*)(outF + (size_t)(m + 8) * 1024 + n) = make_float2(y10, y11);
            }
        }
    }
}

// ---------------------------------------------------------------------------
// Tensor-core causal flash attention, double-buffered K/V pipeline.
// 256 threads / 8 warps, Br=128, Bc=64, DK=64. Warp w owns q rows 16w..16w+15.
// Dyn smem: Q hi/lo 32KB + 2 x (K hi/lo 16KB + V hi/lo 16KB) = 96KB.
// qt reversed (heavy CTAs first). Fully-masked tiles skipped per warp.
// ---------------------------------------------------------------------------
__global__ __launch_bounds__(256, 1) void attn_tc(
    const __nv_bfloat16* __restrict__ qhi, const __nv_bfloat16* __restrict__ qlo,
    const __nv_bfloat16* __restrict__ khi, const __nv_bfloat16* __restrict__ klo,
    const __nv_bfloat16* __restrict__ vhi, const __nv_bfloat16* __restrict__ vlo,
    __nv_bfloat16* __restrict__ atthi, __nv_bfloat16* __restrict__ attlo)
{
    extern __shared__ char dsm_raw[];
    char* dsm = (char*)(((uintptr_t)dsm_raw + 1023) & ~(uintptr_t)1023);

    const int tid  = threadIdx.x;
    const int lane = tid & 31;
    const int w    = tid >> 5;                       // 0..7
    const int qt   = (int)gridDim.x - 1 - (int)blockIdx.x;  // heavy first
    const int bh   = blockIdx.y;
    const size_t bhoff = (size_t)bh * T_ * DK_;

    const uint32_t uQ = smem_u32(dsm);               // hi 16K, lo at +16K
    const uint32_t uKV0 = uQ + 32768u;               // per buf: Kh,Kl,Vh,Vl 8K each

    // ---- Q tile load (128 rows): 2 threads/row, 4 granules/half/thread ----
    {
        const int srow  = tid >> 1;
        const int gb    = (tid & 1) * 4;
        const __nv_bfloat16* qh = qhi + bhoff + (size_t)(qt * 128 + srow) * DK_;
        const __nv_bfloat16* ql = qlo + bhoff + (size_t)(qt * 128 + srow) * DK_;
#pragma unroll
        for (int i = 0; i < 4; i++) {
            int g = gb + i;
            uint32_t off = SWZ((uint32_t)(srow * 128 + g * 16));
            cp16(uQ + off,          qh + g * 8);
            cp16(uQ + 16384u + off, ql + g * 8);
        }
        CP_COMMIT();
    }

    // ---- K/V tile loader: 4 threads/row, 2 granules/half/thread ----
    const int srow2 = tid >> 2;          // 0..63
    const int gb2   = (tid & 3) * 2;
    const int ktmax = 2 * qt + 1;

    {   // prologue: KV tile 0 -> buf 0
        const __nv_bfloat16* kh = khi + bhoff + (size_t)srow2 * DK_;
        const __nv_bfloat16* kl = klo + bhoff + (size_t)srow2 * DK_;
        const __nv_bfloat16* vh = vhi + bhoff + (size_t)srow2 * DK_;
        const __nv_bfloat16* vl = vlo + bhoff + (size_t)srow2 * DK_;
#pragma unroll
        for (int i = 0; i < 2; i++) {
            int g = gb2 + i;
            uint32_t off = SWZ((uint32_t)(srow2 * 128 + g * 16));
            cp16(uKV0 + off,          kh + g * 8);
            cp16(uKV0 + 8192u + off,  kl + g * 8);
            cp16(uKV0 + 16384u + off, vh + g * 8);
            cp16(uKV0 + 24576u + off, vl + g * 8);
        }
        CP_COMMIT();
    }

    float o[8][4];
#pragma unroll
    for (int j = 0; j < 8; j++)
#pragma unroll
        for (int r = 0; r < 4; r++) o[j][r] = 0.f;
    float m0v = -1e30f, m1v = -1e30f, l0v = 0.f, l1v = 0.f;

    const int qrow0 = qt * 128 + w * 16 + (lane >> 2);

    const uint32_t qRow = (uint32_t)(w * 16 + (lane & 15));
    const uint32_t qColB = (uint32_t)((lane >> 4) * 16);
    const uint32_t kRowBase = (uint32_t)((lane >> 4) * 8 + (lane & 7));
    const uint32_t kColB = (uint32_t)(((lane >> 3) & 1) * 16);
    const uint32_t vRow = (uint32_t)(lane & 15);
    const uint32_t vColB = (uint32_t)((lane >> 4) * 16);

#pragma unroll 1
    for (int kt = 0; kt <= ktmax; kt++) {
        // prefetch next KV tile into other buffer (freed by trailing sync of kt-1)
        if (kt + 1 <= ktmax) {
            uint32_t nb = uKV0 + (uint32_t)((kt + 1) & 1) * 32768u;
            const __nv_bfloat16* kh = khi + bhoff + (size_t)((kt + 1) * 64 + srow2) * DK_;
            const __nv_bfloat16* kl = klo + bhoff + (size_t)((kt + 1) * 64 + srow2) * DK_;
            const __nv_bfloat16* vh = vhi + bhoff + (size_t)((kt + 1) * 64 + srow2) * DK_;
            const __nv_bfloat16* vl = vlo + bhoff + (size_t)((kt + 1) * 64 + srow2) * DK_;
#pragma unroll
            for (int i = 0; i < 2; i++) {
                int g = gb2 + i;
                uint32_t off = SWZ((uint32_t)(srow2 * 128 + g * 16));
                cp16(nb + off,          kh + g * 8);
                cp16(nb + 8192u + off,  kl + g * 8);
                cp16(nb + 16384u + off, vh + g * 8);
                cp16(nb + 24576u + off, vl + g * 8);
            }
            CP_COMMIT();
            CP_WAIT1();     // current tile (and Q on kt=0) arrived
        } else {
            CP_WAIT0();
        }
        __syncthreads();

        const uint32_t tb = uKV0 + (uint32_t)(kt & 1) * 32768u;

        // per-warp causal classification
        const int krel = kt * 64 - qt * 128;
        const bool full_skip = (krel > w * 16 + 15);
        const bool need_mask = !full_skip && (krel + 63 > w * 16);

        if (!full_skip) {
            // ---- S = Q K^T, fp32 accum, 3-MMA split ----
            float s[8][4];
#pragma unroll
            for (int j = 0; j < 8; j++)
#pragma unroll
                for (int r = 0; r < 4; r++) s[j][r] = 0.f;

#pragma unroll
            for (int ks4 = 0; ks4 < 4; ks4++) {
                uint32_t qh[4], ql[4];
                uint32_t qoff = SWZ(qRow * 128 + (uint32_t)ks4 * 32 + qColB);
                ldsm_x4(qh, uQ + qoff);
                ldsm_x4(ql, uQ + 16384u + qoff);
#pragma unroll
                for (int nf = 0; nf < 4; nf++) {
                    uint32_t kh[4], kl[4];
                    uint32_t koff = SWZ((kRowBase + (uint32_t)nf * 16) * 128 +
                                        (uint32_t)ks4 * 32 + kColB);
                    ldsm_x4(kh, tb + koff);
                    ldsm_x4(kl, tb + 8192u + koff);
                    mma16816(s[nf * 2],     qh, &kh[0]);
                    mma16816(s[nf * 2],     qh, &kl[0]);
                    mma16816(s[nf * 2],     ql, &kh[0]);
                    mma16816(s[nf * 2 + 1], qh, &kh[2]);
                    mma16816(s[nf * 2 + 1], qh, &kl[2]);
                    mma16816(s[nf * 2 + 1], ql, &kh[2]);
                }
            }

            // ---- causal mask (diagonal-crossing tiles only) ----
            if (need_mask) {
#pragma unroll
                for (int j = 0; j < 8; j++) {
                    int kc = kt * 64 + j * 8 + (lane & 3) * 2;
                    if (kc     > qrow0)     s[j][0] = -1e30f;
                    if (kc + 1 > qrow0)     s[j][1] = -1e30f;
                    if (kc     > qrow0 + 8) s[j][2] = -1e30f;
                    if (kc + 1 > qrow0 + 8) s[j][3] = -1e30f;
                }
            }

            // ---- online softmax ----
            float mA = m0v, mB = m1v;
#pragma unroll
            for (int j = 0; j < 8; j++) {
                mA = fmaxf(mA, fmaxf(s[j][0], s[j][1]));
                mB = fmaxf(mB, fmaxf(s[j][2], s[j][3]));
            }
            mA = fmaxf(mA, __shfl_xor_sync(0xffffffffu, mA, 1));
            mA = fmaxf(mA, __shfl_xor_sync(0xffffffffu, mA, 2));
            mB = fmaxf(mB, __shfl_xor_sync(0xffffffffu, mB, 1));
            mB = fmaxf(mB, __shfl_xor_sync(0xffffffffu, mB, 2));

            float alphaA = __expf(m0v - mA);
            float alphaB = __expf(m1v - mB);
            float sumA = 0.f, sumB = 0.f;
#pragma unroll
            for (int j = 0; j < 8; j++) {
                s[j][0] = __expf(s[j][0] - mA);
                s[j][1] = __expf(s[j][1] - mA);
                s[j][2] = __expf(s[j][2] - mB);
                s[j][3] = __expf(s[j][3] - mB);
                sumA += s[j][0] + s[j][1];
                sumB += s[j][2] + s[j][3];
            }
            sumA += __shfl_xor_sync(0xffffffffu, sumA, 1);
            sumA += __shfl_xor_sync(0xffffffffu, sumA, 2);
            sumB += __shfl_xor_sync(0xffffffffu, sumB, 1);
            sumB += __shfl_xor_sync(0xffffffffu, sumB, 2);

            l0v = l0v * alphaA + sumA;
            l1v = l1v * alphaB + sumB;
            m0v = mA; m1v = mB;
#pragma unroll
            for (int j = 0; j < 8; j++) {
                o[j][0] *= alphaA; o[j][1] *= alphaA;
                o[j][2] *= alphaB; o[j][3] *= alphaB;
            }

            // ---- O += P V ----
            const uint32_t vb_ = tb + 16384u;
#pragma unroll
            for (int ks4 = 0; ks4 < 4; ks4++) {
                uint32_t ahi[4], alo[4];
                split_pack2(s[2 * ks4][0],     s[2 * ks4][1],     ahi[0], alo[0]);
                split_pack2(s[2 * ks4][2],     s[2 * ks4][3],     ahi[1], alo[1]);
                split_pack2(s[2 * ks4 + 1][0], s[2 * ks4 + 1][1], ahi[2], alo[2]);
                split_pack2(s[2 * ks4 + 1][2], s[2 * ks4 + 1][3], ahi[3], alo[3]);
#pragma unroll
                for (int nf = 0; nf < 4; nf++) {
                    uint32_t vh[4], vl[4];
                    uint32_t voff = SWZ(((uint32_t)ks4 * 16 + vRow) * 128 +
                                        (uint32_t)nf * 32 + vColB);
                    ldsm_x4_t(vh, vb_ + voff);
                    ldsm_x4_t(vl, vb_ + 8192u + voff);
                    mma16816(o[nf * 2],     ahi, &vh[0]);
                    mma16816(o[nf * 2],     ahi, &vl[0]);
                    mma16816(o[nf * 2],     alo, &vh[0]);
                    mma16816(o[nf * 2 + 1], ahi, &vh[2]);
                    mma16816(o[nf * 2 + 1], ahi, &vl[2]);
                    mma16816(o[nf * 2 + 1], alo, &vh[2]);
                }
            }
        }
        __syncthreads();   // all warps done with buffer kt before next prefetch reuses it
    }

    // ---- normalize + split-store att (bf16 hi/lo) ----
    float invA = 1.f / l0v;
    float invB = 1.f / l1v;
    int b = bh >> 4, h = bh & 15;
    int t0 = qt * 128 + w * 16 + (lane >> 2);
    size_t r0 = (size_t)(b * T_ + t0) * D_ + h * DK_ + (lane & 3) * 2;
    size_t r1 = (size_t)(b * T_ + t0 + 8) * D_ + h * DK_ + (lane & 3) * 2;
#pragma unroll
    for (int j = 0; j < 8; j++) {
        uint32_t hh, ll;
        split_pack2(o[j][0] * invA, o[j][1] * invA, hh, ll);
        *(uint32_t*)&atthi[r0 + j * 8] = hh;
        *(uint32_t*)&attlo[r0 + j * 8] = ll;
        split_pack2(o[j][2] * invB, o[j][3] * invB, hh, ll);
        *(uint32_t*)&atthi[r1 + j * 8] = hh;
        *(uint32_t*)&attlo[r1 + j * 8] = ll;
    }
}

// ---------------------------------------------------------------------------
extern "C" void kernel_launch(void* const* d_in, const int* in_sizes, int n_in,
                              void* d_out, int out_size)
{
    const float* x  = (const float*)d_in[0];
    const float* wq = (const float*)d_in[1];
    const float* bq = (const float*)d_in[2];
    const float* wk = (const float*)d_in[3];
    const float* bk = (const float*)d_in[4];
    const float* wv = (const float*)d_in[5];
    const float* bv = (const float*)d_in[6];
    const float* wo = (const float*)d_in[7];
    const float* bo = (const float*)d_in[8];
    float* out = (float*)d_out;

    __nv_bfloat16 *xhi, *xlo, *whi, *wlo;
    __nv_bfloat16 *qhi, *qlo, *khi, *klo, *vhi, *vlo, *ahi, *alo;
    cudaGetSymbolAddress((void**)&xhi, g_xhi);
    cudaGetSymbolAddress((void**)&xlo, g_xlo);
    cudaGetSymbolAddress((void**)&whi, g_whi);
    cudaGetSymbolAddress((void**)&wlo, g_wlo);
    cudaGetSymbolAddress((void**)&qhi, g_qhi);
    cudaGetSymbolAddress((void**)&qlo, g_qlo);
    cudaGetSymbolAddress((void**)&khi, g_khi);
    cudaGetSymbolAddress((void**)&klo, g_klo);
    cudaGetSymbolAddress((void**)&vhi, g_vhi);
    cudaGetSymbolAddress((void**)&vlo, g_vlo);
    cudaGetSymbolAddress((void**)&ahi, g_ahi);
    cudaGetSymbolAddress((void**)&alo, g_alo);

    const int NX = 8192 * 1024, NW = 1024 * 1024;
    convert_split<<<NX / 4 / 256, 256>>>(x,  xhi, xlo, NX);
    convert_split<<<NW / 4 / 256, 256>>>(wq, whi + 0 * NW, wlo + 0 * NW, NW);
    convert_split<<<NW / 4 / 256, 256>>>(wk, whi + 1 * NW, wlo + 1 * NW, NW);
    convert_split<<<NW / 4 / 256, 256>>>(wv, whi + 2 * NW, wlo + 2 * NW, NW);
    convert_split<<<NW / 4 / 256, 256>>>(wo, whi + 3 * NW, wlo + 3 * NW, NW);

    const int SMEM_GEMM = 2 * 4 * 16384 + 1024;   // 132096 bytes
    const int SMEM_ATTN = 96 * 1024 + 1024;       // 99328 bytes
    cudaFuncSetAttribute(gemm_bf16, cudaFuncAttributeMaxDynamicSharedMemorySize, SMEM_GEMM);
    cudaFuncSetAttribute(attn_tc,  cudaFuncAttributeMaxDynamicSharedMemorySize, SMEM_ATTN);

    dim3 gemmGrid(1024 / 128, 8192 / 128);  // (8, 64)
    gemm_bf16<<<gemmGrid, 256, SMEM_GEMM>>>(xhi, xlo, whi + 0 * NW, wlo + 0 * NW,
                                            bq, nullptr, qhi, qlo, 0.125f, 1);
    gemm_bf16<<<gemmGrid, 256, SMEM_GEMM>>>(xhi, xlo, whi + 1 * NW, wlo + 1 * NW,
                                            bk, nullptr, khi, klo, 1.0f, 1);
    gemm_bf16<<<gemmGrid, 256, SMEM_GEMM>>>(xhi, xlo, whi + 2 * NW, wlo + 2 * NW,
                                            bv, nullptr, vhi, vlo, 1.0f, 1);

    dim3 attnGrid(T_ / 128, B_ * H_);       // (16, 64)
    attn_tc<<<attnGrid, 256, SMEM_ATTN>>>(qhi, qlo, khi, klo, vhi, vlo, ahi, alo);

    gemm_bf16<<<gemmGrid, 256, SMEM_GEMM>>>(ahi, alo, whi + 3 * NW, wlo + 3 * NW,
                                            bo, out, nullptr, nullptr, 1.0f, 0);
}

// round 14
// speedup vs baseline: 2.9548x; 1.1798x over previous
#include <cuda_runtime.h>
#include <cuda_bf16.h>
#include <cuda_fp16.h>
#include <math.h>
#include <stdint.h>

#define B_ 4
#define T_ 2048
#define D_ 1024
#define H_ 16
#define DK_ 64

// Scratch (allocation-free rule)
__device__ __nv_bfloat16 g_xhi[8192*1024], g_xlo[8192*1024];
__device__ __nv_bfloat16 g_whi[4*1024*1024], g_wlo[4*1024*1024];   // wq,wk,wv,wo
__device__ __half        g_qh[64*2048*64], g_kh[64*2048*64], g_vh[64*2048*64];
__device__ __nv_bfloat16 g_ahi[8192*1024], g_alo[8192*1024];

// ---------------------------------------------------------------------------
// Portable primitives
// ---------------------------------------------------------------------------
__device__ __forceinline__ uint32_t smem_u32(const void* p) {
    uint32_t r;
    asm("{ .reg .u64 t; cvta.to.shared.u64 t, %1; cvt.u32.u64 %0, t; }"
        : "=r"(r) : "l"(p));
    return r;
}
__device__ __forceinline__ void ldsm_x4(uint32_t* r, uint32_t addr) {
    asm volatile("ldmatrix.sync.aligned.m8n8.x4.shared.b16 {%0,%1,%2,%3}, [%4];"
        : "=r"(r[0]), "=r"(r[1]), "=r"(r[2]), "=r"(r[3]) : "r"(addr));
}
__device__ __forceinline__ void ldsm_x4_t(uint32_t* r, uint32_t addr) {
    asm volatile("ldmatrix.sync.aligned.m8n8.x4.trans.shared.b16 {%0,%1,%2,%3}, [%4];"
        : "=r"(r[0]), "=r"(r[1]), "=r"(r[2]), "=r"(r[3]) : "r"(addr));
}
__device__ __forceinline__ void ldsm_x2(uint32_t* r, uint32_t addr) {
    asm volatile("ldmatrix.sync.aligned.m8n8.x2.shared.b16 {%0,%1}, [%2];"
        : "=r"(r[0]), "=r"(r[1]) : "r"(addr));
}
__device__ __forceinline__ void mma_bf16(float* c, const uint32_t* a, const uint32_t* b) {
    asm volatile(
        "mma.sync.aligned.m16n8k16.row.col.f32.bf16.bf16.f32 "
        "{%0,%1,%2,%3}, {%4,%5,%6,%7}, {%8,%9}, {%0,%1,%2,%3};"
        : "+f"(c[0]), "+f"(c[1]), "+f"(c[2]), "+f"(c[3])
        : "r"(a[0]), "r"(a[1]), "r"(a[2]), "r"(a[3]), "r"(b[0]), "r"(b[1]));
}
__device__ __forceinline__ void mma_f16(float* c, const uint32_t* a, const uint32_t* b) {
    asm volatile(
        "mma.sync.aligned.m16n8k16.row.col.f32.f16.f16.f32 "
        "{%0,%1,%2,%3}, {%4,%5,%6,%7}, {%8,%9}, {%0,%1,%2,%3};"
        : "+f"(c[0]), "+f"(c[1]), "+f"(c[2]), "+f"(c[3])
        : "r"(a[0]), "r"(a[1]), "r"(a[2]), "r"(a[3]), "r"(b[0]), "r"(b[1]));
}
__device__ __forceinline__ void cp16(uint32_t saddr, const void* g) {
    asm volatile("cp.async.cg.shared.global [%0], [%1], 16;" :: "r"(saddr), "l"(g));
}
#define CP_COMMIT() asm volatile("cp.async.commit_group;" ::: "memory")
#define CP_WAIT0()  asm volatile("cp.async.wait_group 0;" ::: "memory")
#define CP_WAIT1()  asm volatile("cp.async.wait_group 1;" ::: "memory")

#define SWZ(o) ((o) ^ (((o) >> 3) & 0x70))

__device__ __forceinline__ uint32_t pack2_bf16(float x, float y) {
    __nv_bfloat16 hx = __float2bfloat16_rn(x);
    __nv_bfloat16 hy = __float2bfloat16_rn(y);
    return (uint32_t)__bfloat16_as_ushort(hx) |
           ((uint32_t)__bfloat16_as_ushort(hy) << 16);
}
__device__ __forceinline__ void split_pack2(float x, float y, uint32_t& hi, uint32_t& lo) {
    __nv_bfloat16 hx = __float2bfloat16_rn(x);
    __nv_bfloat16 hy = __float2bfloat16_rn(y);
    float rx = x - __bfloat162float(hx);
    float ry = y - __bfloat162float(hy);
    hi = (uint32_t)__bfloat16_as_ushort(hx) | ((uint32_t)__bfloat16_as_ushort(hy) << 16);
    lo = pack2_bf16(rx, ry);
}
__device__ __forceinline__ uint32_t pack2_f16(float x, float y) {
    __half2 h = __floats2half2_rn(x, y);
    return *(uint32_t*)&h;
}

// ---------------------------------------------------------------------------
// fp32 -> bf16 hi/lo split (one-time; x and weights)
// ---------------------------------------------------------------------------
__global__ void convert_split(const float* __restrict__ src,
                              __nv_bfloat16* __restrict__ hi,
                              __nv_bfloat16* __restrict__ lo, int n)
{
    int i = (blockIdx.x * blockDim.x + threadIdx.x) * 4;
    if (i < n) {
        float4 f = *(const float4*)(src + i);
        uint32_t h01, l01, h23, l23;
        split_pack2(f.x, f.y, h01, l01);
        split_pack2(f.z, f.w, h23, l23);
        *(uint2*)(hi + i) = make_uint2(h01, h23);
        *(uint2*)(lo + i) = make_uint2(l01, l23);
    }
}

// ---------------------------------------------------------------------------
// Split-bf16 tensor-core GEMM (validated): C = A @ W^T + bias.
// qkvLayout=1: scale + SINGLE fp16 store to outH in [B,H,T,DK];
// else fp32 row-major to outF.
// ---------------------------------------------------------------------------
__global__ __launch_bounds__(256, 1) void gemm_bf16(
    const __nv_bfloat16* __restrict__ Ahi, const __nv_bfloat16* __restrict__ Alo,
    const __nv_bfloat16* __restrict__ Whi, const __nv_bfloat16* __restrict__ Wlo,
    const float* __restrict__ bias,
    float* __restrict__ outF, __half* __restrict__ outH,
    float scale, int qkvLayout)
{
    extern __shared__ char dsm_raw[];
    char* dsm = (char*)(((uintptr_t)dsm_raw + 1023) & ~(uintptr_t)1023);

    const int tid  = threadIdx.x;
    const int lane = tid & 31;
    const int wid  = tid >> 5;
    const int warp_m = wid >> 2;
    const int warp_n = wid & 3;
    const int m0 = blockIdx.y * 128;
    const int n0 = blockIdx.x * 128;
    const uint32_t dbase = smem_u32(dsm);

    float acc[4][4][4];
#pragma unroll
    for (int i = 0; i < 4; i++)
#pragma unroll
        for (int j = 0; j < 4; j++)
#pragma unroll
            for (int r = 0; r < 4; r++) acc[i][j][r] = 0.f;

    const uint32_t rowA = (uint32_t)(warp_m * 64 + (lane & 15));
    const uint32_t colA = (uint32_t)((lane >> 4) * 16);
    const uint32_t rowB = (uint32_t)(warp_n * 32 + (lane & 7));
    const uint32_t colB = (uint32_t)(((lane >> 3) & 1) * 16);

    const int srow  = tid >> 1;
    const int gbase = (tid & 1) * 4;
    const __nv_bfloat16* a_h = Ahi + (size_t)(m0 + srow) * 1024;
    const __nv_bfloat16* a_l = Alo + (size_t)(m0 + srow) * 1024;
    const __nv_bfloat16* w_h = Whi + (size_t)(n0 + srow) * 1024;
    const __nv_bfloat16* w_l = Wlo + (size_t)(n0 + srow) * 1024;

#pragma unroll
    for (int i = 0; i < 4; i++) {
        int g = gbase + i;
        uint32_t off = SWZ((uint32_t)(srow * 128 + g * 16));
        cp16(dbase + off,          a_h + g * 8);
        cp16(dbase + 16384u + off, a_l + g * 8);
        cp16(dbase + 32768u + off, w_h + g * 8);
        cp16(dbase + 49152u + off, w_l + g * 8);
    }
    CP_COMMIT();

    const int NCH = 16;
#pragma unroll 1
    for (int kt = 0; kt < NCH; kt++) {
        const uint32_t tb = dbase + (uint32_t)(kt & 1) * 65536u;

        if (kt + 1 < NCH) {
            uint32_t nb = dbase + (uint32_t)((kt + 1) & 1) * 65536u;
            int kc = (kt + 1) * 64;
#pragma unroll
            for (int i = 0; i < 4; i++) {
                int g = gbase + i;
                uint32_t off = SWZ((uint32_t)(srow * 128 + g * 16));
                cp16(nb + off,          a_h + kc + g * 8);
                cp16(nb + 16384u + off, a_l + kc + g * 8);
                cp16(nb + 32768u + off, w_h + kc + g * 8);
                cp16(nb + 49152u + off, w_l + kc + g * 8);
            }
            CP_COMMIT();
            CP_WAIT1();
        } else {
            CP_WAIT0();
        }
        __syncthreads();

#pragma unroll
        for (int ks = 0; ks < 4; ks++) {
            uint32_t ah[4][4], al[4][4], bh[4][2], bl[4][2];
#pragma unroll
            for (int i = 0; i < 4; i++) {
                uint32_t off = (rowA + i * 16) * 128 + (uint32_t)ks * 32 + colA;
                uint32_t sw = SWZ(off);
                ldsm_x4(ah[i], tb + sw);
                ldsm_x4(al[i], tb + 16384u + sw);
            }
#pragma unroll
            for (int j = 0; j < 4; j++) {
                uint32_t off = (rowB + j * 8) * 128 + (uint32_t)ks * 32 + colB;
                uint32_t sw = SWZ(off);
                ldsm_x2(bh[j], tb + 32768u + sw);
                ldsm_x2(bl[j], tb + 49152u + sw);
            }
#pragma unroll
            for (int i = 0; i < 4; i++)
#pragma unroll
                for (int j = 0; j < 4; j++) {
                    mma_bf16(acc[i][j], ah[i], bh[j]);
                    mma_bf16(acc[i][j], ah[i], bl[j]);
                    mma_bf16(acc[i][j], al[i], bh[j]);
                }
        }
        __syncthreads();
    }

    // ---- epilogue ----
    const int mw = m0 + warp_m * 64;
    const int nw = n0 + warp_n * 32;
    const int rl = lane >> 2;
    const int cl = (lane & 3) * 2;
#pragma unroll
    for (int i = 0; i < 4; i++) {
#pragma unroll
        for (int j = 0; j < 4; j++) {
            int m = mw + i * 16 + rl;
            int n = nw + j * 8 + cl;
            float2 bv = *(const float2*)(bias + n);
            float y00 = (acc[i][j][0] + bv.x) * scale;
            float y01 = (acc[i][j][1] + bv.y) * scale;
            float y10 = (acc[i][j][2] + bv.x) * scale;
            float y11 = (acc[i][j][3] + bv.y) * scale;
            if (qkvLayout) {
                int h = n >> 6, d = n & 63;
                int b0 = m >> 11, t0 = m & 2047;
                int m1 = m + 8;
                int b1 = m1 >> 11, t1 = m1 & 2047;
                size_t i0 = ((size_t)(b0 * H_ + h) * T_ + t0) * DK_ + d;
                size_t i1 = ((size_t)(b1 * H_ + h) * T_ + t1) * DK_ + d;
                *(uint32_t*)&outH[i0] = pack2_f16(y00, y01);
                *(uint32_t*)&outH[i1] = pack2_f16(y10, y11);
            } else {
                *(float2*)(outF + (size_t)m * 1024 + n) = make_float2(y00, y01);
                *(float2*)(outF + (size_t)(m + 8) * 1024 + n) = make_float2(y10, y11);
            }
        }
    }
}

// ---------------------------------------------------------------------------
// Tensor-core causal flash attention — SINGLE-plane fp16 MMA.
// 256 threads / 8 warps, Br=128, Bc=64, DK=64. Double-buffered K/V.
// Dyn smem: Q 16KB + 2 x (K 8KB + V 8KB) = 48KB.
// Output: bf16 hi/lo att (exact split) for the final bf16-split GEMM.
// ---------------------------------------------------------------------------
__global__ __launch_bounds__(256, 1) void attn_tc(
    const __half* __restrict__ qh_g, const __half* __restrict__ kh_g,
    const __half* __restrict__ vh_g,
    __nv_bfloat16* __restrict__ atthi, __nv_bfloat16* __restrict__ attlo)
{
    extern __shared__ char dsm_raw[];
    char* dsm = (char*)(((uintptr_t)dsm_raw + 1023) & ~(uintptr_t)1023);

    const int tid  = threadIdx.x;
    const int lane = tid & 31;
    const int w    = tid >> 5;
    const int qt   = (int)gridDim.x - 1 - (int)blockIdx.x;   // heavy first
    const int bh   = blockIdx.y;
    const size_t bhoff = (size_t)bh * T_ * DK_;

    const uint32_t uQ   = smem_u32(dsm);        // 16KB (128 rows x 128B)
    const uint32_t uKV0 = uQ + 16384u;          // per buf: K 8KB, V 8KB

    // ---- Q tile load (128 rows): 2 threads/row, 4 granules/thread ----
    {
        const int srow = tid >> 1;
        const int gb   = (tid & 1) * 4;
        const __half* qp = qh_g + bhoff + (size_t)(qt * 128 + srow) * DK_;
#pragma unroll
        for (int i = 0; i < 4; i++) {
            int g = gb + i;
            uint32_t off = SWZ((uint32_t)(srow * 128 + g * 16));
            cp16(uQ + off, qp + g * 8);
        }
        CP_COMMIT();
    }

    // ---- K/V loader: 4 threads/row, 2 granules per matrix per thread ----
    const int srow2 = tid >> 2;          // 0..63
    const int gb2   = (tid & 3) * 2;
    const int ktmax = 2 * qt + 1;

    {   // prologue: KV tile 0 -> buf 0
        const __half* kp = kh_g + bhoff + (size_t)srow2 * DK_;
        const __half* vp = vh_g + bhoff + (size_t)srow2 * DK_;
#pragma unroll
        for (int i = 0; i < 2; i++) {
            int g = gb2 + i;
            uint32_t off = SWZ((uint32_t)(srow2 * 128 + g * 16));
            cp16(uKV0 + off,         kp + g * 8);
            cp16(uKV0 + 8192u + off, vp + g * 8);
        }
        CP_COMMIT();
    }

    float o[8][4];
#pragma unroll
    for (int j = 0; j < 8; j++)
#pragma unroll
        for (int r = 0; r < 4; r++) o[j][r] = 0.f;
    float m0v = -1e30f, m1v = -1e30f, l0v = 0.f, l1v = 0.f;

    const int qrow0 = qt * 128 + w * 16 + (lane >> 2);

    const uint32_t qRow = (uint32_t)(w * 16 + (lane & 15));
    const uint32_t qColB = (uint32_t)((lane >> 4) * 16);
    const uint32_t kRowBase = (uint32_t)((lane >> 4) * 8 + (lane & 7));
    const uint32_t kColB = (uint32_t)(((lane >> 3) & 1) * 16);
    const uint32_t vRow = (uint32_t)(lane & 15);
    const uint32_t vColB = (uint32_t)((lane >> 4) * 16);

#pragma unroll 1
    for (int kt = 0; kt <= ktmax; kt++) {
        if (kt + 1 <= ktmax) {
            uint32_t nb = uKV0 + (uint32_t)((kt + 1) & 1) * 16384u;
            const __half* kp = kh_g + bhoff + (size_t)((kt + 1) * 64 + srow2) * DK_;
            const __half* vp = vh_g + bhoff + (size_t)((kt + 1) * 64 + srow2) * DK_;
#pragma unroll
            for (int i = 0; i < 2; i++) {
                int g = gb2 + i;
                uint32_t off = SWZ((uint32_t)(srow2 * 128 + g * 16));
                cp16(nb + off,         kp + g * 8);
                cp16(nb + 8192u + off, vp + g * 8);
            }
            CP_COMMIT();
            CP_WAIT1();     // current tile (and Q on kt=0) arrived
        } else {
            CP_WAIT0();
        }
        __syncthreads();

        const uint32_t tb = uKV0 + (uint32_t)(kt & 1) * 16384u;

        const int krel = kt * 64 - qt * 128;
        const bool full_skip = (krel > w * 16 + 15);
        const bool need_mask = !full_skip && (krel + 63 > w * 16);

        if (!full_skip) {
            // ---- S = Q K^T (single fp16 MMA, fp32 accum) ----
            float s[8][4];
#pragma unroll
            for (int j = 0; j < 8; j++)
#pragma unroll
                for (int r = 0; r < 4; r++) s[j][r] = 0.f;

#pragma unroll
            for (int ks4 = 0; ks4 < 4; ks4++) {
                uint32_t qf[4];
                uint32_t qoff = SWZ(qRow * 128 + (uint32_t)ks4 * 32 + qColB);
                ldsm_x4(qf, uQ + qoff);
#pragma unroll
                for (int nf = 0; nf < 4; nf++) {
                    uint32_t kf[4];
                    uint32_t koff = SWZ((kRowBase + (uint32_t)nf * 16) * 128 +
                                        (uint32_t)ks4 * 32 + kColB);
                    ldsm_x4(kf, tb + koff);
                    mma_f16(s[nf * 2],     qf, &kf[0]);
                    mma_f16(s[nf * 2 + 1], qf, &kf[2]);
                }
            }

            // ---- causal mask (diagonal-crossing tiles only) ----
            if (need_mask) {
#pragma unroll
                for (int j = 0; j < 8; j++) {
                    int kc = kt * 64 + j * 8 + (lane & 3) * 2;
                    if (kc     > qrow0)     s[j][0] = -1e30f;
                    if (kc + 1 > qrow0)     s[j][1] = -1e30f;
                    if (kc     > qrow0 + 8) s[j][2] = -1e30f;
                    if (kc + 1 > qrow0 + 8) s[j][3] = -1e30f;
                }
            }

            // ---- online softmax ----
            float mA = m0v, mB = m1v;
#pragma unroll
            for (int j = 0; j < 8; j++) {
                mA = fmaxf(mA, fmaxf(s[j][0], s[j][1]));
                mB = fmaxf(mB, fmaxf(s[j][2], s[j][3]));
            }
            mA = fmaxf(mA, __shfl_xor_sync(0xffffffffu, mA, 1));
            mA = fmaxf(mA, __shfl_xor_sync(0xffffffffu, mA, 2));
            mB = fmaxf(mB, __shfl_xor_sync(0xffffffffu, mB, 1));
            mB = fmaxf(mB, __shfl_xor_sync(0xffffffffu, mB, 2));

            float alphaA = __expf(m0v - mA);
            float alphaB = __expf(m1v - mB);
            float sumA = 0.f, sumB = 0.f;
#pragma unroll
            for (int j = 0; j < 8; j++) {
                s[j][0] = __expf(s[j][0] - mA);
                s[j][1] = __expf(s[j][1] - mA);
                s[j][2] = __expf(s[j][2] - mB);
                s[j][3] = __expf(s[j][3] - mB);
                sumA += s[j][0] + s[j][1];
                sumB += s[j][2] + s[j][3];
            }
            sumA += __shfl_xor_sync(0xffffffffu, sumA, 1);
            sumA += __shfl_xor_sync(0xffffffffu, sumA, 2);
            sumB += __shfl_xor_sync(0xffffffffu, sumB, 1);
            sumB += __shfl_xor_sync(0xffffffffu, sumB, 2);

            l0v = l0v * alphaA + sumA;
            l1v = l1v * alphaB + sumB;
            m0v = mA; m1v = mB;
#pragma unroll
            for (int j = 0; j < 8; j++) {
                o[j][0] *= alphaA; o[j][1] *= alphaA;
                o[j][2] *= alphaB; o[j][3] *= alphaB;
            }

            // ---- O += P V (single fp16 MMA) ----
            const uint32_t vb_ = tb + 8192u;
#pragma unroll
            for (int ks4 = 0; ks4 < 4; ks4++) {
                uint32_t pf[4];
                pf[0] = pack2_f16(s[2 * ks4][0],     s[2 * ks4][1]);
                pf[1] = pack2_f16(s[2 * ks4][2],     s[2 * ks4][3]);
                pf[2] = pack2_f16(s[2 * ks4 + 1][0], s[2 * ks4 + 1][1]);
                pf[3] = pack2_f16(s[2 * ks4 + 1][2], s[2 * ks4 + 1][3]);
#pragma unroll
                for (int nf = 0; nf < 4; nf++) {
                    uint32_t vf[4];
                    uint32_t voff = SWZ(((uint32_t)ks4 * 16 + vRow) * 128 +
                                        (uint32_t)nf * 32 + vColB);
                    ldsm_x4_t(vf, vb_ + voff);
                    mma_f16(o[nf * 2],     pf, &vf[0]);
                    mma_f16(o[nf * 2 + 1], pf, &vf[2]);
                }
            }
        }
        __syncthreads();   // all warps done with buffer kt before reuse
    }

    // ---- normalize + bf16 hi/lo split store of att ----
    float invA = 1.f / l0v;
    float invB = 1.f / l1v;
    int b = bh >> 4, h = bh & 15;
    int t0 = qt * 128 + w * 16 + (lane >> 2);
    size_t r0 = (size_t)(b * T_ + t0) * D_ + h * DK_ + (lane & 3) * 2;
    size_t r1 = (size_t)(b * T_ + t0 + 8) * D_ + h * DK_ + (lane & 3) * 2;
#pragma unroll
    for (int j = 0; j < 8; j++) {
        uint32_t hh, ll;
        split_pack2(o[j][0] * invA, o[j][1] * invA, hh, ll);
        *(uint32_t*)&atthi[r0 + j * 8] = hh;
        *(uint32_t*)&attlo[r0 + j * 8] = ll;
        split_pack2(o[j][2] * invB, o[j][3] * invB, hh, ll);
        *(uint32_t*)&atthi[r1 + j * 8] = hh;
        *(uint32_t*)&attlo[r1 + j * 8] = ll;
    }
}

// ---------------------------------------------------------------------------
extern "C" void kernel_launch(void* const* d_in, const int* in_sizes, int n_in,
                              void* d_out, int out_size)
{
    const float* x  = (const float*)d_in[0];
    const float* wq = (const float*)d_in[1];
    const float* bq = (const float*)d_in[2];
    const float* wk = (const float*)d_in[3];
    const float* bk = (const float*)d_in[4];
    const float* wv = (const float*)d_in[5];
    const float* bv = (const float*)d_in[6];
    const float* wo = (const float*)d_in[7];
    const float* bo = (const float*)d_in[8];
    float* out = (float*)d_out;

    __nv_bfloat16 *xhi, *xlo, *whi, *wlo, *ahi, *alo;
    __half *qh, *kh, *vh;
    cudaGetSymbolAddress((void**)&xhi, g_xhi);
    cudaGetSymbolAddress((void**)&xlo, g_xlo);
    cudaGetSymbolAddress((void**)&whi, g_whi);
    cudaGetSymbolAddress((void**)&wlo, g_wlo);
    cudaGetSymbolAddress((void**)&qh,  g_qh);
    cudaGetSymbolAddress((void**)&kh,  g_kh);
    cudaGetSymbolAddress((void**)&vh,  g_vh);
    cudaGetSymbolAddress((void**)&ahi, g_ahi);
    cudaGetSymbolAddress((void**)&alo, g_alo);

    const int NX = 8192 * 1024, NW = 1024 * 1024;
    convert_split<<<NX / 4 / 256, 256>>>(x,  xhi, xlo, NX);
    convert_split<<<NW / 4 / 256, 256>>>(wq, whi + 0 * NW, wlo + 0 * NW, NW);
    convert_split<<<NW / 4 / 256, 256>>>(wk, whi + 1 * NW, wlo + 1 * NW, NW);
    convert_split<<<NW / 4 / 256, 256>>>(wv, whi + 2 * NW, wlo + 2 * NW, NW);
    convert_split<<<NW / 4 / 256, 256>>>(wo, whi + 3 * NW, wlo + 3 * NW, NW);

    const int SMEM_GEMM = 2 * 4 * 16384 + 1024;   // 132096 bytes
    const int SMEM_ATTN = 48 * 1024 + 1024;       // 50176 bytes
    cudaFuncSetAttribute(gemm_bf16, cudaFuncAttributeMaxDynamicSharedMemorySize, SMEM_GEMM);
    cudaFuncSetAttribute(attn_tc,  cudaFuncAttributeMaxDynamicSharedMemorySize, SMEM_ATTN);

    dim3 gemmGrid(1024 / 128, 8192 / 128);  // (8, 64)
    gemm_bf16<<<gemmGrid, 256, SMEM_GEMM>>>(xhi, xlo, whi + 0 * NW, wlo + 0 * NW,
                                            bq, nullptr, qh, 0.125f, 1);
    gemm_bf16<<<gemmGrid, 256, SMEM_GEMM>>>(xhi, xlo, whi + 1 * NW, wlo + 1 * NW,
                                            bk, nullptr, kh, 1.0f, 1);
    gemm_bf16<<<gemmGrid, 256, SMEM_GEMM>>>(xhi, xlo, whi + 2 * NW, wlo + 2 * NW,
                                            bv, nullptr, vh, 1.0f, 1);

    dim3 attnGrid(T_ / 128, B_ * H_);       // (16, 64)
    attn_tc<<<attnGrid, 256, SMEM_ATTN>>>(qh, kh, vh, ahi, alo);

    gemm_bf16<<<gemmGrid, 256, SMEM_GEMM>>>(ahi, alo, whi + 3 * NW, wlo + 3 * NW,
                                            bo, out, nullptr, 1.0f, 0);
}

// round 15
// speedup vs baseline: 3.7182x; 1.2584x over previous
#include <cuda_runtime.h>
#include <cuda_bf16.h>
#include <cuda_fp16.h>
#include <math.h>
#include <stdint.h>

#define B_ 4
#define T_ 2048
#define D_ 1024
#define H_ 16
#define DK_ 64

// Scratch (allocation-free rule): fp16 planes
__device__ __half g_xh[8192*1024], g_xl[8192*1024];     // x hi/lo
__device__ __half g_wh[4*1024*1024];                    // wq,wk,wv,wo single
__device__ __half g_qh[64*2048*64], g_kh[64*2048*64], g_vh[64*2048*64];
__device__ __half g_ath[8192*1024], g_atl[8192*1024];   // att hi/lo

// ---------------------------------------------------------------------------
// Portable primitives
// ---------------------------------------------------------------------------
__device__ __forceinline__ uint32_t smem_u32(const void* p) {
    uint32_t r;
    asm("{ .reg .u64 t; cvta.to.shared.u64 t, %1; cvt.u32.u64 %0, t; }"
        : "=r"(r) : "l"(p));
    return r;
}
__device__ __forceinline__ void ldsm_x4(uint32_t* r, uint32_t addr) {
    asm volatile("ldmatrix.sync.aligned.m8n8.x4.shared.b16 {%0,%1,%2,%3}, [%4];"
        : "=r"(r[0]), "=r"(r[1]), "=r"(r[2]), "=r"(r[3]) : "r"(addr));
}
__device__ __forceinline__ void ldsm_x4_t(uint32_t* r, uint32_t addr) {
    asm volatile("ldmatrix.sync.aligned.m8n8.x4.trans.shared.b16 {%0,%1,%2,%3}, [%4];"
        : "=r"(r[0]), "=r"(r[1]), "=r"(r[2]), "=r"(r[3]) : "r"(addr));
}
__device__ __forceinline__ void ldsm_x2(uint32_t* r, uint32_t addr) {
    asm volatile("ldmatrix.sync.aligned.m8n8.x2.shared.b16 {%0,%1}, [%2];"
        : "=r"(r[0]), "=r"(r[1]) : "r"(addr));
}
__device__ __forceinline__ void mma_f16(float* c, const uint32_t* a, const uint32_t* b) {
    asm volatile(
        "mma.sync.aligned.m16n8k16.row.col.f32.f16.f16.f32 "
        "{%0,%1,%2,%3}, {%4,%5,%6,%7}, {%8,%9}, {%0,%1,%2,%3};"
        : "+f"(c[0]), "+f"(c[1]), "+f"(c[2]), "+f"(c[3])
        : "r"(a[0]), "r"(a[1]), "r"(a[2]), "r"(a[3]), "r"(b[0]), "r"(b[1]));
}
__device__ __forceinline__ void cp16(uint32_t saddr, const void* g) {
    asm volatile("cp.async.cg.shared.global [%0], [%1], 16;" :: "r"(saddr), "l"(g));
}
#define CP_COMMIT() asm volatile("cp.async.commit_group;" ::: "memory")
#define CP_WAIT0()  asm volatile("cp.async.wait_group 0;" ::: "memory")
#define CP_WAIT1()  asm volatile("cp.async.wait_group 1;" ::: "memory")

#define SWZ(o) ((o) ^ (((o) >> 3) & 0x70))

__device__ __forceinline__ uint32_t pack2_f16(float x, float y) {
    __half2 h = __floats2half2_rn(x, y);
    return *(uint32_t*)&h;
}
// fp16 hi/lo split of a pair
__device__ __forceinline__ void split_pack2_f16(float x, float y, uint32_t& hi, uint32_t& lo) {
    __half hx = __float2half_rn(x);
    __half hy = __float2half_rn(y);
    float rx = x - __half2float(hx);
    float ry = y - __half2float(hy);
    hi = (uint32_t)__half_as_ushort(hx) | ((uint32_t)__half_as_ushort(hy) << 16);
    lo = pack2_f16(rx, ry);
}

// ---------------------------------------------------------------------------
// One-time converts
// ---------------------------------------------------------------------------
__global__ void convertf16_split(const float* __restrict__ src,
                                 __half* __restrict__ hi, __half* __restrict__ lo, int n)
{
    int i = (blockIdx.x * blockDim.x + threadIdx.x) * 4;
    if (i < n) {
        float4 f = *(const float4*)(src + i);
        uint32_t h01, l01, h23, l23;
        split_pack2_f16(f.x, f.y, h01, l01);
        split_pack2_f16(f.z, f.w, h23, l23);
        *(uint2*)(hi + i) = make_uint2(h01, h23);
        *(uint2*)(lo + i) = make_uint2(l01, l23);
    }
}
__global__ void convertf16(const float* __restrict__ src, __half* __restrict__ dst, int n)
{
    int i = (blockIdx.x * blockDim.x + threadIdx.x) * 4;
    if (i < n) {
        float4 f = *(const float4*)(src + i);
        *(uint2*)(dst + i) = make_uint2(pack2_f16(f.x, f.y), pack2_f16(f.z, f.w));
    }
}

// ---------------------------------------------------------------------------
// fp16 2-MMA tensor-core GEMM: C = (Ah+Al) @ W^T + bias.
// A hi/lo fp16 planes (exact split), W single fp16 plane.
// 128x128 CTA tile, 8 warps, K chunks of 64, double-buffered smem
// (Ah,Al,W 16KB each x 2 = 96KB). qkvLayout=1: scale + fp16 store to outH in
// [B,H,T,DK]; else fp32 row-major to outF.
// ---------------------------------------------------------------------------
__global__ __launch_bounds__(256, 1) void gemm_f16(
    const __half* __restrict__ Ahp, const __half* __restrict__ Alp,
    const __half* __restrict__ Wp,
    const float* __restrict__ bias,
    float* __restrict__ outF, __half* __restrict__ outH,
    float scale, int qkvLayout)
{
    extern __shared__ char dsm_raw[];
    char* dsm = (char*)(((uintptr_t)dsm_raw + 1023) & ~(uintptr_t)1023);

    const int tid  = threadIdx.x;
    const int lane = tid & 31;
    const int wid  = tid >> 5;
    const int warp_m = wid >> 2;
    const int warp_n = wid & 3;
    const int m0 = blockIdx.y * 128;
    const int n0 = blockIdx.x * 128;
    const uint32_t dbase = smem_u32(dsm);

    float acc[4][4][4];
#pragma unroll
    for (int i = 0; i < 4; i++)
#pragma unroll
        for (int j = 0; j < 4; j++)
#pragma unroll
            for (int r = 0; r < 4; r++) acc[i][j][r] = 0.f;

    const uint32_t rowA = (uint32_t)(warp_m * 64 + (lane & 15));
    const uint32_t colA = (uint32_t)((lane >> 4) * 16);
    const uint32_t rowB = (uint32_t)(warp_n * 32 + (lane & 7));
    const uint32_t colB = (uint32_t)(((lane >> 3) & 1) * 16);

    // staging: 2 threads/row, 4 x 16B granules per plane per thread
    const int srow  = tid >> 1;
    const int gbase = (tid & 1) * 4;
    const __half* a_h = Ahp + (size_t)(m0 + srow) * 1024;
    const __half* a_l = Alp + (size_t)(m0 + srow) * 1024;
    const __half* w_p = Wp  + (size_t)(n0 + srow) * 1024;

    const uint32_t BUF = 49152u;   // 3 x 16KB planes per buffer

#pragma unroll
    for (int i = 0; i < 4; i++) {
        int g = gbase + i;
        uint32_t off = SWZ((uint32_t)(srow * 128 + g * 16));
        cp16(dbase + off,          a_h + g * 8);
        cp16(dbase + 16384u + off, a_l + g * 8);
        cp16(dbase + 32768u + off, w_p + g * 8);
    }
    CP_COMMIT();

    const int NCH = 16;
#pragma unroll 1
    for (int kt = 0; kt < NCH; kt++) {
        const uint32_t tb = dbase + (uint32_t)(kt & 1) * BUF;

        if (kt + 1 < NCH) {
            uint32_t nb = dbase + (uint32_t)((kt + 1) & 1) * BUF;
            int kc = (kt + 1) * 64;
#pragma unroll
            for (int i = 0; i < 4; i++) {
                int g = gbase + i;
                uint32_t off = SWZ((uint32_t)(srow * 128 + g * 16));
                cp16(nb + off,          a_h + kc + g * 8);
                cp16(nb + 16384u + off, a_l + kc + g * 8);
                cp16(nb + 32768u + off, w_p + kc + g * 8);
            }
            CP_COMMIT();
            CP_WAIT1();
        } else {
            CP_WAIT0();
        }
        __syncthreads();

#pragma unroll
        for (int ks = 0; ks < 4; ks++) {
            uint32_t ah[4][4], al[4][4], bw[4][2];
#pragma unroll
            for (int i = 0; i < 4; i++) {
                uint32_t off = (rowA + i * 16) * 128 + (uint32_t)ks * 32 + colA;
                uint32_t sw = SWZ(off);
                ldsm_x4(ah[i], tb + sw);
                ldsm_x4(al[i], tb + 16384u + sw);
            }
#pragma unroll
            for (int j = 0; j < 4; j++) {
                uint32_t off = (rowB + j * 8) * 128 + (uint32_t)ks * 32 + colB;
                ldsm_x2(bw[j], tb + 32768u + SWZ(off));
            }
#pragma unroll
            for (int i = 0; i < 4; i++)
#pragma unroll
                for (int j = 0; j < 4; j++) {
                    mma_f16(acc[i][j], ah[i], bw[j]);
                    mma_f16(acc[i][j], al[i], bw[j]);
                }
        }
        __syncthreads();
    }

    // ---- epilogue ----
    const int mw = m0 + warp_m * 64;
    const int nw = n0 + warp_n * 32;
    const int rl = lane >> 2;
    const int cl = (lane & 3) * 2;
#pragma unroll
    for (int i = 0; i < 4; i++) {
#pragma unroll
        for (int j = 0; j < 4; j++) {
            int m = mw + i * 16 + rl;
            int n = nw + j * 8 + cl;
            float2 bv = *(const float2*)(bias + n);
            float y00 = (acc[i][j][0] + bv.x) * scale;
            float y01 = (acc[i][j][1] + bv.y) * scale;
            float y10 = (acc[i][j][2] + bv.x) * scale;
            float y11 = (acc[i][j][3] + bv.y) * scale;
            if (qkvLayout) {
                int h = n >> 6, d = n & 63;
                int b0 = m >> 11, t0 = m & 2047;
                int m1 = m + 8;
                int b1 = m1 >> 11, t1 = m1 & 2047;
                size_t i0 = ((size_t)(b0 * H_ + h) * T_ + t0) * DK_ + d;
                size_t i1 = ((size_t)(b1 * H_ + h) * T_ + t1) * DK_ + d;
                *(uint32_t*)&outH[i0] = pack2_f16(y00, y01);
                *(uint32_t*)&outH[i1] = pack2_f16(y10, y11);
            } else {
                *(float2*)(outF + (size_t)m * 1024 + n) = make_float2(y00, y01);
                *(float2*)(outF + (size_t)(m + 8) * 1024 + n) = make_float2(y10, y11);
            }
        }
    }
}

// ---------------------------------------------------------------------------
// Tensor-core causal flash attention — single-plane fp16 MMA (validated R14).
// 256 threads / 8 warps, Br=128, Bc=64, DK=64. Double-buffered K/V.
// Dyn smem: Q 16KB + 2 x (K 8KB + V 8KB) = 48KB.
// Output: fp16 hi/lo att planes for the final fp16 2-MMA GEMM.
// ---------------------------------------------------------------------------
__global__ __launch_bounds__(256, 1) void attn_tc(
    const __half* __restrict__ qh_g, const __half* __restrict__ kh_g,
    const __half* __restrict__ vh_g,
    __half* __restrict__ atth, __half* __restrict__ attl)
{
    extern __shared__ char dsm_raw[];
    char* dsm = (char*)(((uintptr_t)dsm_raw + 1023) & ~(uintptr_t)1023);

    const int tid  = threadIdx.x;
    const int lane = tid & 31;
    const int w    = tid >> 5;
    const int qt   = (int)gridDim.x - 1 - (int)blockIdx.x;   // heavy first
    const int bh   = blockIdx.y;
    const size_t bhoff = (size_t)bh * T_ * DK_;

    const uint32_t uQ   = smem_u32(dsm);        // 16KB (128 rows x 128B)
    const uint32_t uKV0 = uQ + 16384u;          // per buf: K 8KB, V 8KB

    // ---- Q tile load ----
    {
        const int srow = tid >> 1;
        const int gb   = (tid & 1) * 4;
        const __half* qp = qh_g + bhoff + (size_t)(qt * 128 + srow) * DK_;
#pragma unroll
        for (int i = 0; i < 4; i++) {
            int g = gb + i;
            uint32_t off = SWZ((uint32_t)(srow * 128 + g * 16));
            cp16(uQ + off, qp + g * 8);
        }
        CP_COMMIT();
    }

    const int srow2 = tid >> 2;          // 0..63
    const int gb2   = (tid & 3) * 2;
    const int ktmax = 2 * qt + 1;

    {   // prologue: KV tile 0 -> buf 0
        const __half* kp = kh_g + bhoff + (size_t)srow2 * DK_;
        const __half* vp = vh_g + bhoff + (size_t)srow2 * DK_;
#pragma unroll
        for (int i = 0; i < 2; i++) {
            int g = gb2 + i;
            uint32_t off = SWZ((uint32_t)(srow2 * 128 + g * 16));
            cp16(uKV0 + off,         kp + g * 8);
            cp16(uKV0 + 8192u + off, vp + g * 8);
        }
        CP_COMMIT();
    }

    float o[8][4];
#pragma unroll
    for (int j = 0; j < 8; j++)
#pragma unroll
        for (int r = 0; r < 4; r++) o[j][r] = 0.f;
    float m0v = -1e30f, m1v = -1e30f, l0v = 0.f, l1v = 0.f;

    const int qrow0 = qt * 128 + w * 16 + (lane >> 2);

    const uint32_t qRow = (uint32_t)(w * 16 + (lane & 15));
    const uint32_t qColB = (uint32_t)((lane >> 4) * 16);
    const uint32_t kRowBase = (uint32_t)((lane >> 4) * 8 + (lane & 7));
    const uint32_t kColB = (uint32_t)(((lane >> 3) & 1) * 16);
    const uint32_t vRow = (uint32_t)(lane & 15);
    const uint32_t vColB = (uint32_t)((lane >> 4) * 16);

#pragma unroll 1
    for (int kt = 0; kt <= ktmax; kt++) {
        if (kt + 1 <= ktmax) {
            uint32_t nb = uKV0 + (uint32_t)((kt + 1) & 1) * 16384u;
            const __half* kp = kh_g + bhoff + (size_t)((kt + 1) * 64 + srow2) * DK_;
            const __half* vp = vh_g + bhoff + (size_t)((kt + 1) * 64 + srow2) * DK_;
#pragma unroll
            for (int i = 0; i < 2; i++) {
                int g = gb2 + i;
                uint32_t off = SWZ((uint32_t)(srow2 * 128 + g * 16));
                cp16(nb + off,         kp + g * 8);
                cp16(nb + 8192u + off, vp + g * 8);
            }
            CP_COMMIT();
            CP_WAIT1();
        } else {
            CP_WAIT0();
        }
        __syncthreads();

        const uint32_t tb = uKV0 + (uint32_t)(kt & 1) * 16384u;

        const int krel = kt * 64 - qt * 128;
        const bool full_skip = (krel > w * 16 + 15);
        const bool need_mask = !full_skip && (krel + 63 > w * 16);

        if (!full_skip) {
            float s[8][4];
#pragma unroll
            for (int j = 0; j < 8; j++)
#pragma unroll
                for (int r = 0; r < 4; r++) s[j][r] = 0.f;

#pragma unroll
            for (int ks4 = 0; ks4 < 4; ks4++) {
                uint32_t qf[4];
                uint32_t qoff = SWZ(qRow * 128 + (uint32_t)ks4 * 32 + qColB);
                ldsm_x4(qf, uQ + qoff);
#pragma unroll
                for (int nf = 0; nf < 4; nf++) {
                    uint32_t kf[4];
                    uint32_t koff = SWZ((kRowBase + (uint32_t)nf * 16) * 128 +
                                        (uint32_t)ks4 * 32 + kColB);
                    ldsm_x4(kf, tb + koff);
                    mma_f16(s[nf * 2],     qf, &kf[0]);
                    mma_f16(s[nf * 2 + 1], qf, &kf[2]);
                }
            }

            if (need_mask) {
#pragma unroll
                for (int j = 0; j < 8; j++) {
                    int kc = kt * 64 + j * 8 + (lane & 3) * 2;
                    if (kc     > qrow0)     s[j][0] = -1e30f;
                    if (kc + 1 > qrow0)     s[j][1] = -1e30f;
                    if (kc     > qrow0 + 8) s[j][2] = -1e30f;
                    if (kc + 1 > qrow0 + 8) s[j][3] = -1e30f;
                }
            }

            float mA = m0v, mB = m1v;
#pragma unroll
            for (int j = 0; j < 8; j++) {
                mA = fmaxf(mA, fmaxf(s[j][0], s[j][1]));
                mB = fmaxf(mB, fmaxf(s[j][2], s[j][3]));
            }
            mA = fmaxf(mA, __shfl_xor_sync(0xffffffffu, mA, 1));
            mA = fmaxf(mA, __shfl_xor_sync(0xffffffffu, mA, 2));
            mB = fmaxf(mB, __shfl_xor_sync(0xffffffffu, mB, 1));
            mB = fmaxf(mB, __shfl_xor_sync(0xffffffffu, mB, 2));

            float alphaA = __expf(m0v - mA);
            float alphaB = __expf(m1v - mB);
            float sumA = 0.f, sumB = 0.f;
#pragma unroll
            for (int j = 0; j < 8; j++) {
                s[j][0] = __expf(s[j][0] - mA);
                s[j][1] = __expf(s[j][1] - mA);
                s[j][2] = __expf(s[j][2] - mB);
                s[j][3] = __expf(s[j][3] - mB);
                sumA += s[j][0] + s[j][1];
                sumB += s[j][2] + s[j][3];
            }
            sumA += __shfl_xor_sync(0xffffffffu, sumA, 1);
            sumA += __shfl_xor_sync(0xffffffffu, sumA, 2);
            sumB += __shfl_xor_sync(0xffffffffu, sumB, 1);
            sumB += __shfl_xor_sync(0xffffffffu, sumB, 2);

            l0v = l0v * alphaA + sumA;
            l1v = l1v * alphaB + sumB;
            m0v = mA; m1v = mB;
#pragma unroll
            for (int j = 0; j < 8; j++) {
                o[j][0] *= alphaA; o[j][1] *= alphaA;
                o[j][2] *= alphaB; o[j][3] *= alphaB;
            }

            const uint32_t vb_ = tb + 8192u;
#pragma unroll
            for (int ks4 = 0; ks4 < 4; ks4++) {
                uint32_t pf[4];
                pf[0] = pack2_f16(s[2 * ks4][0],     s[2 * ks4][1]);
                pf[1] = pack2_f16(s[2 * ks4][2],     s[2 * ks4][3]);
                pf[2] = pack2_f16(s[2 * ks4 + 1][0], s[2 * ks4 + 1][1]);
                pf[3] = pack2_f16(s[2 * ks4 + 1][2], s[2 * ks4 + 1][3]);
#pragma unroll
                for (int nf = 0; nf < 4; nf++) {
                    uint32_t vf[4];
                    uint32_t voff = SWZ(((uint32_t)ks4 * 16 + vRow) * 128 +
                                        (uint32_t)nf * 32 + vColB);
                    ldsm_x4_t(vf, vb_ + voff);
                    mma_f16(o[nf * 2],     pf, &vf[0]);
                    mma_f16(o[nf * 2 + 1], pf, &vf[2]);
                }
            }
        }
        __syncthreads();
    }

    // ---- normalize + fp16 hi/lo split store of att ----
    float invA = 1.f / l0v;
    float invB = 1.f / l1v;
    int b = bh >> 4, h = bh & 15;
    int t0 = qt * 128 + w * 16 + (lane >> 2);
    size_t r0 = (size_t)(b * T_ + t0) * D_ + h * DK_ + (lane & 3) * 2;
    size_t r1 = (size_t)(b * T_ + t0 + 8) * D_ + h * DK_ + (lane & 3) * 2;
#pragma unroll
    for (int j = 0; j < 8; j++) {
        uint32_t hh, ll;
        split_pack2_f16(o[j][0] * invA, o[j][1] * invA, hh, ll);
        *(uint32_t*)&atth[r0 + j * 8] = hh;
        *(uint32_t*)&attl[r0 + j * 8] = ll;
        split_pack2_f16(o[j][2] * invB, o[j][3] * invB, hh, ll);
        *(uint32_t*)&atth[r1 + j * 8] = hh;
        *(uint32_t*)&attl[r1 + j * 8] = ll;
    }
}

// ---------------------------------------------------------------------------
extern "C" void kernel_launch(void* const* d_in, const int* in_sizes, int n_in,
                              void* d_out, int out_size)
{
    const float* x  = (const float*)d_in[0];
    const float* wq = (const float*)d_in[1];
    const float* bq = (const float*)d_in[2];
    const float* wk = (const float*)d_in[3];
    const float* bk = (const float*)d_in[4];
    const float* wv = (const float*)d_in[5];
    const float* bv = (const float*)d_in[6];
    const float* wo = (const float*)d_in[7];
    const float* bo = (const float*)d_in[8];
    float* out = (float*)d_out;

    __half *xh, *xl, *wh, *qh, *kh, *vh, *ath, *atl;
    cudaGetSymbolAddress((void**)&xh,  g_xh);
    cudaGetSymbolAddress((void**)&xl,  g_xl);
    cudaGetSymbolAddress((void**)&wh,  g_wh);
    cudaGetSymbolAddress((void**)&qh,  g_qh);
    cudaGetSymbolAddress((void**)&kh,  g_kh);
    cudaGetSymbolAddress((void**)&vh,  g_vh);
    cudaGetSymbolAddress((void**)&ath, g_ath);
    cudaGetSymbolAddress((void**)&atl, g_atl);

    const int NX = 8192 * 1024, NW = 1024 * 1024;
    convertf16_split<<<NX / 4 / 256, 256>>>(x, xh, xl, NX);
    convertf16<<<NW / 4 / 256, 256>>>(wq, wh + 0 * NW, NW);
    convertf16<<<NW / 4 / 256, 256>>>(wk, wh + 1 * NW, NW);
    convertf16<<<NW / 4 / 256, 256>>>(wv, wh + 2 * NW, NW);
    convertf16<<<NW / 4 / 256, 256>>>(wo, wh + 3 * NW, NW);

    const int SMEM_GEMM = 2 * 3 * 16384 + 1024;   // 99328 bytes
    const int SMEM_ATTN = 48 * 1024 + 1024;       // 50176 bytes
    cudaFuncSetAttribute(gemm_f16, cudaFuncAttributeMaxDynamicSharedMemorySize, SMEM_GEMM);
    cudaFuncSetAttribute(attn_tc, cudaFuncAttributeMaxDynamicSharedMemorySize, SMEM_ATTN);

    dim3 gemmGrid(1024 / 128, 8192 / 128);  // (8, 64)
    gemm_f16<<<gemmGrid, 256, SMEM_GEMM>>>(xh, xl, wh + 0 * NW,
                                           bq, nullptr, qh, 0.125f, 1);
    gemm_f16<<<gemmGrid, 256, SMEM_GEMM>>>(xh, xl, wh + 1 * NW,
                                           bk, nullptr, kh, 1.0f, 1);
    gemm_f16<<<gemmGrid, 256, SMEM_GEMM>>>(xh, xl, wh + 2 * NW,
                                           bv, nullptr, vh, 1.0f, 1);

    dim3 attnGrid(T_ / 128, B_ * H_);       // (16, 64)
    attn_tc<<<attnGrid, 256, SMEM_ATTN>>>(qh, kh, vh, ath, atl);

    gemm_f16<<<gemmGrid, 256, SMEM_GEMM>>>(ath, atl, wh + 3 * NW,
                                           bo, out, nullptr, 1.0f, 0);
}

// round 16
// speedup vs baseline: 3.9912x; 1.0734x over previous
#include <cuda_runtime.h>
#include <cuda_bf16.h>
#include <cuda_fp16.h>
#include <math.h>
#include <stdint.h>

#define B_ 4
#define T_ 2048
#define D_ 1024
#define H_ 16
#define DK_ 64

// Scratch (allocation-free rule): fp16 planes
__device__ __half g_xh[8192*1024];                      // x single plane
__device__ __half g_wh[4*1024*1024];                    // wq,wk,wv,wo single
__device__ __half g_qh[64*2048*64], g_kh[64*2048*64], g_vh[64*2048*64];
__device__ __half g_ath[8192*1024], g_atl[8192*1024];   // att hi/lo (exact split)

// ---------------------------------------------------------------------------
// Portable primitives
// ---------------------------------------------------------------------------
__device__ __forceinline__ uint32_t smem_u32(const void* p) {
    uint32_t r;
    asm("{ .reg .u64 t; cvta.to.shared.u64 t, %1; cvt.u32.u64 %0, t; }"
        : "=r"(r) : "l"(p));
    return r;
}
__device__ __forceinline__ void ldsm_x4(uint32_t* r, uint32_t addr) {
    asm volatile("ldmatrix.sync.aligned.m8n8.x4.shared.b16 {%0,%1,%2,%3}, [%4];"
        : "=r"(r[0]), "=r"(r[1]), "=r"(r[2]), "=r"(r[3]) : "r"(addr));
}
__device__ __forceinline__ void ldsm_x4_t(uint32_t* r, uint32_t addr) {
    asm volatile("ldmatrix.sync.aligned.m8n8.x4.trans.shared.b16 {%0,%1,%2,%3}, [%4];"
        : "=r"(r[0]), "=r"(r[1]), "=r"(r[2]), "=r"(r[3]) : "r"(addr));
}
__device__ __forceinline__ void ldsm_x2(uint32_t* r, uint32_t addr) {
    asm volatile("ldmatrix.sync.aligned.m8n8.x2.shared.b16 {%0,%1}, [%2];"
        : "=r"(r[0]), "=r"(r[1]) : "r"(addr));
}
__device__ __forceinline__ void mma_f16(float* c, const uint32_t* a, const uint32_t* b) {
    asm volatile(
        "mma.sync.aligned.m16n8k16.row.col.f32.f16.f16.f32 "
        "{%0,%1,%2,%3}, {%4,%5,%6,%7}, {%8,%9}, {%0,%1,%2,%3};"
        : "+f"(c[0]), "+f"(c[1]), "+f"(c[2]), "+f"(c[3])
        : "r"(a[0]), "r"(a[1]), "r"(a[2]), "r"(a[3]), "r"(b[0]), "r"(b[1]));
}
__device__ __forceinline__ void cp16(uint32_t saddr, const void* g) {
    asm volatile("cp.async.cg.shared.global [%0], [%1], 16;" :: "r"(saddr), "l"(g));
}
#define CP_COMMIT() asm volatile("cp.async.commit_group;" ::: "memory")
#define CP_WAIT0()  asm volatile("cp.async.wait_group 0;" ::: "memory")
#define CP_WAIT1()  asm volatile("cp.async.wait_group 1;" ::: "memory")

#define SWZ(o) ((o) ^ (((o) >> 3) & 0x70))

__device__ __forceinline__ uint32_t pack2_f16(float x, float y) {
    __half2 h = __floats2half2_rn(x, y);
    return *(uint32_t*)&h;
}
__device__ __forceinline__ void split_pack2_f16(float x, float y, uint32_t& hi, uint32_t& lo) {
    __half hx = __float2half_rn(x);
    __half hy = __float2half_rn(y);
    float rx = x - __half2float(hx);
    float ry = y - __half2float(hy);
    hi = (uint32_t)__half_as_ushort(hx) | ((uint32_t)__half_as_ushort(hy) << 16);
    lo = pack2_f16(rx, ry);
}

// ---------------------------------------------------------------------------
// One-time convert (fp32 -> single fp16 plane)
// ---------------------------------------------------------------------------
__global__ void convertf16(const float* __restrict__ src, __half* __restrict__ dst, int n)
{
    int i = (blockIdx.x * blockDim.x + threadIdx.x) * 4;
    if (i < n) {
        float4 f = *(const float4*)(src + i);
        *(uint2*)(dst + i) = make_uint2(pack2_f16(f.x, f.y), pack2_f16(f.z, f.w));
    }
}

// ---------------------------------------------------------------------------
// fp16 tensor-core GEMM: C = (Ah [+ Al]) @ W^T + bias.
// twoPlane=1: A hi/lo fp16 planes (exact split, 2 MMAs); else single (1 MMA).
// 128x128 CTA tile, 8 warps, K chunks of 64, double-buffered smem
// (Ah,Al,W 16KB planes x 2 bufs). qkvLayout=1: scale + fp16 store to outH in
// [B,H,T,DK]; else fp32 row-major to outF.
// ---------------------------------------------------------------------------
__global__ __launch_bounds__(256, 1) void gemm_f16(
    const __half* __restrict__ Ahp, const __half* __restrict__ Alp,
    const __half* __restrict__ Wp,
    const float* __restrict__ bias,
    float* __restrict__ outF, __half* __restrict__ outH,
    float scale, int qkvLayout, int twoPlane)
{
    extern __shared__ char dsm_raw[];
    char* dsm = (char*)(((uintptr_t)dsm_raw + 1023) & ~(uintptr_t)1023);

    const int tid  = threadIdx.x;
    const int lane = tid & 31;
    const int wid  = tid >> 5;
    const int warp_m = wid >> 2;
    const int warp_n = wid & 3;
    const int m0 = blockIdx.y * 128;
    const int n0 = blockIdx.x * 128;
    const uint32_t dbase = smem_u32(dsm);

    float acc[4][4][4];
#pragma unroll
    for (int i = 0; i < 4; i++)
#pragma unroll
        for (int j = 0; j < 4; j++)
#pragma unroll
            for (int r = 0; r < 4; r++) acc[i][j][r] = 0.f;

    const uint32_t rowA = (uint32_t)(warp_m * 64 + (lane & 15));
    const uint32_t colA = (uint32_t)((lane >> 4) * 16);
    const uint32_t rowB = (uint32_t)(warp_n * 32 + (lane & 7));
    const uint32_t colB = (uint32_t)(((lane >> 3) & 1) * 16);

    // staging: 2 threads/row, 4 x 16B granules per plane per thread
    const int srow  = tid >> 1;
    const int gbase = (tid & 1) * 4;
    const __half* a_h = Ahp + (size_t)(m0 + srow) * 1024;
    const __half* a_l = twoPlane ? (Alp + (size_t)(m0 + srow) * 1024) : a_h;
    const __half* w_p = Wp  + (size_t)(n0 + srow) * 1024;

    const uint32_t BUF = 49152u;   // 3 x 16KB planes per buffer

#pragma unroll
    for (int i = 0; i < 4; i++) {
        int g = gbase + i;
        uint32_t off = SWZ((uint32_t)(srow * 128 + g * 16));
        cp16(dbase + off,          a_h + g * 8);
        if (twoPlane) cp16(dbase + 16384u + off, a_l + g * 8);
        cp16(dbase + 32768u + off, w_p + g * 8);
    }
    CP_COMMIT();

    const int NCH = 16;
#pragma unroll 1
    for (int kt = 0; kt < NCH; kt++) {
        const uint32_t tb = dbase + (uint32_t)(kt & 1) * BUF;

        if (kt + 1 < NCH) {
            uint32_t nb = dbase + (uint32_t)((kt + 1) & 1) * BUF;
            int kc = (kt + 1) * 64;
#pragma unroll
            for (int i = 0; i < 4; i++) {
                int g = gbase + i;
                uint32_t off = SWZ((uint32_t)(srow * 128 + g * 16));
                cp16(nb + off,          a_h + kc + g * 8);
                if (twoPlane) cp16(nb + 16384u + off, a_l + kc + g * 8);
                cp16(nb + 32768u + off, w_p + kc + g * 8);
            }
            CP_COMMIT();
            CP_WAIT1();
        } else {
            CP_WAIT0();
        }
        __syncthreads();

#pragma unroll
        for (int ks = 0; ks < 4; ks++) {
            uint32_t ah[4][4], al[4][4], bw[4][2];
#pragma unroll
            for (int i = 0; i < 4; i++) {
                uint32_t off = (rowA + i * 16) * 128 + (uint32_t)ks * 32 + colA;
                uint32_t sw = SWZ(off);
                ldsm_x4(ah[i], tb + sw);
                if (twoPlane) ldsm_x4(al[i], tb + 16384u + sw);
            }
#pragma unroll
            for (int j = 0; j < 4; j++) {
                uint32_t off = (rowB + j * 8) * 128 + (uint32_t)ks * 32 + colB;
                ldsm_x2(bw[j], tb + 32768u + SWZ(off));
            }
#pragma unroll
            for (int i = 0; i < 4; i++)
#pragma unroll
                for (int j = 0; j < 4; j++) {
                    mma_f16(acc[i][j], ah[i], bw[j]);
                    if (twoPlane) mma_f16(acc[i][j], al[i], bw[j]);
                }
        }
        __syncthreads();
    }

    // ---- epilogue ----
    const int mw = m0 + warp_m * 64;
    const int nw = n0 + warp_n * 32;
    const int rl = lane >> 2;
    const int cl = (lane & 3) * 2;
#pragma unroll
    for (int i = 0; i < 4; i++) {
#pragma unroll
        for (int j = 0; j < 4; j++) {
            int m = mw + i * 16 + rl;
            int n = nw + j * 8 + cl;
            float2 bv = *(const float2*)(bias + n);
            float y00 = (acc[i][j][0] + bv.x) * scale;
            float y01 = (acc[i][j][1] + bv.y) * scale;
            float y10 = (acc[i][j][2] + bv.x) * scale;
            float y11 = (acc[i][j][3] + bv.y) * scale;
            if (qkvLayout) {
                int h = n >> 6, d = n & 63;
                int b0 = m >> 11, t0 = m & 2047;
                int m1 = m + 8;
                int b1 = m1 >> 11, t1 = m1 & 2047;
                size_t i0 = ((size_t)(b0 * H_ + h) * T_ + t0) * DK_ + d;
                size_t i1 = ((size_t)(b1 * H_ + h) * T_ + t1) * DK_ + d;
                *(uint32_t*)&outH[i0] = pack2_f16(y00, y01);
                *(uint32_t*)&outH[i1] = pack2_f16(y10, y11);
            } else {
                *(float2*)(outF + (size_t)m * 1024 + n) = make_float2(y00, y01);
                *(float2*)(outF + (size_t)(m + 8) * 1024 + n) = make_float2(y10, y11);
            }
        }
    }
}

// ---------------------------------------------------------------------------
// Tensor-core causal flash attention — single-plane fp16 MMA (validated).
// 256 threads / 8 warps, Br=128, Bc=64, DK=64. Double-buffered K/V.
// Dyn smem: Q 16KB + 2 x (K 8KB + V 8KB) = 48KB.
// Output: fp16 hi/lo att planes for the final fp16 2-MMA GEMM.
// ---------------------------------------------------------------------------
__global__ __launch_bounds__(256, 1) void attn_tc(
    const __half* __restrict__ qh_g, const __half* __restrict__ kh_g,
    const __half* __restrict__ vh_g,
    __half* __restrict__ atth, __half* __restrict__ attl)
{
    extern __shared__ char dsm_raw[];
    char* dsm = (char*)(((uintptr_t)dsm_raw + 1023) & ~(uintptr_t)1023);

    const int tid  = threadIdx.x;
    const int lane = tid & 31;
    const int w    = tid >> 5;
    const int qt   = (int)gridDim.x - 1 - (int)blockIdx.x;   // heavy first
    const int bh   = blockIdx.y;
    const size_t bhoff = (size_t)bh * T_ * DK_;

    const uint32_t uQ   = smem_u32(dsm);        // 16KB (128 rows x 128B)
    const uint32_t uKV0 = uQ + 16384u;          // per buf: K 8KB, V 8KB

    // ---- Q tile load ----
    {
        const int srow = tid >> 1;
        const int gb   = (tid & 1) * 4;
        const __half* qp = qh_g + bhoff + (size_t)(qt * 128 + srow) * DK_;
#pragma unroll
        for (int i = 0; i < 4; i++) {
            int g = gb + i;
            uint32_t off = SWZ((uint32_t)(srow * 128 + g * 16));
            cp16(uQ + off, qp + g * 8);
        }
        CP_COMMIT();
    }

    const int srow2 = tid >> 2;          // 0..63
    const int gb2   = (tid & 3) * 2;
    const int ktmax = 2 * qt + 1;

    {   // prologue: KV tile 0 -> buf 0
        const __half* kp = kh_g + bhoff + (size_t)srow2 * DK_;
        const __half* vp = vh_g + bhoff + (size_t)srow2 * DK_;
#pragma unroll
        for (int i = 0; i < 2; i++) {
            int g = gb2 + i;
            uint32_t off = SWZ((uint32_t)(srow2 * 128 + g * 16));
            cp16(uKV0 + off,         kp + g * 8);
            cp16(uKV0 + 8192u + off, vp + g * 8);
        }
        CP_COMMIT();
    }

    float o[8][4];
#pragma unroll
    for (int j = 0; j < 8; j++)
#pragma unroll
        for (int r = 0; r < 4; r++) o[j][r] = 0.f;
    float m0v = -1e30f, m1v = -1e30f, l0v = 0.f, l1v = 0.f;

    const int qrow0 = qt * 128 + w * 16 + (lane >> 2);

    const uint32_t qRow = (uint32_t)(w * 16 + (lane & 15));
    const uint32_t qColB = (uint32_t)((lane >> 4) * 16);
    const uint32_t kRowBase = (uint32_t)((lane >> 4) * 8 + (lane & 7));
    const uint32_t kColB = (uint32_t)(((lane >> 3) & 1) * 16);
    const uint32_t vRow = (uint32_t)(lane & 15);
    const uint32_t vColB = (uint32_t)((lane >> 4) * 16);

#pragma unroll 1
    for (int kt = 0; kt <= ktmax; kt++) {
        if (kt + 1 <= ktmax) {
            uint32_t nb = uKV0 + (uint32_t)((kt + 1) & 1) * 16384u;
            const __half* kp = kh_g + bhoff + (size_t)((kt + 1) * 64 + srow2) * DK_;
            const __half* vp = vh_g + bhoff + (size_t)((kt + 1) * 64 + srow2) * DK_;
#pragma unroll
            for (int i = 0; i < 2; i++) {
                int g = gb2 + i;
                uint32_t off = SWZ((uint32_t)(srow2 * 128 + g * 16));
                cp16(nb + off,         kp + g * 8);
                cp16(nb + 8192u + off, vp + g * 8);
            }
            CP_COMMIT();
            CP_WAIT1();
        } else {
            CP_WAIT0();
        }
        __syncthreads();

        const uint32_t tb = uKV0 + (uint32_t)(kt & 1) * 16384u;

        const int krel = kt * 64 - qt * 128;
        const bool full_skip = (krel > w * 16 + 15);
        const bool need_mask = !full_skip && (krel + 63 > w * 16);

        if (!full_skip) {
            float s[8][4];
#pragma unroll
            for (int j = 0; j < 8; j++)
#pragma unroll
                for (int r = 0; r < 4; r++) s[j][r] = 0.f;

#pragma unroll
            for (int ks4 = 0; ks4 < 4; ks4++) {
                uint32_t qf[4];
                uint32_t qoff = SWZ(qRow * 128 + (uint32_t)ks4 * 32 + qColB);
                ldsm_x4(qf, uQ + qoff);
#pragma unroll
                for (int nf = 0; nf < 4; nf++) {
                    uint32_t kf[4];
                    uint32_t koff = SWZ((kRowBase + (uint32_t)nf * 16) * 128 +
                                        (uint32_t)ks4 * 32 + kColB);
                    ldsm_x4(kf, tb + koff);
                    mma_f16(s[nf * 2],     qf, &kf[0]);
                    mma_f16(s[nf * 2 + 1], qf, &kf[2]);
                }
            }

            if (need_mask) {
#pragma unroll
                for (int j = 0; j < 8; j++) {
                    int kc = kt * 64 + j * 8 + (lane & 3) * 2;
                    if (kc     > qrow0)     s[j][0] = -1e30f;
                    if (kc + 1 > qrow0)     s[j][1] = -1e30f;
                    if (kc     > qrow0 + 8) s[j][2] = -1e30f;
                    if (kc + 1 > qrow0 + 8) s[j][3] = -1e30f;
                }
            }

            float mA = m0v, mB = m1v;
#pragma unroll
            for (int j = 0; j < 8; j++) {
                mA = fmaxf(mA, fmaxf(s[j][0], s[j][1]));
                mB = fmaxf(mB, fmaxf(s[j][2], s[j][3]));
            }
            mA = fmaxf(mA, __shfl_xor_sync(0xffffffffu, mA, 1));
            mA = fmaxf(mA, __shfl_xor_sync(0xffffffffu, mA, 2));
            mB = fmaxf(mB, __shfl_xor_sync(0xffffffffu, mB, 1));
            mB = fmaxf(mB, __shfl_xor_sync(0xffffffffu, mB, 2));

            float alphaA = __expf(m0v - mA);
            float alphaB = __expf(m1v - mB);
            float sumA = 0.f, sumB = 0.f;
#pragma unroll
            for (int j = 0; j < 8; j++) {
                s[j][0] = __expf(s[j][0] - mA);
                s[j][1] = __expf(s[j][1] - mA);
                s[j][2] = __expf(s[j][2] - mB);
                s[j][3] = __expf(s[j][3] - mB);
                sumA += s[j][0] + s[j][1];
                sumB += s[j][2] + s[j][3];
            }
            sumA += __shfl_xor_sync(0xffffffffu, sumA, 1);
            sumA += __shfl_xor_sync(0xffffffffu, sumA, 2);
            sumB += __shfl_xor_sync(0xffffffffu, sumB, 1);
            sumB += __shfl_xor_sync(0xffffffffu, sumB, 2);

            l0v = l0v * alphaA + sumA;
            l1v = l1v * alphaB + sumB;
            m0v = mA; m1v = mB;
#pragma unroll
            for (int j = 0; j < 8; j++) {
                o[j][0] *= alphaA; o[j][1] *= alphaA;
                o[j][2] *= alphaB; o[j][3] *= alphaB;
            }

            const uint32_t vb_ = tb + 8192u;
#pragma unroll
            for (int ks4 = 0; ks4 < 4; ks4++) {
                uint32_t pf[4];
                pf[0] = pack2_f16(s[2 * ks4][0],     s[2 * ks4][1]);
                pf[1] = pack2_f16(s[2 * ks4][2],     s[2 * ks4][3]);
                pf[2] = pack2_f16(s[2 * ks4 + 1][0], s[2 * ks4 + 1][1]);
                pf[3] = pack2_f16(s[2 * ks4 + 1][2], s[2 * ks4 + 1][3]);
#pragma unroll
                for (int nf = 0; nf < 4; nf++) {
                    uint32_t vf[4];
                    uint32_t voff = SWZ(((uint32_t)ks4 * 16 + vRow) * 128 +
                                        (uint32_t)nf * 32 + vColB);
                    ldsm_x4_t(vf, vb_ + voff);
                    mma_f16(o[nf * 2],     pf, &vf[0]);
                    mma_f16(o[nf * 2 + 1], pf, &vf[2]);
                }
            }
        }
        __syncthreads();
    }

    // ---- normalize + fp16 hi/lo split store of att ----
    float invA = 1.f / l0v;
    float invB = 1.f / l1v;
    int b = bh >> 4, h = bh & 15;
    int t0 = qt * 128 + w * 16 + (lane >> 2);
    size_t r0 = (size_t)(b * T_ + t0) * D_ + h * DK_ + (lane & 3) * 2;
    size_t r1 = (size_t)(b * T_ + t0 + 8) * D_ + h * DK_ + (lane & 3) * 2;
#pragma unroll
    for (int j = 0; j < 8; j++) {
        uint32_t hh, ll;
        split_pack2_f16(o[j][0] * invA, o[j][1] * invA, hh, ll);
        *(uint32_t*)&atth[r0 + j * 8] = hh;
        *(uint32_t*)&attl[r0 + j * 8] = ll;
        split_pack2_f16(o[j][2] * invB, o[j][3] * invB, hh, ll);
        *(uint32_t*)&atth[r1 + j * 8] = hh;
        *(uint32_t*)&attl[r1 + j * 8] = ll;
    }
}

// ---------------------------------------------------------------------------
extern "C" void kernel_launch(void* const* d_in, const int* in_sizes, int n_in,
                              void* d_out, int out_size)
{
    const float* x  = (const float*)d_in[0];
    const float* wq = (const float*)d_in[1];
    const float* bq = (const float*)d_in[2];
    const float* wk = (const float*)d_in[3];
    const float* bk = (const float*)d_in[4];
    const float* wv = (const float*)d_in[5];
    const float* bv = (const float*)d_in[6];
    const float* wo = (const float*)d_in[7];
    const float* bo = (const float*)d_in[8];
    float* out = (float*)d_out;

    __half *xh, *wh, *qh, *kh, *vh, *ath, *atl;
    cudaGetSymbolAddress((void**)&xh,  g_xh);
    cudaGetSymbolAddress((void**)&wh,  g_wh);
    cudaGetSymbolAddress((void**)&qh,  g_qh);
    cudaGetSymbolAddress((void**)&kh,  g_kh);
    cudaGetSymbolAddress((void**)&vh,  g_vh);
    cudaGetSymbolAddress((void**)&ath, g_ath);
    cudaGetSymbolAddress((void**)&atl, g_atl);

    const int NX = 8192 * 1024, NW = 1024 * 1024;
    convertf16<<<NX / 4 / 256, 256>>>(x,  xh, NX);
    convertf16<<<NW / 4 / 256, 256>>>(wq, wh + 0 * NW, NW);
    convertf16<<<NW / 4 / 256, 256>>>(wk, wh + 1 * NW, NW);
    convertf16<<<NW / 4 / 256, 256>>>(wv, wh + 2 * NW, NW);
    convertf16<<<NW / 4 / 256, 256>>>(wo, wh + 3 * NW, NW);

    const int SMEM_GEMM = 2 * 3 * 16384 + 1024;   // 99328 bytes
    const int SMEM_ATTN = 48 * 1024 + 1024;       // 50176 bytes
    cudaFuncSetAttribute(gemm_f16, cudaFuncAttributeMaxDynamicSharedMemorySize, SMEM_GEMM);
    cudaFuncSetAttribute(attn_tc, cudaFuncAttributeMaxDynamicSharedMemorySize, SMEM_ATTN);

    dim3 gemmGrid(1024 / 128, 8192 / 128);  // (8, 64)
    // QKV: single-plane x (1 MMA per fragment)
    gemm_f16<<<gemmGrid, 256, SMEM_GEMM>>>(xh, nullptr, wh + 0 * NW,
                                           bq, nullptr, qh, 0.125f, 1, 0);
    gemm_f16<<<gemmGrid, 256, SMEM_GEMM>>>(xh, nullptr, wh + 1 * NW,
                                           bk, nullptr, kh, 1.0f, 1, 0);
    gemm_f16<<<gemmGrid, 256, SMEM_GEMM>>>(xh, nullptr, wh + 2 * NW,
                                           bv, nullptr, vh, 1.0f, 1, 0);

    dim3 attnGrid(T_ / 128, B_ * H_);       // (16, 64)
    attn_tc<<<attnGrid, 256, SMEM_ATTN>>>(qh, kh, vh, ath, atl);

    // Final: 2-plane att (exact split, 2 MMAs) — protects output accuracy
    gemm_f16<<<gemmGrid, 256, SMEM_GEMM>>>(ath, atl, wh + 3 * NW,
                                           bo, out, nullptr, 1.0f, 0, 1);
}

// round 17
// speedup vs baseline: 4.4423x; 1.1130x over previous
#include <cuda_runtime.h>
#include <cuda_bf16.h>
#include <cuda_fp16.h>
#include <math.h>
#include <stdint.h>

#define B_ 4
#define T_ 2048
#define D_ 1024
#define H_ 16
#define DK_ 64

#define QKV_SZ (64*2048*64)   // elements per q/k/v tensor

// Scratch (allocation-free rule): fp16 planes
__device__ __half g_xh[8192*1024];            // x single plane
__device__ __half g_wh[4*1024*1024];          // wq,wk,wv,wo (contiguous rows)
__device__ __half g_qkvh[3*QKV_SZ];           // q,k,v in [B,H,T,DK]
__device__ __half g_ath[8192*1024];           // att single plane

// ---------------------------------------------------------------------------
// Portable primitives
// ---------------------------------------------------------------------------
__device__ __forceinline__ uint32_t smem_u32(const void* p) {
    uint32_t r;
    asm("{ .reg .u64 t; cvta.to.shared.u64 t, %1; cvt.u32.u64 %0, t; }"
        : "=r"(r) : "l"(p));
    return r;
}
__device__ __forceinline__ void ldsm_x4(uint32_t* r, uint32_t addr) {
    asm volatile("ldmatrix.sync.aligned.m8n8.x4.shared.b16 {%0,%1,%2,%3}, [%4];"
        : "=r"(r[0]), "=r"(r[1]), "=r"(r[2]), "=r"(r[3]) : "r"(addr));
}
__device__ __forceinline__ void ldsm_x4_t(uint32_t* r, uint32_t addr) {
    asm volatile("ldmatrix.sync.aligned.m8n8.x4.trans.shared.b16 {%0,%1,%2,%3}, [%4];"
        : "=r"(r[0]), "=r"(r[1]), "=r"(r[2]), "=r"(r[3]) : "r"(addr));
}
__device__ __forceinline__ void ldsm_x2(uint32_t* r, uint32_t addr) {
    asm volatile("ldmatrix.sync.aligned.m8n8.x2.shared.b16 {%0,%1}, [%2];"
        : "=r"(r[0]), "=r"(r[1]) : "r"(addr));
}
__device__ __forceinline__ void mma_f16(float* c, const uint32_t* a, const uint32_t* b) {
    asm volatile(
        "mma.sync.aligned.m16n8k16.row.col.f32.f16.f16.f32 "
        "{%0,%1,%2,%3}, {%4,%5,%6,%7}, {%8,%9}, {%0,%1,%2,%3};"
        : "+f"(c[0]), "+f"(c[1]), "+f"(c[2]), "+f"(c[3])
        : "r"(a[0]), "r"(a[1]), "r"(a[2]), "r"(a[3]), "r"(b[0]), "r"(b[1]));
}
__device__ __forceinline__ void cp16(uint32_t saddr, const void* g) {
    asm volatile("cp.async.cg.shared.global [%0], [%1], 16;" :: "r"(saddr), "l"(g));
}
#define CP_COMMIT() asm volatile("cp.async.commit_group;" ::: "memory")
#define CP_WAIT0()  asm volatile("cp.async.wait_group 0;" ::: "memory")
#define CP_WAIT1()  asm volatile("cp.async.wait_group 1;" ::: "memory")

#define SWZ(o) ((o) ^ (((o) >> 3) & 0x70))

__device__ __forceinline__ uint32_t pack2_f16(float x, float y) {
    __half2 h = __floats2half2_rn(x, y);
    return *(uint32_t*)&h;
}

// ---------------------------------------------------------------------------
// One-time convert (fp32 -> single fp16 plane)
// ---------------------------------------------------------------------------
__global__ void convertf16(const float* __restrict__ src, __half* __restrict__ dst, int n)
{
    int i = (blockIdx.x * blockDim.x + threadIdx.x) * 4;
    if (i < n) {
        float4 f = *(const float4*)(src + i);
        *(uint2*)(dst + i) = make_uint2(pack2_f16(f.x, f.y), pack2_f16(f.z, f.w));
    }
}

// ---------------------------------------------------------------------------
// Single-plane fp16 GEMM: C[M=8192, N] = A @ W^T + bias.
// 128x128 CTA tile, 8 warps, K chunks of 128 (two 64-col sub-tiles per chunk,
// SW128 layout preserved), double-buffered smem (A 32KB + W 32KB per buffer).
// qkvMode=1: merged QKV (N=3072): which = n0>>10 selects bias/scale/output
//            third; fp16 store to outH in [B,H,T,DK].
// qkvMode=0: fp32 row-major to outF (bias b0).
// ---------------------------------------------------------------------------
__global__ __launch_bounds__(256, 1) void gemm_f16(
    const __half* __restrict__ Ap, const __half* __restrict__ Wp,
    const float* __restrict__ b0, const float* __restrict__ b1,
    const float* __restrict__ b2,
    float* __restrict__ outF, __half* __restrict__ outH, int qkvMode)
{
    extern __shared__ char dsm_raw[];
    char* dsm = (char*)(((uintptr_t)dsm_raw + 1023) & ~(uintptr_t)1023);

    const int tid  = threadIdx.x;
    const int lane = tid & 31;
    const int wid  = tid >> 5;
    const int warp_m = wid >> 2;
    const int warp_n = wid & 3;
    const int m0 = blockIdx.y * 128;
    const int n0 = blockIdx.x * 128;
    const uint32_t dbase = smem_u32(dsm);

    const int which = qkvMode ? (n0 >> 10) : 0;
    const float* bias = (which == 0) ? b0 : ((which == 1) ? b1 : b2);
    const float scale = (qkvMode && which == 0) ? 0.125f : 1.0f;

    float acc[4][4][4];
#pragma unroll
    for (int i = 0; i < 4; i++)
#pragma unroll
        for (int j = 0; j < 4; j++)
#pragma unroll
            for (int r = 0; r < 4; r++) acc[i][j][r] = 0.f;

    const uint32_t rowA = (uint32_t)(warp_m * 64 + (lane & 15));
    const uint32_t colA = (uint32_t)((lane >> 4) * 16);
    const uint32_t rowB = (uint32_t)(warp_n * 32 + (lane & 7));
    const uint32_t colB = (uint32_t)(((lane >> 3) & 1) * 16);

    // staging: 2 threads/row; 8 granules of 16B per plane per thread (256B rows,
    // stored as two 64-col sub-tiles of 128B rows to keep SW128 swizzle)
    const int srow  = tid >> 1;
    const int gbase = (tid & 1) * 8;
    const __half* a_p = Ap + (size_t)(m0 + srow) * 1024;
    const __half* w_p = Wp + (size_t)(n0 + srow) * 1024;

    const uint32_t BUF = 65536u;   // A 32KB + W 32KB per buffer

#pragma unroll
    for (int i = 0; i < 8; i++) {
        int g = gbase + i;
        uint32_t off = (uint32_t)((g >> 3) * 16384) +
                       SWZ((uint32_t)(srow * 128 + (g & 7) * 16));
        cp16(dbase + off,          a_p + g * 8);
        cp16(dbase + 32768u + off, w_p + g * 8);
    }
    CP_COMMIT();

    const int NCH = 8;   // 8 chunks x 128 K
#pragma unroll 1
    for (int kt = 0; kt < NCH; kt++) {
        const uint32_t tb = dbase + (uint32_t)(kt & 1) * BUF;

        if (kt + 1 < NCH) {
            uint32_t nb = dbase + (uint32_t)((kt + 1) & 1) * BUF;
            int kc = (kt + 1) * 128;
#pragma unroll
            for (int i = 0; i < 8; i++) {
                int g = gbase + i;
                uint32_t off = (uint32_t)((g >> 3) * 16384) +
                               SWZ((uint32_t)(srow * 128 + (g & 7) * 16));
                cp16(nb + off,          a_p + kc + g * 8);
                cp16(nb + 32768u + off, w_p + kc + g * 8);
            }
            CP_COMMIT();
            CP_WAIT1();
        } else {
            CP_WAIT0();
        }
        __syncthreads();

#pragma unroll
        for (int ks = 0; ks < 8; ks++) {       // k16 steps within the chunk
            const uint32_t st = (uint32_t)((ks >> 2) * 16384);
            const uint32_t lk = (uint32_t)(ks & 3) * 32;
            uint32_t av[4][4], bw[4][2];
#pragma unroll
            for (int i = 0; i < 4; i++) {
                uint32_t off = (rowA + i * 16) * 128 + lk + colA;
                ldsm_x4(av[i], tb + st + SWZ(off));
            }
#pragma unroll
            for (int j = 0; j < 4; j++) {
                uint32_t off = (rowB + j * 8) * 128 + lk + colB;
                ldsm_x2(bw[j], tb + 32768u + st + SWZ(off));
            }
#pragma unroll
            for (int i = 0; i < 4; i++)
#pragma unroll
                for (int j = 0; j < 4; j++)
                    mma_f16(acc[i][j], av[i], bw[j]);
        }
        __syncthreads();
    }

    // ---- epilogue ----
    const int mw = m0 + warp_m * 64;
    const int nw = n0 + warp_n * 32;
    const int rl = lane >> 2;
    const int cl = (lane & 3) * 2;
    __half* outQ = qkvMode ? (outH + (size_t)which * QKV_SZ) : nullptr;
#pragma unroll
    for (int i = 0; i < 4; i++) {
#pragma unroll
        for (int j = 0; j < 4; j++) {
            int m = mw + i * 16 + rl;
            int n = nw + j * 8 + cl;
            int nb_ = n & 1023;
            float2 bv = *(const float2*)(bias + nb_);
            float y00 = (acc[i][j][0] + bv.x) * scale;
            float y01 = (acc[i][j][1] + bv.y) * scale;
            float y10 = (acc[i][j][2] + bv.x) * scale;
            float y11 = (acc[i][j][3] + bv.y) * scale;
            if (qkvMode) {
                int h = nb_ >> 6, d = nb_ & 63;
                int b0i = m >> 11, t0 = m & 2047;
                int m1 = m + 8;
                int b1i = m1 >> 11, t1 = m1 & 2047;
                size_t i0 = ((size_t)(b0i * H_ + h) * T_ + t0) * DK_ + d;
                size_t i1 = ((size_t)(b1i * H_ + h) * T_ + t1) * DK_ + d;
                *(uint32_t*)&outQ[i0] = pack2_f16(y00, y01);
                *(uint32_t*)&outQ[i1] = pack2_f16(y10, y11);
            } else {
                *(float2*)(outF + (size_t)m * 1024 + n) = make_float2(y00, y01);
                *(float2*)(outF + (size_t)(m + 8) * 1024 + n) = make_float2(y10, y11);
            }
        }
    }
}

// ---------------------------------------------------------------------------
// Tensor-core causal flash attention — single-plane fp16 MMA (validated).
// 256 threads / 8 warps, Br=128, Bc=64, DK=64. Double-buffered K/V.
// Dyn smem: Q 16KB + 2 x (K 8KB + V 8KB) = 48KB.
// Output: SINGLE fp16 plane att for the final single-plane GEMM.
// ---------------------------------------------------------------------------
__global__ __launch_bounds__(256, 1) void attn_tc(
    const __half* __restrict__ qh_g, const __half* __restrict__ kh_g,
    const __half* __restrict__ vh_g, __half* __restrict__ atth)
{
    extern __shared__ char dsm_raw[];
    char* dsm = (char*)(((uintptr_t)dsm_raw + 1023) & ~(uintptr_t)1023);

    const int tid  = threadIdx.x;
    const int lane = tid & 31;
    const int w    = tid >> 5;
    const int qt   = (int)gridDim.x - 1 - (int)blockIdx.x;   // heavy first
    const int bh   = blockIdx.y;
    const size_t bhoff = (size_t)bh * T_ * DK_;

    const uint32_t uQ   = smem_u32(dsm);        // 16KB (128 rows x 128B)
    const uint32_t uKV0 = uQ + 16384u;          // per buf: K 8KB, V 8KB

    // ---- Q tile load ----
    {
        const int srow = tid >> 1;
        const int gb   = (tid & 1) * 4;
        const __half* qp = qh_g + bhoff + (size_t)(qt * 128 + srow) * DK_;
#pragma unroll
        for (int i = 0; i < 4; i++) {
            int g = gb + i;
            uint32_t off = SWZ((uint32_t)(srow * 128 + g * 16));
            cp16(uQ + off, qp + g * 8);
        }
        CP_COMMIT();
    }

    const int srow2 = tid >> 2;          // 0..63
    const int gb2   = (tid & 3) * 2;
    const int ktmax = 2 * qt + 1;

    {   // prologue: KV tile 0 -> buf 0
        const __half* kp = kh_g + bhoff + (size_t)srow2 * DK_;
        const __half* vp = vh_g + bhoff + (size_t)srow2 * DK_;
#pragma unroll
        for (int i = 0; i < 2; i++) {
            int g = gb2 + i;
            uint32_t off = SWZ((uint32_t)(srow2 * 128 + g * 16));
            cp16(uKV0 + off,         kp + g * 8);
            cp16(uKV0 + 8192u + off, vp + g * 8);
        }
        CP_COMMIT();
    }

    float o[8][4];
#pragma unroll
    for (int j = 0; j < 8; j++)
#pragma unroll
        for (int r = 0; r < 4; r++) o[j][r] = 0.f;
    float m0v = -1e30f, m1v = -1e30f, l0v = 0.f, l1v = 0.f;

    const int qrow0 = qt * 128 + w * 16 + (lane >> 2);

    const uint32_t qRow = (uint32_t)(w * 16 + (lane & 15));
    const uint32_t qColB = (uint32_t)((lane >> 4) * 16);
    const uint32_t kRowBase = (uint32_t)((lane >> 4) * 8 + (lane & 7));
    const uint32_t kColB = (uint32_t)(((lane >> 3) & 1) * 16);
    const uint32_t vRow = (uint32_t)(lane & 15);
    const uint32_t vColB = (uint32_t)((lane >> 4) * 16);

#pragma unroll 1
    for (int kt = 0; kt <= ktmax; kt++) {
        if (kt + 1 <= ktmax) {
            uint32_t nb = uKV0 + (uint32_t)((kt + 1) & 1) * 16384u;
            const __half* kp = kh_g + bhoff + (size_t)((kt + 1) * 64 + srow2) * DK_;
            const __half* vp = vh_g + bhoff + (size_t)((kt + 1) * 64 + srow2) * DK_;
#pragma unroll
            for (int i = 0; i < 2; i++) {
                int g = gb2 + i;
                uint32_t off = SWZ((uint32_t)(srow2 * 128 + g * 16));
                cp16(nb + off,         kp + g * 8);
                cp16(nb + 8192u + off, vp + g * 8);
            }
            CP_COMMIT();
            CP_WAIT1();
        } else {
            CP_WAIT0();
        }
        __syncthreads();

        const uint32_t tb = uKV0 + (uint32_t)(kt & 1) * 16384u;

        const int krel = kt * 64 - qt * 128;
        const bool full_skip = (krel > w * 16 + 15);
        const bool need_mask = !full_skip && (krel + 63 > w * 16);

        if (!full_skip) {
            float s[8][4];
#pragma unroll
            for (int j = 0; j < 8; j++)
#pragma unroll
                for (int r = 0; r < 4; r++) s[j][r] = 0.f;

#pragma unroll
            for (int ks4 = 0; ks4 < 4; ks4++) {
                uint32_t qf[4];
                uint32_t qoff = SWZ(qRow * 128 + (uint32_t)ks4 * 32 + qColB);
                ldsm_x4(qf, uQ + qoff);
#pragma unroll
                for (int nf = 0; nf < 4; nf++) {
                    uint32_t kf[4];
                    uint32_t koff = SWZ((kRowBase + (uint32_t)nf * 16) * 128 +
                                        (uint32_t)ks4 * 32 + kColB);
                    ldsm_x4(kf, tb + koff);
                    mma_f16(s[nf * 2],     qf, &kf[0]);
                    mma_f16(s[nf * 2 + 1], qf, &kf[2]);
                }
            }

            if (need_mask) {
#pragma unroll
                for (int j = 0; j < 8; j++) {
                    int kc = kt * 64 + j * 8 + (lane & 3) * 2;
                    if (kc     > qrow0)     s[j][0] = -1e30f;
                    if (kc + 1 > qrow0)     s[j][1] = -1e30f;
                    if (kc     > qrow0 + 8) s[j][2] = -1e30f;
                    if (kc + 1 > qrow0 + 8) s[j][3] = -1e30f;
                }
            }

            float mA = m0v, mB = m1v;
#pragma unroll
            for (int j = 0; j < 8; j++) {
                mA = fmaxf(mA, fmaxf(s[j][0], s[j][1]));
                mB = fmaxf(mB, fmaxf(s[j][2], s[j][3]));
            }
            mA = fmaxf(mA, __shfl_xor_sync(0xffffffffu, mA, 1));
            mA = fmaxf(mA, __shfl_xor_sync(0xffffffffu, mA, 2));
            mB = fmaxf(mB, __shfl_xor_sync(0xffffffffu, mB, 1));
            mB = fmaxf(mB, __shfl_xor_sync(0xffffffffu, mB, 2));

            float alphaA = __expf(m0v - mA);
            float alphaB = __expf(m1v - mB);
            float sumA = 0.f, sumB = 0.f;
#pragma unroll
            for (int j = 0; j < 8; j++) {
                s[j][0] = __expf(s[j][0] - mA);
                s[j][1] = __expf(s[j][1] - mA);
                s[j][2] = __expf(s[j][2] - mB);
                s[j][3] = __expf(s[j][3] - mB);
                sumA += s[j][0] + s[j][1];
                sumB += s[j][2] + s[j][3];
            }
            sumA += __shfl_xor_sync(0xffffffffu, sumA, 1);
            sumA += __shfl_xor_sync(0xffffffffu, sumA, 2);
            sumB += __shfl_xor_sync(0xffffffffu, sumB, 1);
            sumB += __shfl_xor_sync(0xffffffffu, sumB, 2);

            l0v = l0v * alphaA + sumA;
            l1v = l1v * alphaB + sumB;
            m0v = mA; m1v = mB;
#pragma unroll
            for (int j = 0; j < 8; j++) {
                o[j][0] *= alphaA; o[j][1] *= alphaA;
                o[j][2] *= alphaB; o[j][3] *= alphaB;
            }

            const uint32_t vb_ = tb + 8192u;
#pragma unroll
            for (int ks4 = 0; ks4 < 4; ks4++) {
                uint32_t pf[4];
                pf[0] = pack2_f16(s[2 * ks4][0],     s[2 * ks4][1]);
                pf[1] = pack2_f16(s[2 * ks4][2],     s[2 * ks4][3]);
                pf[2] = pack2_f16(s[2 * ks4 + 1][0], s[2 * ks4 + 1][1]);
                pf[3] = pack2_f16(s[2 * ks4 + 1][2], s[2 * ks4 + 1][3]);
#pragma unroll
                for (int nf = 0; nf < 4; nf++) {
                    uint32_t vf[4];
                    uint32_t voff = SWZ(((uint32_t)ks4 * 16 + vRow) * 128 +
                                        (uint32_t)nf * 32 + vColB);
                    ldsm_x4_t(vf, vb_ + voff);
                    mma_f16(o[nf * 2],     pf, &vf[0]);
                    mma_f16(o[nf * 2 + 1], pf, &vf[2]);
                }
            }
        }
        __syncthreads();
    }

    // ---- normalize + single fp16 plane store of att ----
    float invA = 1.f / l0v;
    float invB = 1.f / l1v;
    int b = bh >> 4, h = bh & 15;
    int t0 = qt * 128 + w * 16 + (lane >> 2);
    size_t r0 = (size_t)(b * T_ + t0) * D_ + h * DK_ + (lane & 3) * 2;
    size_t r1 = (size_t)(b * T_ + t0 + 8) * D_ + h * DK_ + (lane & 3) * 2;
#pragma unroll
    for (int j = 0; j < 8; j++) {
        *(uint32_t*)&atth[r0 + j * 8] = pack2_f16(o[j][0] * invA, o[j][1] * invA);
        *(uint32_t*)&atth[r1 + j * 8] = pack2_f16(o[j][2] * invB, o[j][3] * invB);
    }
}

// ---------------------------------------------------------------------------
extern "C" void kernel_launch(void* const* d_in, const int* in_sizes, int n_in,
                              void* d_out, int out_size)
{
    const float* x  = (const float*)d_in[0];
    const float* wq = (const float*)d_in[1];
    const float* bq = (const float*)d_in[2];
    const float* wk = (const float*)d_in[3];
    const float* bk = (const float*)d_in[4];
    const float* wv = (const float*)d_in[5];
    const float* bv = (const float*)d_in[6];
    const float* wo = (const float*)d_in[7];
    const float* bo = (const float*)d_in[8];
    float* out = (float*)d_out;

    __half *xh, *wh, *qkvh, *ath;
    cudaGetSymbolAddress((void**)&xh,   g_xh);
    cudaGetSymbolAddress((void**)&wh,   g_wh);
    cudaGetSymbolAddress((void**)&qkvh, g_qkvh);
    cudaGetSymbolAddress((void**)&ath,  g_ath);

    const int NX = 8192 * 1024, NW = 1024 * 1024;
    convertf16<<<NX / 4 / 256, 256>>>(x,  xh, NX);
    convertf16<<<NW / 4 / 256, 256>>>(wq, wh + 0 * NW, NW);
    convertf16<<<NW / 4 / 256, 256>>>(wk, wh + 1 * NW, NW);
    convertf16<<<NW / 4 / 256, 256>>>(wv, wh + 2 * NW, NW);
    convertf16<<<NW / 4 / 256, 256>>>(wo, wh + 3 * NW, NW);

    const int SMEM_GEMM = 2 * 65536 + 1024;   // 132096 bytes
    const int SMEM_ATTN = 48 * 1024 + 1024;   // 50176 bytes
    cudaFuncSetAttribute(gemm_f16, cudaFuncAttributeMaxDynamicSharedMemorySize, SMEM_GEMM);
    cudaFuncSetAttribute(attn_tc, cudaFuncAttributeMaxDynamicSharedMemorySize, SMEM_ATTN);

    // Merged QKV: N = 3072, W rows 0..3071 of g_wh
    dim3 qkvGrid(3072 / 128, 8192 / 128);   // (24, 64) = 1536 CTAs
    gemm_f16<<<qkvGrid, 256, SMEM_GEMM>>>(xh, wh, bq, bk, bv,
                                          nullptr, qkvh, 1);

    dim3 attnGrid(T_ / 128, B_ * H_);       // (16, 64)
    attn_tc<<<attnGrid, 256, SMEM_ATTN>>>(qkvh, qkvh + QKV_SZ, qkvh + 2 * QKV_SZ, ath);

    // Final: att single plane @ wo
    dim3 outGrid(1024 / 128, 8192 / 128);   // (8, 64)
    gemm_f16<<<outGrid, 256, SMEM_GEMM>>>(ath, wh + 3 * NW, bo, bo, bo,
                                          out, nullptr, 0);
}